// round 7
// baseline (speedup 1.0000x reference)
#include <cuda_runtime.h>
#include <cuda_fp16.h>
#include <math.h>
#include <stdint.h>

// Problem constants
#define BATCH 2
#define SEQ   2048
#define DMODEL 2048
#define NHEADS 16
#define DHEAD 128
#define MROWS (BATCH*SEQ)          // 4096
#define KDIM  DMODEL

// -------------------- scratch (static device globals; no allocation) ------
__device__ float g_q[MROWS * DMODEL];
__device__ float g_k[MROWS * DMODEL];
__device__ float g_v[MROWS * DMODEL];

__device__ __align__(16) __half g_xhi[MROWS * DMODEL];
__device__ __align__(16) __half g_xlo[MROWS * DMODEL];
__device__ __align__(16) __half g_wqhi[DMODEL * DMODEL];
__device__ __align__(16) __half g_wqlo[DMODEL * DMODEL];
__device__ __align__(16) __half g_wkhi[DMODEL * DMODEL];
__device__ __align__(16) __half g_wklo[DMODEL * DMODEL];
__device__ __align__(16) __half g_wvhi[DMODEL * DMODEL];
__device__ __align__(16) __half g_wvlo[DMODEL * DMODEL];   // unused by gemm (2-prod), kept for symmetry
__device__ __align__(16) __half g_wohi[DMODEL * DMODEL];
__device__ __align__(16) __half g_wolo[DMODEL * DMODEL];
__device__ __align__(16) __half g_atthi[MROWS * DMODEL];
__device__ __align__(16) __half g_attlo[MROWS * DMODEL];
__device__ __align__(16) __half g_khi[MROWS * DMODEL];
__device__ __align__(16) __half g_klo[MROWS * DMODEL];
__device__ __align__(16) __half g_vhi[MROWS * DMODEL];     // single V plane

// ============================ PTX helpers (sm_80-baseline only) ============
__device__ __forceinline__ uint32_t smem_u32(const void* p) {
    uint32_t a;
    asm("{ .reg .u64 t; cvta.to.shared.u64 t, %1; cvt.u32.u64 %0, t; }" : "=r"(a) : "l"(p));
    return a;
}
#define CP_ASYNC16(dst, src) \
    asm volatile("cp.async.cg.shared.global [%0], [%1], 16;" :: "r"(dst), "l"(src))
#define CP_COMMIT() asm volatile("cp.async.commit_group;" ::: "memory")
#define CP_WAIT(n)  asm volatile("cp.async.wait_group %0;" :: "n"(n) : "memory")

#define LDSM4(r0, r1, r2, r3, addr) \
    asm volatile("ldmatrix.sync.aligned.m8n8.x4.shared.b16 {%0,%1,%2,%3}, [%4];" \
        : "=r"(r0), "=r"(r1), "=r"(r2), "=r"(r3) : "r"(addr))
#define LDSM4T(r0, r1, r2, r3, addr) \
    asm volatile("ldmatrix.sync.aligned.m8n8.x4.trans.shared.b16 {%0,%1,%2,%3}, [%4];" \
        : "=r"(r0), "=r"(r1), "=r"(r2), "=r"(r3) : "r"(addr))

#define MMA16816(c, a, b) \
    asm volatile("mma.sync.aligned.m16n8k16.row.col.f32.f16.f16.f32 " \
        "{%0,%1,%2,%3},{%4,%5,%6,%7},{%8,%9},{%0,%1,%2,%3};" \
        : "+f"((c)[0]), "+f"((c)[1]), "+f"((c)[2]), "+f"((c)[3]) \
        : "r"((a)[0]), "r"((a)[1]), "r"((a)[2]), "r"((a)[3]), "r"((b)[0]), "r"((b)[1]))

__device__ __forceinline__ uint32_t pk16(__half a, __half b) {
    return (uint32_t)__half_as_ushort(a) | ((uint32_t)__half_as_ushort(b) << 16);
}
__device__ __forceinline__ void split1(float x, __half& h, __half& l) {
    h = __float2half(x);
    l = __float2half(x - __half2float(h));
}

// ============================================================================
// pack_split: fp32 row-major -> fp16 hi/lo planes
// ============================================================================
__global__ __launch_bounds__(256)
void pack_split(const float* __restrict__ src,
                uint32_t* __restrict__ hi, uint32_t* __restrict__ lo, int npairs)
{
    int i = blockIdx.x * 256 + threadIdx.x;
    if (i >= npairs) return;
    float2 v = ((const float2*)src)[i];
    __half h0, l0, h1, l1;
    split1(v.x, h0, l0); split1(v.y, h1, l1);
    hi[i] = pk16(h0, h1);
    lo[i] = pk16(l0, l1);
}

// ============================================================================
// gemm_fused: C_z = A @ B_z^T, fp16 hi/lo split.
// z == twoZ -> 2 products (ah*bh + al*bh, B-lo never loaded); else 3 products.
// 512 threads / 16 warps (4m x 4n), warp tile 32x32, 3-stage cp.async.
// ============================================================================
#define BKD 32
#define TILE_B   (128 * BKD * 2)
#define STAGE_B  (4 * TILE_B)
#define GSTAGES  3
#define GEMM_SMEM (GSTAGES * STAGE_B)

__global__ __launch_bounds__(512)
void gemm_fused(const __half* __restrict__ Ahi, const __half* __restrict__ Alo,
                const __half* __restrict__ B0h, const __half* __restrict__ B0l,
                const __half* __restrict__ B1h, const __half* __restrict__ B1l,
                const __half* __restrict__ B2h, const __half* __restrict__ B2l,
                float* __restrict__ C0, float* __restrict__ C1, float* __restrict__ C2,
                int twoZ)
{
    extern __shared__ char smc[];
    const uint32_t sb = smem_u32(smc);

    const int tid  = threadIdx.x;
    const int lane = tid & 31;
    const int wid  = tid >> 5;          // 0..15
    const int wm   = wid & 3;
    const int wn   = wid >> 2;
    const int m0   = blockIdx.y * 128;
    const int n0   = blockIdx.x * 128;
    const int z    = blockIdx.z;
    const bool use3 = (z != twoZ);

    const __half* Bhi = (z == 0) ? B0h : (z == 1) ? B1h : B2h;
    const __half* Blo = (z == 0) ? B0l : (z == 1) ? B1l : B2l;
    float* C = (z == 0) ? C0 : (z == 1) ? C1 : C2;

    const int r1 = tid >> 2, c1 = tid & 3;
    const uint32_t d1 = (uint32_t)(r1 * 64 + ((c1 ^ ((r1 >> 1) & 3)) * 16));

    const __half* srcA[2] = { Ahi + (size_t)m0 * KDIM, Alo + (size_t)m0 * KDIM };
    const __half* srcB[2] = { Bhi + (size_t)n0 * KDIM, Blo + (size_t)n0 * KDIM };

    auto load_stage = [&](int s, int kb) {
        uint32_t base = sb + s * STAGE_B;
        int koff = kb * BKD;
        CP_ASYNC16(base + d1,              srcA[0] + (size_t)r1 * KDIM + koff + c1 * 8);
        CP_ASYNC16(base + TILE_B + d1,     srcA[1] + (size_t)r1 * KDIM + koff + c1 * 8);
        CP_ASYNC16(base + 2 * TILE_B + d1, srcB[0] + (size_t)r1 * KDIM + koff + c1 * 8);
        if (use3)
            CP_ASYNC16(base + 3 * TILE_B + d1, srcB[1] + (size_t)r1 * KDIM + koff + c1 * 8);
    };

    float acc[2][4][4];
#pragma unroll
    for (int i = 0; i < 2; i++)
#pragma unroll
        for (int j = 0; j < 4; j++)
#pragma unroll
            for (int r = 0; r < 4; r++) acc[i][j][r] = 0.f;

    load_stage(0, 0); CP_COMMIT();
    load_stage(1, 1); CP_COMMIT();

    const int arow = wm * 32 + (lane & 15);
    const int bnrow = wn * 32 + (lane & 15);
    const int lhalf = lane >> 4;

    const int NKB = KDIM / BKD;
    for (int kc = 0; kc < NKB; kc++) {
        CP_WAIT(1);
        __syncthreads();
        if (kc + 2 < NKB) load_stage((kc + 2) % GSTAGES, kc + 2);
        CP_COMMIT();

        uint32_t base = sb + (kc % GSTAGES) * STAGE_B;
        uint32_t aHb = base, aLb = base + TILE_B, bHb = base + 2 * TILE_B, bLb = base + 3 * TILE_B;

#pragma unroll
        for (int ks = 0; ks < 2; ks++) {
            uint32_t ah[2][4], al[2][4], bh[4][2], bl[4][2];
#pragma unroll
            for (int i = 0; i < 2; i++) {
                int row = arow + i * 16;
                uint32_t off = (uint32_t)(row * 64 + (((ks * 2 + lhalf) ^ ((row >> 1) & 3)) * 16));
                LDSM4(ah[i][0], ah[i][1], ah[i][2], ah[i][3], aHb + off);
                LDSM4(al[i][0], al[i][1], al[i][2], al[i][3], aLb + off);
            }
#pragma unroll
            for (int jp = 0; jp < 2; jp++) {
                int row = bnrow + jp * 16;
                uint32_t off = (uint32_t)(row * 64 + (((ks * 2 + lhalf) ^ ((row >> 1) & 3)) * 16));
                uint32_t r0, r1_, r2_, r3_;
                LDSM4(r0, r1_, r2_, r3_, bHb + off);
                bh[2 * jp][0] = r0;  bh[2 * jp][1] = r2_;
                bh[2 * jp + 1][0] = r1_; bh[2 * jp + 1][1] = r3_;
                if (use3) {
                    LDSM4(r0, r1_, r2_, r3_, bLb + off);
                    bl[2 * jp][0] = r0;  bl[2 * jp][1] = r2_;
                    bl[2 * jp + 1][0] = r1_; bl[2 * jp + 1][1] = r3_;
                }
            }
            if (use3) {
#pragma unroll
                for (int i = 0; i < 2; i++)
#pragma unroll
                    for (int j = 0; j < 4; j++) {
                        MMA16816(acc[i][j], ah[i], bh[j]);
                        MMA16816(acc[i][j], ah[i], bl[j]);
                        MMA16816(acc[i][j], al[i], bh[j]);
                    }
            } else {
#pragma unroll
                for (int i = 0; i < 2; i++)
#pragma unroll
                    for (int j = 0; j < 4; j++) {
                        MMA16816(acc[i][j], ah[i], bh[j]);
                        MMA16816(acc[i][j], al[i], bh[j]);
                    }
            }
        }
    }

#pragma unroll
    for (int i = 0; i < 2; i++) {
#pragma unroll
        for (int j = 0; j < 4; j++) {
            int m = m0 + wm * 32 + i * 16 + (lane >> 2);
            int n = n0 + wn * 32 + j * 8 + (lane & 3) * 2;
            *(float2*)&C[(size_t)m * DMODEL + n]       = make_float2(acc[i][j][0], acc[i][j][1]);
            *(float2*)&C[(size_t)(m + 8) * DMODEL + n] = make_float2(acc[i][j][2], acc[i][j][3]);
        }
    }
}

// ============================================================================
// rope_pack: rope q (in place fp32) and k -> khi/klo fp16; v -> vhi (single).
// ============================================================================
__global__ __launch_bounds__(256)
void rope_pack(float* __restrict__ q, const float* __restrict__ k, const float* __restrict__ v,
               const float* __restrict__ rc, const float* __restrict__ rs,
               __half* __restrict__ khi, __half* __restrict__ klo,
               __half* __restrict__ vhi)
{
    int idx = blockIdx.x * 256 + threadIdx.x;
    const int total = BATCH * SEQ * NHEADS * 64;
    if (idx >= total) return;
    int d = idx & 63;
    int h = (idx >> 6) & (NHEADS - 1);
    int s = (idx >> 10) & (SEQ - 1);
    int b = idx >> 21;
    size_t base = ((size_t)(b * SEQ + s)) * DMODEL + h * DHEAD;
    float c0 = rc[s * DHEAD + d],      s0 = rs[s * DHEAD + d];
    float c1 = rc[s * DHEAD + 64 + d], s1 = rs[s * DHEAD + 64 + d];

    float q0 = q[base + d], q1 = q[base + 64 + d];
    q[base + d]      = q0 * c0 - q1 * s0;
    q[base + 64 + d] = q1 * c1 + q0 * s1;

    float k0 = k[base + d], k1 = k[base + 64 + d];
    float kr0 = k0 * c0 - k1 * s0;
    float kr1 = k1 * c1 + k0 * s1;
    __half h0, l0;
    split1(kr0, h0, l0); khi[base + d] = h0;      klo[base + d] = l0;
    split1(kr1, h0, l0); khi[base + 64 + d] = h0; klo[base + 64 + d] = l0;

    vhi[base + d]      = __float2half(v[base + d]);
    vhi[base + 64 + d] = __float2half(v[base + 64 + d]);
}

// ============================================================================
// attn_tc: flash attention, fp16 mma.
// QK: 3 products (Q hi/lo, K hi/lo). PV: 2 products (P hi/lo, V single plane).
// Stage planes: KH, KL, V (3 x 16KB).
// ============================================================================
#define NKT (SEQ/64)
#define ATT_PLANE_B 16384
#define ATT_STAGE_B (3*ATT_PLANE_B)          // 48 KB
#define ATT_Q_B     65536
#define ATT_TC_SMEM (ATT_Q_B + 2*ATT_STAGE_B)   // 163840

__global__ __launch_bounds__(256, 1)
void attn_tc(const float* __restrict__ q,
             const __half* __restrict__ khi, const __half* __restrict__ klo,
             const __half* __restrict__ vhi,
             __half* __restrict__ ohi, __half* __restrict__ olo)
{
    extern __shared__ char smc[];
    const uint32_t sb = smem_u32(smc);
    const uint32_t QH = sb, QL = sb + 32768;
    const uint32_t ST = sb + ATT_Q_B;

    const int tid = threadIdx.x;
    const int lane = tid & 31;
    const int wid = tid >> 5;
    const int b = blockIdx.z, h = blockIdx.y;
    const int q0 = blockIdx.x * 128;
    const int wrow = wid * 16;
    const float scale = 0.088388347648318447f;   // 1/sqrt(128)

    // ---- fill Q smem (scaled, hi/lo fp16 split, swizzled) ----
    const float* qp = q + ((size_t)(b * SEQ + q0)) * DMODEL + h * DHEAD;
#pragma unroll
    for (int i = 0; i < 8; i++) {
        int idx = tid + i * 256;
        int row = idx >> 4, ch = idx & 15;
        const float* s = qp + (size_t)row * DMODEL + ch * 8;
        float4 f0 = *(const float4*)s;
        float4 f1 = *(const float4*)(s + 4);
        float v[8] = { f0.x*scale, f0.y*scale, f0.z*scale, f0.w*scale,
                       f1.x*scale, f1.y*scale, f1.z*scale, f1.w*scale };
        uint32_t hp[4], lp[4];
#pragma unroll
        for (int p = 0; p < 4; p++) {
            __half ha, la, hc, lc;
            split1(v[2*p], ha, la); split1(v[2*p+1], hc, lc);
            hp[p] = pk16(ha, hc);
            lp[p] = pk16(la, lc);
        }
        uint32_t off = (uint32_t)(row * 256 + ((ch ^ (row & 15)) << 4));
        *(uint4*)(smc + off)         = make_uint4(hp[0], hp[1], hp[2], hp[3]);
        *(uint4*)(smc + 32768 + off) = make_uint4(lp[0], lp[1], lp[2], lp[3]);
    }

    const __half* pl[3] = { khi, klo, vhi };
    auto load_kv = [&](int st, int kt) {
        uint32_t base = ST + st * ATT_STAGE_B;
#pragma unroll
        for (int i = 0; i < 12; i++) {
            int idx = tid + i * 256;           // 0..3071
            int p = idx >> 10;                 // plane 0..2
            int c = idx & 1023;
            int row = c >> 4, ch = c & 15;
            const __half* src = pl[p] +
                ((size_t)(b * SEQ + kt * 64 + row)) * DMODEL + h * DHEAD + ch * 8;
            uint32_t dst = base + p * ATT_PLANE_B + row * 256 + ((ch ^ (row & 15)) << 4);
            CP_ASYNC16(dst, src);
        }
    };

    float o_[16][4];
#pragma unroll
    for (int n = 0; n < 16; n++)
#pragma unroll
        for (int r = 0; r < 4; r++) o_[n][r] = 0.f;
    float m_a = -3.0e38f, m_b = -3.0e38f, l_a = 0.f, l_b = 0.f;

    load_kv(0, 0); CP_COMMIT();
    load_kv(1, 1); CP_COMMIT();

    const int qrow = wrow + (lane & 15);
    const int lh = lane >> 4;

    for (int kt = 0; kt < NKT; kt++) {
        CP_WAIT(1);
        __syncthreads();
        uint32_t bs = ST + (kt & 1) * ATT_STAGE_B;

        float s[8][4];
#pragma unroll
        for (int j = 0; j < 8; j++)
#pragma unroll
            for (int r = 0; r < 4; r++) s[j][r] = 0.f;

#pragma unroll
        for (int ks = 0; ks < 8; ks++) {
            uint32_t qoff = (uint32_t)(qrow * 256 + (((ks * 2 + lh) ^ (qrow & 15)) << 4));
            uint32_t ah[4], al[4];
            LDSM4(ah[0], ah[1], ah[2], ah[3], QH + qoff);
            LDSM4(al[0], al[1], al[2], al[3], QL + qoff);
#pragma unroll
            for (int nb = 0; nb < 4; nb++) {
                int krow = nb * 16 + (lane & 15);
                uint32_t koff = (uint32_t)(krow * 256 + (((ks * 2 + lh) ^ (krow & 15)) << 4));
                uint32_t h0, h1, h2, h3, l0, l1, l2, l3;
                LDSM4(h0, h1, h2, h3, bs + koff);
                LDSM4(l0, l1, l2, l3, bs + ATT_PLANE_B + koff);
                uint32_t bh0[2] = { h0, h2 }, bh1[2] = { h1, h3 };
                uint32_t bl0[2] = { l0, l2 }, bl1[2] = { l1, l3 };
                MMA16816(s[2*nb],   ah, bh0); MMA16816(s[2*nb],   ah, bl0); MMA16816(s[2*nb],   al, bh0);
                MMA16816(s[2*nb+1], ah, bh1); MMA16816(s[2*nb+1], ah, bl1); MMA16816(s[2*nb+1], al, bh1);
            }
        }

        float mla = -3.0e38f, mlb = -3.0e38f;
#pragma unroll
        for (int j = 0; j < 8; j++) {
            mla = fmaxf(mla, fmaxf(s[j][0], s[j][1]));
            mlb = fmaxf(mlb, fmaxf(s[j][2], s[j][3]));
        }
        mla = fmaxf(mla, __shfl_xor_sync(0xffffffffu, mla, 1));
        mla = fmaxf(mla, __shfl_xor_sync(0xffffffffu, mla, 2));
        mlb = fmaxf(mlb, __shfl_xor_sync(0xffffffffu, mlb, 1));
        mlb = fmaxf(mlb, __shfl_xor_sync(0xffffffffu, mlb, 2));
        float mna = fmaxf(m_a, mla), mnb = fmaxf(m_b, mlb);
        float aa = __expf(m_a - mna), ab = __expf(m_b - mnb);

        uint32_t pAh[8], pBh[8], pAl[8], pBl[8];
        float sa = 0.f, sb2 = 0.f;
#pragma unroll
        for (int j = 0; j < 8; j++) {
            float p0 = __expf(s[j][0] - mna), p1 = __expf(s[j][1] - mna);
            float p2 = __expf(s[j][2] - mnb), p3 = __expf(s[j][3] - mnb);
            sa += p0 + p1; sb2 += p2 + p3;
            __half h0, l0, h1, l1, h2, l2, h3, l3;
            split1(p0, h0, l0); split1(p1, h1, l1);
            split1(p2, h2, l2); split1(p3, h3, l3);
            pAh[j] = pk16(h0, h1); pAl[j] = pk16(l0, l1);
            pBh[j] = pk16(h2, h3); pBl[j] = pk16(l2, l3);
        }
        sa  += __shfl_xor_sync(0xffffffffu, sa, 1);
        sa  += __shfl_xor_sync(0xffffffffu, sa, 2);
        sb2 += __shfl_xor_sync(0xffffffffu, sb2, 1);
        sb2 += __shfl_xor_sync(0xffffffffu, sb2, 2);
        m_a = mna; m_b = mnb;
        l_a = l_a * aa + sa; l_b = l_b * ab + sb2;

#pragma unroll
        for (int n = 0; n < 16; n++) {
            o_[n][0] *= aa; o_[n][1] *= aa; o_[n][2] *= ab; o_[n][3] *= ab;
        }

        // ---- PV: 2 products (Ph*V + Pl*V), V single plane via ldmatrix.trans ----
#pragma unroll
        for (int kp = 0; kp < 4; kp++) {
            uint32_t ah4[4] = { pAh[2*kp], pBh[2*kp], pAh[2*kp+1], pBh[2*kp+1] };
            uint32_t al4[4] = { pAl[2*kp], pBl[2*kp], pAl[2*kp+1], pBl[2*kp+1] };
            int vrow = kp * 16 + (lane & 15);
#pragma unroll
            for (int nb = 0; nb < 8; nb++) {
                uint32_t ch = (uint32_t)(nb * 2 + lh);
                uint32_t voff = (uint32_t)(vrow * 256 + ((ch ^ (vrow & 15)) << 4));
                uint32_t h0, h1, h2, h3;
                LDSM4T(h0, h1, h2, h3, bs + 2 * ATT_PLANE_B + voff);
                uint32_t bh0[2] = { h0, h1 }, bh1[2] = { h2, h3 };
                MMA16816(o_[2*nb],   ah4, bh0); MMA16816(o_[2*nb],   al4, bh0);
                MMA16816(o_[2*nb+1], ah4, bh1); MMA16816(o_[2*nb+1], al4, bh1);
            }
        }

        __syncthreads();
        if (kt + 2 < NKT) { load_kv(kt & 1, kt + 2); CP_COMMIT(); }
    }

    // ---- epilogue: split O/l into fp16 hi/lo planes ----
    float ia = 1.f / l_a, ib = 1.f / l_b;
    size_t r0 = (size_t)(b * SEQ + q0 + wrow + (lane >> 2)) * DMODEL + h * DHEAD + 2 * (lane & 3);
    size_t r1 = r0 + (size_t)8 * DMODEL;
#pragma unroll
    for (int n = 0; n < 16; n++) {
        __half hh, ll;
        split1(o_[n][0] * ia, hh, ll); ohi[r0 + n*8]     = hh; olo[r0 + n*8]     = ll;
        split1(o_[n][1] * ia, hh, ll); ohi[r0 + n*8 + 1] = hh; olo[r0 + n*8 + 1] = ll;
        split1(o_[n][2] * ib, hh, ll); ohi[r1 + n*8]     = hh; olo[r1 + n*8]     = ll;
        split1(o_[n][3] * ib, hh, ll); ohi[r1 + n*8 + 1] = hh; olo[r1 + n*8 + 1] = ll;
    }
}

// ============================================================================
extern "C" void kernel_launch(void* const* d_in, const int* in_sizes, int n_in,
                              void* d_out, int out_size)
{
    const float* x  = (const float*)d_in[0];
    const float* rc = (const float*)d_in[1];
    const float* rs = (const float*)d_in[2];
    const float* Wq = (const float*)d_in[3];
    const float* Wk = (const float*)d_in[4];
    const float* Wv = (const float*)d_in[5];
    const float* Wo = (const float*)d_in[6];
    float* out = (float*)d_out;

    float *q, *k, *v;
    cudaGetSymbolAddress((void**)&q, g_q);
    cudaGetSymbolAddress((void**)&k, g_k);
    cudaGetSymbolAddress((void**)&v, g_v);

    __half *xhi, *xlo, *wqhi, *wqlo, *wkhi, *wklo, *wvhi, *wvlo, *wohi, *wolo, *atthi, *attlo;
    __half *khi, *klo, *vhi;
    cudaGetSymbolAddress((void**)&xhi,  g_xhi);   cudaGetSymbolAddress((void**)&xlo,  g_xlo);
    cudaGetSymbolAddress((void**)&wqhi, g_wqhi);  cudaGetSymbolAddress((void**)&wqlo, g_wqlo);
    cudaGetSymbolAddress((void**)&wkhi, g_wkhi);  cudaGetSymbolAddress((void**)&wklo, g_wklo);
    cudaGetSymbolAddress((void**)&wvhi, g_wvhi);  cudaGetSymbolAddress((void**)&wvlo, g_wvlo);
    cudaGetSymbolAddress((void**)&wohi, g_wohi);  cudaGetSymbolAddress((void**)&wolo, g_wolo);
    cudaGetSymbolAddress((void**)&atthi, g_atthi); cudaGetSymbolAddress((void**)&attlo, g_attlo);
    cudaGetSymbolAddress((void**)&khi, g_khi);    cudaGetSymbolAddress((void**)&klo, g_klo);
    cudaGetSymbolAddress((void**)&vhi, g_vhi);

    cudaFuncSetAttribute(gemm_fused, cudaFuncAttributeMaxDynamicSharedMemorySize, GEMM_SMEM);
    cudaFuncSetAttribute(attn_tc,    cudaFuncAttributeMaxDynamicSharedMemorySize, ATT_TC_SMEM);

    const int npx = MROWS * DMODEL / 2;
    const int npw = DMODEL * DMODEL / 2;
    pack_split<<<(npx + 255) / 256, 256>>>(x,  (uint32_t*)xhi,  (uint32_t*)xlo,  npx);
    pack_split<<<(npw + 255) / 256, 256>>>(Wq, (uint32_t*)wqhi, (uint32_t*)wqlo, npw);
    pack_split<<<(npw + 255) / 256, 256>>>(Wk, (uint32_t*)wkhi, (uint32_t*)wklo, npw);
    pack_split<<<(npw + 255) / 256, 256>>>(Wv, (uint32_t*)wvhi, (uint32_t*)wvlo, npw);
    pack_split<<<(npw + 255) / 256, 256>>>(Wo, (uint32_t*)wohi, (uint32_t*)wolo, npw);

    // fused QKV projection; z==2 (Wv) runs 2-product
    gemm_fused<<<dim3(DMODEL / 128, MROWS / 128, 3), 512, GEMM_SMEM>>>(
        xhi, xlo, wqhi, wqlo, wkhi, wklo, wvhi, wvlo, q, k, v, /*twoZ=*/2);

    int rope_threads = BATCH * SEQ * NHEADS * 64;
    rope_pack<<<(rope_threads + 255) / 256, 256>>>(q, k, v, rc, rs, khi, klo, vhi);

    attn_tc<<<dim3(SEQ / 128, NHEADS, BATCH), 256, ATT_TC_SMEM>>>(q, khi, klo, vhi, atthi, attlo);

    // output projection: 3 products
    gemm_fused<<<dim3(DMODEL / 128, MROWS / 128, 1), 512, GEMM_SMEM>>>(
        atthi, attlo, wohi, wolo, wohi, wolo, wohi, wolo, out, out, out, /*twoZ=*/-1);
}

// round 8
// speedup vs baseline: 1.0903x; 1.0903x over previous
#include <cuda_runtime.h>
#include <cuda_fp16.h>
#include <math.h>
#include <stdint.h>

// Problem constants
#define BATCH 2
#define SEQ   2048
#define DMODEL 2048
#define NHEADS 16
#define DHEAD 128
#define MROWS (BATCH*SEQ)          // 4096
#define KDIM  DMODEL

// -------------------- scratch (static device globals; no allocation) ------
__device__ float g_q[MROWS * DMODEL];
__device__ float g_k[MROWS * DMODEL];
__device__ float g_v[MROWS * DMODEL];

__device__ __align__(16) __half g_xhi[MROWS * DMODEL];
__device__ __align__(16) __half g_xlo[MROWS * DMODEL];
__device__ __align__(16) __half g_wqhi[DMODEL * DMODEL];
__device__ __align__(16) __half g_wqlo[DMODEL * DMODEL];
__device__ __align__(16) __half g_wkhi[DMODEL * DMODEL];
__device__ __align__(16) __half g_wklo[DMODEL * DMODEL];
__device__ __align__(16) __half g_wvhi[DMODEL * DMODEL];
__device__ __align__(16) __half g_wvlo[DMODEL * DMODEL];
__device__ __align__(16) __half g_wohi[DMODEL * DMODEL];
__device__ __align__(16) __half g_wolo[DMODEL * DMODEL];
__device__ __align__(16) __half g_atthi[MROWS * DMODEL];
__device__ __align__(16) __half g_attlo[MROWS * DMODEL];
__device__ __align__(16) __half g_khi[MROWS * DMODEL];
__device__ __align__(16) __half g_klo[MROWS * DMODEL];
__device__ __align__(16) __half g_vhi[MROWS * DMODEL];

// ============================ PTX helpers ==================================
__device__ __forceinline__ uint32_t smem_u32(const void* p) {
    uint32_t a;
    asm("{ .reg .u64 t; cvta.to.shared.u64 t, %1; cvt.u32.u64 %0, t; }" : "=r"(a) : "l"(p));
    return a;
}
#define CP_ASYNC16(dst, src) \
    asm volatile("cp.async.cg.shared.global [%0], [%1], 16;" :: "r"(dst), "l"(src))
#define CP_COMMIT() asm volatile("cp.async.commit_group;" ::: "memory")
#define CP_WAIT(n)  asm volatile("cp.async.wait_group %0;" :: "n"(n) : "memory")

#define LDSM4(r0, r1, r2, r3, addr) \
    asm volatile("ldmatrix.sync.aligned.m8n8.x4.shared.b16 {%0,%1,%2,%3}, [%4];" \
        : "=r"(r0), "=r"(r1), "=r"(r2), "=r"(r3) : "r"(addr))
#define LDSM4T(r0, r1, r2, r3, addr) \
    asm volatile("ldmatrix.sync.aligned.m8n8.x4.trans.shared.b16 {%0,%1,%2,%3}, [%4];" \
        : "=r"(r0), "=r"(r1), "=r"(r2), "=r"(r3) : "r"(addr))

#define MMA16816(c, a, b) \
    asm volatile("mma.sync.aligned.m16n8k16.row.col.f32.f16.f16.f32 " \
        "{%0,%1,%2,%3},{%4,%5,%6,%7},{%8,%9},{%0,%1,%2,%3};" \
        : "+f"((c)[0]), "+f"((c)[1]), "+f"((c)[2]), "+f"((c)[3]) \
        : "r"((a)[0]), "r"((a)[1]), "r"((a)[2]), "r"((a)[3]), "r"((b)[0]), "r"((b)[1]))

__device__ __forceinline__ uint32_t pk16(__half a, __half b) {
    return (uint32_t)__half_as_ushort(a) | ((uint32_t)__half_as_ushort(b) << 16);
}
__device__ __forceinline__ void split1(float x, __half& h, __half& l) {
    h = __float2half(x);
    l = __float2half(x - __half2float(h));
}

// ============================================================================
// pack_split: fp32 row-major -> fp16 hi/lo planes (coalesced uint32 I/O)
// ============================================================================
__global__ __launch_bounds__(256)
void pack_split(const float* __restrict__ src,
                uint32_t* __restrict__ hi, uint32_t* __restrict__ lo, int npairs)
{
    int i = blockIdx.x * 256 + threadIdx.x;
    if (i >= npairs) return;
    float2 v = ((const float2*)src)[i];
    __half h0, l0, h1, l1;
    split1(v.x, h0, l0); split1(v.y, h1, l1);
    hi[i] = pk16(h0, h1);
    lo[i] = pk16(l0, l1);
}

// ============================================================================
// gemm_fused: C_z = A @ B_z^T, fp16 hi/lo split; z==twoZ -> 2 products.
// 512 threads / 16 warps (4m x 4n), warp tile 32x32.
// BKD=64, 2-stage cp.async: half the barriers of the BKD=32 version.
// Smem tile layout: 128 rows x 128B, chunk swizzle ch ^ (row & 7).
// ============================================================================
#define BKD 64
#define TILE_B   (128 * BKD * 2)              // 16 KB per plane
#define STAGE_B  (4 * TILE_B)                 // 64 KB
#define GEMM_SMEM (2 * STAGE_B)               // 128 KB

__global__ __launch_bounds__(512)
void gemm_fused(const __half* __restrict__ Ahi, const __half* __restrict__ Alo,
                const __half* __restrict__ B0h, const __half* __restrict__ B0l,
                const __half* __restrict__ B1h, const __half* __restrict__ B1l,
                const __half* __restrict__ B2h, const __half* __restrict__ B2l,
                float* __restrict__ C0, float* __restrict__ C1, float* __restrict__ C2,
                int twoZ)
{
    extern __shared__ char smc[];
    const uint32_t sb = smem_u32(smc);

    const int tid  = threadIdx.x;
    const int lane = tid & 31;
    const int wid  = tid >> 5;
    const int wm   = wid & 3;
    const int wn   = wid >> 2;
    const int m0   = blockIdx.y * 128;
    const int n0   = blockIdx.x * 128;
    const int z    = blockIdx.z;
    const bool use3 = (z != twoZ);

    const __half* Bhi = (z == 0) ? B0h : (z == 1) ? B1h : B2h;
    const __half* Blo = (z == 0) ? B0l : (z == 1) ? B1l : B2l;
    float* C = (z == 0) ? C0 : (z == 1) ? C1 : C2;

    // loader slots: plane has 1024 16B-chunks; 512 threads x 2 slots
    const int rA = tid >> 3, cA = tid & 7;                 // slot0
    const int rB = (tid + 512) >> 3, cB = (tid + 512) & 7; // slot1
    const uint32_t dA = (uint32_t)(rA * 128 + ((cA ^ (rA & 7)) << 4));
    const uint32_t dB = (uint32_t)(rB * 128 + ((cB ^ (rB & 7)) << 4));

    const __half* srcA[2] = { Ahi + (size_t)m0 * KDIM, Alo + (size_t)m0 * KDIM };
    const __half* srcB[2] = { Bhi + (size_t)n0 * KDIM, Blo + (size_t)n0 * KDIM };

    auto load_stage = [&](int s, int kb) {
        uint32_t base = sb + s * STAGE_B;
        int koff = kb * BKD;
#pragma unroll
        for (int t = 0; t < 2; t++) {
            CP_ASYNC16(base + t * TILE_B + dA, srcA[t] + (size_t)rA * KDIM + koff + cA * 8);
            CP_ASYNC16(base + t * TILE_B + dB, srcA[t] + (size_t)rB * KDIM + koff + cB * 8);
        }
        CP_ASYNC16(base + 2 * TILE_B + dA, srcB[0] + (size_t)rA * KDIM + koff + cA * 8);
        CP_ASYNC16(base + 2 * TILE_B + dB, srcB[0] + (size_t)rB * KDIM + koff + cB * 8);
        if (use3) {
            CP_ASYNC16(base + 3 * TILE_B + dA, srcB[1] + (size_t)rA * KDIM + koff + cA * 8);
            CP_ASYNC16(base + 3 * TILE_B + dB, srcB[1] + (size_t)rB * KDIM + koff + cB * 8);
        }
    };

    float acc[2][4][4];
#pragma unroll
    for (int i = 0; i < 2; i++)
#pragma unroll
        for (int j = 0; j < 4; j++)
#pragma unroll
            for (int r = 0; r < 4; r++) acc[i][j][r] = 0.f;

    load_stage(0, 0); CP_COMMIT();

    const int arow = wm * 32 + (lane & 15);
    const int bnrow = wn * 32 + (lane & 15);
    const int lhalf = lane >> 4;

    const int NKB = KDIM / BKD;                 // 32
    for (int kc = 0; kc < NKB; kc++) {
        if (kc + 1 < NKB) {
            load_stage((kc + 1) & 1, kc + 1); CP_COMMIT();
            CP_WAIT(1);
        } else {
            CP_WAIT(0);
        }
        __syncthreads();

        uint32_t base = sb + (kc & 1) * STAGE_B;
        uint32_t aHb = base, aLb = base + TILE_B, bHb = base + 2 * TILE_B, bLb = base + 3 * TILE_B;

#pragma unroll
        for (int ks = 0; ks < 4; ks++) {
            uint32_t ah[2][4], al[2][4], bh[4][2], bl[4][2];
#pragma unroll
            for (int i = 0; i < 2; i++) {
                int row = arow + i * 16;
                uint32_t off = (uint32_t)(row * 128 + (((ks * 2 + lhalf) ^ (row & 7)) << 4));
                LDSM4(ah[i][0], ah[i][1], ah[i][2], ah[i][3], aHb + off);
                LDSM4(al[i][0], al[i][1], al[i][2], al[i][3], aLb + off);
            }
#pragma unroll
            for (int jp = 0; jp < 2; jp++) {
                int row = bnrow + jp * 16;
                uint32_t off = (uint32_t)(row * 128 + (((ks * 2 + lhalf) ^ (row & 7)) << 4));
                uint32_t r0, r1_, r2_, r3_;
                LDSM4(r0, r1_, r2_, r3_, bHb + off);
                bh[2 * jp][0] = r0;  bh[2 * jp][1] = r2_;
                bh[2 * jp + 1][0] = r1_; bh[2 * jp + 1][1] = r3_;
                if (use3) {
                    LDSM4(r0, r1_, r2_, r3_, bLb + off);
                    bl[2 * jp][0] = r0;  bl[2 * jp][1] = r2_;
                    bl[2 * jp + 1][0] = r1_; bl[2 * jp + 1][1] = r3_;
                }
            }
            if (use3) {
#pragma unroll
                for (int i = 0; i < 2; i++)
#pragma unroll
                    for (int j = 0; j < 4; j++) {
                        MMA16816(acc[i][j], ah[i], bh[j]);
                        MMA16816(acc[i][j], ah[i], bl[j]);
                        MMA16816(acc[i][j], al[i], bh[j]);
                    }
            } else {
#pragma unroll
                for (int i = 0; i < 2; i++)
#pragma unroll
                    for (int j = 0; j < 4; j++) {
                        MMA16816(acc[i][j], ah[i], bh[j]);
                        MMA16816(acc[i][j], al[i], bh[j]);
                    }
            }
        }
        __syncthreads();   // protect stage kc buffer before it is reloaded
    }

#pragma unroll
    for (int i = 0; i < 2; i++) {
#pragma unroll
        for (int j = 0; j < 4; j++) {
            int m = m0 + wm * 32 + i * 16 + (lane >> 2);
            int n = n0 + wn * 32 + j * 8 + (lane & 3) * 2;
            *(float2*)&C[(size_t)m * DMODEL + n]       = make_float2(acc[i][j][0], acc[i][j][1]);
            *(float2*)&C[(size_t)(m + 8) * DMODEL + n] = make_float2(acc[i][j][2], acc[i][j][3]);
        }
    }
}

// ============================================================================
// rope_pack: each thread owns 2 consecutive d's (same rotation half).
// All stores vectorized: float2 (q), uint32 half2 (khi/klo/vhi).
// ============================================================================
__global__ __launch_bounds__(256)
void rope_pack(float* __restrict__ q, const float* __restrict__ k, const float* __restrict__ v,
               const float* __restrict__ rc, const float* __restrict__ rs,
               __half* __restrict__ khi, __half* __restrict__ klo,
               __half* __restrict__ vhi)
{
    int idx = blockIdx.x * 256 + threadIdx.x;
    const int total = BATCH * SEQ * NHEADS * 32;
    if (idx >= total) return;
    int d = (idx & 31) * 2;                    // 0,2,..,62
    int h = (idx >> 5) & (NHEADS - 1);
    int s = (idx >> 9) & (SEQ - 1);
    int b = idx >> 20;
    size_t base = ((size_t)(b * SEQ + s)) * DMODEL + h * DHEAD;

    float2 c0 = *(const float2*)&rc[s * DHEAD + d];
    float2 s0 = *(const float2*)&rs[s * DHEAD + d];
    float2 c1 = *(const float2*)&rc[s * DHEAD + 64 + d];
    float2 s1 = *(const float2*)&rs[s * DHEAD + 64 + d];

    // q rope (fp32, in place, vectorized)
    float2 qa = *(const float2*)&q[base + d];
    float2 qb = *(const float2*)&q[base + 64 + d];
    *(float2*)&q[base + d]      = make_float2(qa.x * c0.x - qb.x * s0.x, qa.y * c0.y - qb.y * s0.y);
    *(float2*)&q[base + 64 + d] = make_float2(qb.x * c1.x + qa.x * s1.x, qb.y * c1.y + qa.y * s1.y);

    // k rope + split
    float2 ka = *(const float2*)&k[base + d];
    float2 kb = *(const float2*)&k[base + 64 + d];
    float kr0 = ka.x * c0.x - kb.x * s0.x, kr1 = ka.y * c0.y - kb.y * s0.y;
    float kr2 = kb.x * c1.x + ka.x * s1.x, kr3 = kb.y * c1.y + ka.y * s1.y;
    __half h0, l0, h1, l1;
    split1(kr0, h0, l0); split1(kr1, h1, l1);
    *(uint32_t*)&khi[base + d] = pk16(h0, h1);
    *(uint32_t*)&klo[base + d] = pk16(l0, l1);
    split1(kr2, h0, l0); split1(kr3, h1, l1);
    *(uint32_t*)&khi[base + 64 + d] = pk16(h0, h1);
    *(uint32_t*)&klo[base + 64 + d] = pk16(l0, l1);

    // v single plane
    float2 va = *(const float2*)&v[base + d];
    float2 vb = *(const float2*)&v[base + 64 + d];
    *(uint32_t*)&vhi[base + d]      = pk16(__float2half(va.x), __float2half(va.y));
    *(uint32_t*)&vhi[base + 64 + d] = pk16(__float2half(vb.x), __float2half(vb.y));
}

// ============================================================================
// attn_tc: flash attention, fp16 mma; QK 3-product, PV 2-product.
// Epilogue: vectorized uint32 stores of (pair of halves).
// ============================================================================
#define NKT (SEQ/64)
#define ATT_PLANE_B 16384
#define ATT_STAGE_B (3*ATT_PLANE_B)
#define ATT_Q_B     65536
#define ATT_TC_SMEM (ATT_Q_B + 2*ATT_STAGE_B)   // 163840

__global__ __launch_bounds__(256, 1)
void attn_tc(const float* __restrict__ q,
             const __half* __restrict__ khi, const __half* __restrict__ klo,
             const __half* __restrict__ vhi,
             __half* __restrict__ ohi, __half* __restrict__ olo)
{
    extern __shared__ char smc[];
    const uint32_t sb = smem_u32(smc);
    const uint32_t QH = sb, QL = sb + 32768;
    const uint32_t ST = sb + ATT_Q_B;

    const int tid = threadIdx.x;
    const int lane = tid & 31;
    const int wid = tid >> 5;
    const int b = blockIdx.z, h = blockIdx.y;
    const int q0 = blockIdx.x * 128;
    const int wrow = wid * 16;
    const float scale = 0.088388347648318447f;

    const float* qp = q + ((size_t)(b * SEQ + q0)) * DMODEL + h * DHEAD;
#pragma unroll
    for (int i = 0; i < 8; i++) {
        int idx = tid + i * 256;
        int row = idx >> 4, ch = idx & 15;
        const float* s = qp + (size_t)row * DMODEL + ch * 8;
        float4 f0 = *(const float4*)s;
        float4 f1 = *(const float4*)(s + 4);
        float v[8] = { f0.x*scale, f0.y*scale, f0.z*scale, f0.w*scale,
                       f1.x*scale, f1.y*scale, f1.z*scale, f1.w*scale };
        uint32_t hp[4], lp[4];
#pragma unroll
        for (int p = 0; p < 4; p++) {
            __half ha, la, hc, lc;
            split1(v[2*p], ha, la); split1(v[2*p+1], hc, lc);
            hp[p] = pk16(ha, hc);
            lp[p] = pk16(la, lc);
        }
        uint32_t off = (uint32_t)(row * 256 + ((ch ^ (row & 15)) << 4));
        *(uint4*)(smc + off)         = make_uint4(hp[0], hp[1], hp[2], hp[3]);
        *(uint4*)(smc + 32768 + off) = make_uint4(lp[0], lp[1], lp[2], lp[3]);
    }

    const __half* pl[3] = { khi, klo, vhi };
    auto load_kv = [&](int st, int kt) {
        uint32_t base = ST + st * ATT_STAGE_B;
#pragma unroll
        for (int i = 0; i < 12; i++) {
            int idx = tid + i * 256;
            int p = idx >> 10;
            int c = idx & 1023;
            int row = c >> 4, ch = c & 15;
            const __half* src = pl[p] +
                ((size_t)(b * SEQ + kt * 64 + row)) * DMODEL + h * DHEAD + ch * 8;
            uint32_t dst = base + p * ATT_PLANE_B + row * 256 + ((ch ^ (row & 15)) << 4);
            CP_ASYNC16(dst, src);
        }
    };

    float o_[16][4];
#pragma unroll
    for (int n = 0; n < 16; n++)
#pragma unroll
        for (int r = 0; r < 4; r++) o_[n][r] = 0.f;
    float m_a = -3.0e38f, m_b = -3.0e38f, l_a = 0.f, l_b = 0.f;

    load_kv(0, 0); CP_COMMIT();
    load_kv(1, 1); CP_COMMIT();

    const int qrow = wrow + (lane & 15);
    const int lh = lane >> 4;

    for (int kt = 0; kt < NKT; kt++) {
        CP_WAIT(1);
        __syncthreads();
        uint32_t bs = ST + (kt & 1) * ATT_STAGE_B;

        float s[8][4];
#pragma unroll
        for (int j = 0; j < 8; j++)
#pragma unroll
            for (int r = 0; r < 4; r++) s[j][r] = 0.f;

#pragma unroll
        for (int ks = 0; ks < 8; ks++) {
            uint32_t qoff = (uint32_t)(qrow * 256 + (((ks * 2 + lh) ^ (qrow & 15)) << 4));
            uint32_t ah[4], al[4];
            LDSM4(ah[0], ah[1], ah[2], ah[3], QH + qoff);
            LDSM4(al[0], al[1], al[2], al[3], QL + qoff);
#pragma unroll
            for (int nb = 0; nb < 4; nb++) {
                int krow = nb * 16 + (lane & 15);
                uint32_t koff = (uint32_t)(krow * 256 + (((ks * 2 + lh) ^ (krow & 15)) << 4));
                uint32_t h0, h1, h2, h3, l0, l1, l2, l3;
                LDSM4(h0, h1, h2, h3, bs + koff);
                LDSM4(l0, l1, l2, l3, bs + ATT_PLANE_B + koff);
                uint32_t bh0[2] = { h0, h2 }, bh1[2] = { h1, h3 };
                uint32_t bl0[2] = { l0, l2 }, bl1[2] = { l1, l3 };
                MMA16816(s[2*nb],   ah, bh0); MMA16816(s[2*nb],   ah, bl0); MMA16816(s[2*nb],   al, bh0);
                MMA16816(s[2*nb+1], ah, bh1); MMA16816(s[2*nb+1], ah, bl1); MMA16816(s[2*nb+1], al, bh1);
            }
        }

        float mla = -3.0e38f, mlb = -3.0e38f;
#pragma unroll
        for (int j = 0; j < 8; j++) {
            mla = fmaxf(mla, fmaxf(s[j][0], s[j][1]));
            mlb = fmaxf(mlb, fmaxf(s[j][2], s[j][3]));
        }
        mla = fmaxf(mla, __shfl_xor_sync(0xffffffffu, mla, 1));
        mla = fmaxf(mla, __shfl_xor_sync(0xffffffffu, mla, 2));
        mlb = fmaxf(mlb, __shfl_xor_sync(0xffffffffu, mlb, 1));
        mlb = fmaxf(mlb, __shfl_xor_sync(0xffffffffu, mlb, 2));
        float mna = fmaxf(m_a, mla), mnb = fmaxf(m_b, mlb);
        float aa = __expf(m_a - mna), ab = __expf(m_b - mnb);

        uint32_t pAh[8], pBh[8], pAl[8], pBl[8];
        float sa = 0.f, sb2 = 0.f;
#pragma unroll
        for (int j = 0; j < 8; j++) {
            float p0 = __expf(s[j][0] - mna), p1 = __expf(s[j][1] - mna);
            float p2 = __expf(s[j][2] - mnb), p3 = __expf(s[j][3] - mnb);
            sa += p0 + p1; sb2 += p2 + p3;
            __half h0, l0, h1, l1, h2, l2, h3, l3;
            split1(p0, h0, l0); split1(p1, h1, l1);
            split1(p2, h2, l2); split1(p3, h3, l3);
            pAh[j] = pk16(h0, h1); pAl[j] = pk16(l0, l1);
            pBh[j] = pk16(h2, h3); pBl[j] = pk16(l2, l3);
        }
        sa  += __shfl_xor_sync(0xffffffffu, sa, 1);
        sa  += __shfl_xor_sync(0xffffffffu, sa, 2);
        sb2 += __shfl_xor_sync(0xffffffffu, sb2, 1);
        sb2 += __shfl_xor_sync(0xffffffffu, sb2, 2);
        m_a = mna; m_b = mnb;
        l_a = l_a * aa + sa; l_b = l_b * ab + sb2;

#pragma unroll
        for (int n = 0; n < 16; n++) {
            o_[n][0] *= aa; o_[n][1] *= aa; o_[n][2] *= ab; o_[n][3] *= ab;
        }

#pragma unroll
        for (int kp = 0; kp < 4; kp++) {
            uint32_t ah4[4] = { pAh[2*kp], pBh[2*kp], pAh[2*kp+1], pBh[2*kp+1] };
            uint32_t al4[4] = { pAl[2*kp], pBl[2*kp], pAl[2*kp+1], pBl[2*kp+1] };
            int vrow = kp * 16 + (lane & 15);
#pragma unroll
            for (int nb = 0; nb < 8; nb++) {
                uint32_t ch = (uint32_t)(nb * 2 + lh);
                uint32_t voff = (uint32_t)(vrow * 256 + ((ch ^ (vrow & 15)) << 4));
                uint32_t h0, h1, h2, h3;
                LDSM4T(h0, h1, h2, h3, bs + 2 * ATT_PLANE_B + voff);
                uint32_t bh0[2] = { h0, h1 }, bh1[2] = { h2, h3 };
                MMA16816(o_[2*nb],   ah4, bh0); MMA16816(o_[2*nb],   al4, bh0);
                MMA16816(o_[2*nb+1], ah4, bh1); MMA16816(o_[2*nb+1], al4, bh1);
            }
        }

        __syncthreads();
        if (kt + 2 < NKT) { load_kv(kt & 1, kt + 2); CP_COMMIT(); }
    }

    // ---- epilogue: vectorized uint32 stores (pairs of fp16) ----
    float ia = 1.f / l_a, ib = 1.f / l_b;
    size_t r0 = (size_t)(b * SEQ + q0 + wrow + (lane >> 2)) * DMODEL + h * DHEAD + 2 * (lane & 3);
    size_t r1 = r0 + (size_t)8 * DMODEL;
#pragma unroll
    for (int n = 0; n < 16; n++) {
        __half h0, l0, h1, l1;
        split1(o_[n][0] * ia, h0, l0); split1(o_[n][1] * ia, h1, l1);
        *(uint32_t*)&ohi[r0 + n*8] = pk16(h0, h1);
        *(uint32_t*)&olo[r0 + n*8] = pk16(l0, l1);
        split1(o_[n][2] * ib, h0, l0); split1(o_[n][3] * ib, h1, l1);
        *(uint32_t*)&ohi[r1 + n*8] = pk16(h0, h1);
        *(uint32_t*)&olo[r1 + n*8] = pk16(l0, l1);
    }
}

// ============================================================================
extern "C" void kernel_launch(void* const* d_in, const int* in_sizes, int n_in,
                              void* d_out, int out_size)
{
    const float* x  = (const float*)d_in[0];
    const float* rc = (const float*)d_in[1];
    const float* rs = (const float*)d_in[2];
    const float* Wq = (const float*)d_in[3];
    const float* Wk = (const float*)d_in[4];
    const float* Wv = (const float*)d_in[5];
    const float* Wo = (const float*)d_in[6];
    float* out = (float*)d_out;

    float *q, *k, *v;
    cudaGetSymbolAddress((void**)&q, g_q);
    cudaGetSymbolAddress((void**)&k, g_k);
    cudaGetSymbolAddress((void**)&v, g_v);

    __half *xhi, *xlo, *wqhi, *wqlo, *wkhi, *wklo, *wvhi, *wvlo, *wohi, *wolo, *atthi, *attlo;
    __half *khi, *klo, *vhi;
    cudaGetSymbolAddress((void**)&xhi,  g_xhi);   cudaGetSymbolAddress((void**)&xlo,  g_xlo);
    cudaGetSymbolAddress((void**)&wqhi, g_wqhi);  cudaGetSymbolAddress((void**)&wqlo, g_wqlo);
    cudaGetSymbolAddress((void**)&wkhi, g_wkhi);  cudaGetSymbolAddress((void**)&wklo, g_wklo);
    cudaGetSymbolAddress((void**)&wvhi, g_wvhi);  cudaGetSymbolAddress((void**)&wvlo, g_wvlo);
    cudaGetSymbolAddress((void**)&wohi, g_wohi);  cudaGetSymbolAddress((void**)&wolo, g_wolo);
    cudaGetSymbolAddress((void**)&atthi, g_atthi); cudaGetSymbolAddress((void**)&attlo, g_attlo);
    cudaGetSymbolAddress((void**)&khi, g_khi);    cudaGetSymbolAddress((void**)&klo, g_klo);
    cudaGetSymbolAddress((void**)&vhi, g_vhi);

    cudaFuncSetAttribute(gemm_fused, cudaFuncAttributeMaxDynamicSharedMemorySize, GEMM_SMEM);
    cudaFuncSetAttribute(attn_tc,    cudaFuncAttributeMaxDynamicSharedMemorySize, ATT_TC_SMEM);

    const int npx = MROWS * DMODEL / 2;
    const int npw = DMODEL * DMODEL / 2;
    pack_split<<<(npx + 255) / 256, 256>>>(x,  (uint32_t*)xhi,  (uint32_t*)xlo,  npx);
    pack_split<<<(npw + 255) / 256, 256>>>(Wq, (uint32_t*)wqhi, (uint32_t*)wqlo, npw);
    pack_split<<<(npw + 255) / 256, 256>>>(Wk, (uint32_t*)wkhi, (uint32_t*)wklo, npw);
    pack_split<<<(npw + 255) / 256, 256>>>(Wv, (uint32_t*)wvhi, (uint32_t*)wvlo, npw);
    pack_split<<<(npw + 255) / 256, 256>>>(Wo, (uint32_t*)wohi, (uint32_t*)wolo, npw);

    gemm_fused<<<dim3(DMODEL / 128, MROWS / 128, 3), 512, GEMM_SMEM>>>(
        xhi, xlo, wqhi, wqlo, wkhi, wklo, wvhi, wvlo, q, k, v, /*twoZ=*/2);

    int rope_threads = BATCH * SEQ * NHEADS * 32;
    rope_pack<<<(rope_threads + 255) / 256, 256>>>(q, k, v, rc, rs, khi, klo, vhi);

    attn_tc<<<dim3(SEQ / 128, NHEADS, BATCH), 256, ATT_TC_SMEM>>>(q, khi, klo, vhi, atthi, attlo);

    gemm_fused<<<dim3(DMODEL / 128, MROWS / 128, 1), 512, GEMM_SMEM>>>(
        atthi, attlo, wohi, wolo, wohi, wolo, wohi, wolo, out, out, out, /*twoZ=*/-1);
}

// round 9
// speedup vs baseline: 1.3842x; 1.2696x over previous
#include <cuda_runtime.h>
#include <cuda_fp16.h>
#include <math.h>
#include <stdint.h>

// Problem constants
#define BATCH 2
#define SEQ   2048
#define DMODEL 2048
#define NHEADS 16
#define DHEAD 128
#define MROWS (BATCH*SEQ)          // 4096
#define KDIM  DMODEL

// -------------------- scratch (static device globals; no allocation) ------
__device__ float g_q[MROWS * DMODEL];
__device__ float g_k[MROWS * DMODEL];
__device__ float g_v[MROWS * DMODEL];

__device__ __align__(16) __half g_xhi[MROWS * DMODEL];
__device__ __align__(16) __half g_xlo[MROWS * DMODEL];
__device__ __align__(16) __half g_wq[DMODEL * DMODEL];
__device__ __align__(16) __half g_wk[DMODEL * DMODEL];
__device__ __align__(16) __half g_wv[DMODEL * DMODEL];
__device__ __align__(16) __half g_wo[DMODEL * DMODEL];
__device__ __align__(16) __half g_atthi[MROWS * DMODEL];
__device__ __align__(16) __half g_attlo[MROWS * DMODEL];
__device__ __align__(16) __half g_khi[MROWS * DMODEL];
__device__ __align__(16) __half g_klo[MROWS * DMODEL];
__device__ __align__(16) __half g_vhi[MROWS * DMODEL];

// ============================ PTX helpers ==================================
__device__ __forceinline__ uint32_t smem_u32(const void* p) {
    uint32_t a;
    asm("{ .reg .u64 t; cvta.to.shared.u64 t, %1; cvt.u32.u64 %0, t; }" : "=r"(a) : "l"(p));
    return a;
}
#define CP_ASYNC16(dst, src) \
    asm volatile("cp.async.cg.shared.global [%0], [%1], 16;" :: "r"(dst), "l"(src))
#define CP_COMMIT() asm volatile("cp.async.commit_group;" ::: "memory")
#define CP_WAIT(n)  asm volatile("cp.async.wait_group %0;" :: "n"(n) : "memory")

#define LDSM4(r0, r1, r2, r3, addr) \
    asm volatile("ldmatrix.sync.aligned.m8n8.x4.shared.b16 {%0,%1,%2,%3}, [%4];" \
        : "=r"(r0), "=r"(r1), "=r"(r2), "=r"(r3) : "r"(addr))
#define LDSM4T(r0, r1, r2, r3, addr) \
    asm volatile("ldmatrix.sync.aligned.m8n8.x4.trans.shared.b16 {%0,%1,%2,%3}, [%4];" \
        : "=r"(r0), "=r"(r1), "=r"(r2), "=r"(r3) : "r"(addr))

#define MMA16816(c, a, b) \
    asm volatile("mma.sync.aligned.m16n8k16.row.col.f32.f16.f16.f32 " \
        "{%0,%1,%2,%3},{%4,%5,%6,%7},{%8,%9},{%0,%1,%2,%3};" \
        : "+f"((c)[0]), "+f"((c)[1]), "+f"((c)[2]), "+f"((c)[3]) \
        : "r"((a)[0]), "r"((a)[1]), "r"((a)[2]), "r"((a)[3]), "r"((b)[0]), "r"((b)[1]))

__device__ __forceinline__ uint32_t pk16(__half a, __half b) {
    return (uint32_t)__half_as_ushort(a) | ((uint32_t)__half_as_ushort(b) << 16);
}
__device__ __forceinline__ void split1(float x, __half& h, __half& l) {
    h = __float2half(x);
    l = __float2half(x - __half2float(h));
}

// ============================================================================
// pack_split: fp32 -> fp16 hi/lo planes.   pack_single: fp32 -> fp16.
// ============================================================================
__global__ __launch_bounds__(256)
void pack_split(const float* __restrict__ src,
                uint32_t* __restrict__ hi, uint32_t* __restrict__ lo, int npairs)
{
    int i = blockIdx.x * 256 + threadIdx.x;
    if (i >= npairs) return;
    float2 v = ((const float2*)src)[i];
    __half h0, l0, h1, l1;
    split1(v.x, h0, l0); split1(v.y, h1, l1);
    hi[i] = pk16(h0, h1);
    lo[i] = pk16(l0, l1);
}

__global__ __launch_bounds__(256)
void pack_single(const float* __restrict__ src, uint32_t* __restrict__ dst, int npairs)
{
    int i = blockIdx.x * 256 + threadIdx.x;
    if (i >= npairs) return;
    float2 v = ((const float2*)src)[i];
    dst[i] = pk16(__float2half(v.x), __float2half(v.y));
}

// ============================================================================
// gemm_2p: C_z = A @ B_z^T — 2 products (A hi/lo split, B single fp16).
// 512 threads / 16 warps (4m x 4n), warp tile 32x32, BKD=64, 2 stages.
// Stage: A-hi, A-lo, B (3 x 16KB = 48KB); total smem 96KB.
// ============================================================================
#define BKD 64
#define TILE_B   (128 * BKD * 2)              // 16 KB
#define STAGE_B  (3 * TILE_B)                 // 48 KB
#define GEMM_SMEM (2 * STAGE_B)               // 96 KB

__global__ __launch_bounds__(512)
void gemm_2p(const __half* __restrict__ Ahi, const __half* __restrict__ Alo,
             const __half* __restrict__ B0, const __half* __restrict__ B1,
             const __half* __restrict__ B2,
             float* __restrict__ C0, float* __restrict__ C1, float* __restrict__ C2)
{
    extern __shared__ char smc[];
    const uint32_t sb = smem_u32(smc);

    const int tid  = threadIdx.x;
    const int lane = tid & 31;
    const int wid  = tid >> 5;
    const int wm   = wid & 3;
    const int wn   = wid >> 2;
    const int m0   = blockIdx.y * 128;
    const int n0   = blockIdx.x * 128;
    const int z    = blockIdx.z;

    const __half* B = (z == 0) ? B0 : (z == 1) ? B1 : B2;
    float* C = (z == 0) ? C0 : (z == 1) ? C1 : C2;

    const int rA = tid >> 3, cA = tid & 7;
    const int rB = (tid + 512) >> 3, cB = (tid + 512) & 7;
    const uint32_t dA = (uint32_t)(rA * 128 + ((cA ^ (rA & 7)) << 4));
    const uint32_t dB = (uint32_t)(rB * 128 + ((cB ^ (rB & 7)) << 4));

    const __half* srcA[2] = { Ahi + (size_t)m0 * KDIM, Alo + (size_t)m0 * KDIM };
    const __half* srcB = B + (size_t)n0 * KDIM;

    auto load_stage = [&](int s, int kb) {
        uint32_t base = sb + s * STAGE_B;
        int koff = kb * BKD;
#pragma unroll
        for (int t = 0; t < 2; t++) {
            CP_ASYNC16(base + t * TILE_B + dA, srcA[t] + (size_t)rA * KDIM + koff + cA * 8);
            CP_ASYNC16(base + t * TILE_B + dB, srcA[t] + (size_t)rB * KDIM + koff + cB * 8);
        }
        CP_ASYNC16(base + 2 * TILE_B + dA, srcB + (size_t)rA * KDIM + koff + cA * 8);
        CP_ASYNC16(base + 2 * TILE_B + dB, srcB + (size_t)rB * KDIM + koff + cB * 8);
    };

    float acc[2][4][4];
#pragma unroll
    for (int i = 0; i < 2; i++)
#pragma unroll
        for (int j = 0; j < 4; j++)
#pragma unroll
            for (int r = 0; r < 4; r++) acc[i][j][r] = 0.f;

    load_stage(0, 0); CP_COMMIT();

    const int arow = wm * 32 + (lane & 15);
    const int bnrow = wn * 32 + (lane & 15);
    const int lhalf = lane >> 4;

    const int NKB = KDIM / BKD;                 // 32
    for (int kc = 0; kc < NKB; kc++) {
        if (kc + 1 < NKB) {
            load_stage((kc + 1) & 1, kc + 1); CP_COMMIT();
            CP_WAIT(1);
        } else {
            CP_WAIT(0);
        }
        __syncthreads();

        uint32_t base = sb + (kc & 1) * STAGE_B;
        uint32_t aHb = base, aLb = base + TILE_B, bHb = base + 2 * TILE_B;

#pragma unroll
        for (int ks = 0; ks < 4; ks++) {
            uint32_t ah[2][4], al[2][4], bh[4][2];
#pragma unroll
            for (int i = 0; i < 2; i++) {
                int row = arow + i * 16;
                uint32_t off = (uint32_t)(row * 128 + (((ks * 2 + lhalf) ^ (row & 7)) << 4));
                LDSM4(ah[i][0], ah[i][1], ah[i][2], ah[i][3], aHb + off);
                LDSM4(al[i][0], al[i][1], al[i][2], al[i][3], aLb + off);
            }
#pragma unroll
            for (int jp = 0; jp < 2; jp++) {
                int row = bnrow + jp * 16;
                uint32_t off = (uint32_t)(row * 128 + (((ks * 2 + lhalf) ^ (row & 7)) << 4));
                uint32_t r0, r1_, r2_, r3_;
                LDSM4(r0, r1_, r2_, r3_, bHb + off);
                bh[2 * jp][0] = r0;  bh[2 * jp][1] = r2_;
                bh[2 * jp + 1][0] = r1_; bh[2 * jp + 1][1] = r3_;
            }
#pragma unroll
            for (int i = 0; i < 2; i++)
#pragma unroll
                for (int j = 0; j < 4; j++) {
                    MMA16816(acc[i][j], ah[i], bh[j]);
                    MMA16816(acc[i][j], al[i], bh[j]);
                }
        }
        __syncthreads();
    }

#pragma unroll
    for (int i = 0; i < 2; i++) {
#pragma unroll
        for (int j = 0; j < 4; j++) {
            int m = m0 + wm * 32 + i * 16 + (lane >> 2);
            int n = n0 + wn * 32 + j * 8 + (lane & 3) * 2;
            *(float2*)&C[(size_t)m * DMODEL + n]       = make_float2(acc[i][j][0], acc[i][j][1]);
            *(float2*)&C[(size_t)(m + 8) * DMODEL + n] = make_float2(acc[i][j][2], acc[i][j][3]);
        }
    }
}

// ============================================================================
// rope_pack: rope q (fp32 in place) and k -> khi/klo; v -> vhi. Vectorized.
// ============================================================================
__global__ __launch_bounds__(256)
void rope_pack(float* __restrict__ q, const float* __restrict__ k, const float* __restrict__ v,
               const float* __restrict__ rc, const float* __restrict__ rs,
               __half* __restrict__ khi, __half* __restrict__ klo,
               __half* __restrict__ vhi)
{
    int idx = blockIdx.x * 256 + threadIdx.x;
    const int total = BATCH * SEQ * NHEADS * 32;
    if (idx >= total) return;
    int d = (idx & 31) * 2;
    int h = (idx >> 5) & (NHEADS - 1);
    int s = (idx >> 9) & (SEQ - 1);
    int b = idx >> 20;
    size_t base = ((size_t)(b * SEQ + s)) * DMODEL + h * DHEAD;

    float2 c0 = *(const float2*)&rc[s * DHEAD + d];
    float2 s0 = *(const float2*)&rs[s * DHEAD + d];
    float2 c1 = *(const float2*)&rc[s * DHEAD + 64 + d];
    float2 s1 = *(const float2*)&rs[s * DHEAD + 64 + d];

    float2 qa = *(const float2*)&q[base + d];
    float2 qb = *(const float2*)&q[base + 64 + d];
    *(float2*)&q[base + d]      = make_float2(qa.x * c0.x - qb.x * s0.x, qa.y * c0.y - qb.y * s0.y);
    *(float2*)&q[base + 64 + d] = make_float2(qb.x * c1.x + qa.x * s1.x, qb.y * c1.y + qa.y * s1.y);

    float2 ka = *(const float2*)&k[base + d];
    float2 kb = *(const float2*)&k[base + 64 + d];
    float kr0 = ka.x * c0.x - kb.x * s0.x, kr1 = ka.y * c0.y - kb.y * s0.y;
    float kr2 = kb.x * c1.x + ka.x * s1.x, kr3 = kb.y * c1.y + ka.y * s1.y;
    __half h0, l0, h1, l1;
    split1(kr0, h0, l0); split1(kr1, h1, l1);
    *(uint32_t*)&khi[base + d] = pk16(h0, h1);
    *(uint32_t*)&klo[base + d] = pk16(l0, l1);
    split1(kr2, h0, l0); split1(kr3, h1, l1);
    *(uint32_t*)&khi[base + 64 + d] = pk16(h0, h1);
    *(uint32_t*)&klo[base + 64 + d] = pk16(l0, l1);

    float2 va = *(const float2*)&v[base + d];
    float2 vb = *(const float2*)&v[base + 64 + d];
    *(uint32_t*)&vhi[base + d]      = pk16(__float2half(va.x), __float2half(va.y));
    *(uint32_t*)&vhi[base + 64 + d] = pk16(__float2half(vb.x), __float2half(vb.y));
}

// ============================================================================
// attn_tc: flash attention; QK 3-product, PV 2-product.
// R9: 3 KV stages -> single __syncthreads per kt iteration.
// ============================================================================
#define NKT (SEQ/64)
#define ATT_PLANE_B 16384
#define ATT_STAGE_B (3*ATT_PLANE_B)              // 48 KB
#define ATT_Q_B     65536
#define ATT_NSTAGE  3
#define ATT_TC_SMEM (ATT_Q_B + ATT_NSTAGE*ATT_STAGE_B)   // 212992

__global__ __launch_bounds__(256, 1)
void attn_tc(const float* __restrict__ q,
             const __half* __restrict__ khi, const __half* __restrict__ klo,
             const __half* __restrict__ vhi,
             __half* __restrict__ ohi, __half* __restrict__ olo)
{
    extern __shared__ char smc[];
    const uint32_t sb = smem_u32(smc);
    const uint32_t QH = sb, QL = sb + 32768;
    const uint32_t ST = sb + ATT_Q_B;

    const int tid = threadIdx.x;
    const int lane = tid & 31;
    const int wid = tid >> 5;
    const int b = blockIdx.z, h = blockIdx.y;
    const int q0 = blockIdx.x * 128;
    const int wrow = wid * 16;
    const float scale = 0.088388347648318447f;

    const float* qp = q + ((size_t)(b * SEQ + q0)) * DMODEL + h * DHEAD;
#pragma unroll
    for (int i = 0; i < 8; i++) {
        int idx = tid + i * 256;
        int row = idx >> 4, ch = idx & 15;
        const float* s = qp + (size_t)row * DMODEL + ch * 8;
        float4 f0 = *(const float4*)s;
        float4 f1 = *(const float4*)(s + 4);
        float v[8] = { f0.x*scale, f0.y*scale, f0.z*scale, f0.w*scale,
                       f1.x*scale, f1.y*scale, f1.z*scale, f1.w*scale };
        uint32_t hp[4], lp[4];
#pragma unroll
        for (int p = 0; p < 4; p++) {
            __half ha, la, hc, lc;
            split1(v[2*p], ha, la); split1(v[2*p+1], hc, lc);
            hp[p] = pk16(ha, hc);
            lp[p] = pk16(la, lc);
        }
        uint32_t off = (uint32_t)(row * 256 + ((ch ^ (row & 15)) << 4));
        *(uint4*)(smc + off)         = make_uint4(hp[0], hp[1], hp[2], hp[3]);
        *(uint4*)(smc + 32768 + off) = make_uint4(lp[0], lp[1], lp[2], lp[3]);
    }

    const __half* pl[3] = { khi, klo, vhi };
    auto load_kv = [&](int st, int kt) {
        uint32_t base = ST + st * ATT_STAGE_B;
#pragma unroll
        for (int i = 0; i < 12; i++) {
            int idx = tid + i * 256;
            int p = idx >> 10;
            int c = idx & 1023;
            int row = c >> 4, ch = c & 15;
            const __half* src = pl[p] +
                ((size_t)(b * SEQ + kt * 64 + row)) * DMODEL + h * DHEAD + ch * 8;
            uint32_t dst = base + p * ATT_PLANE_B + row * 256 + ((ch ^ (row & 15)) << 4);
            CP_ASYNC16(dst, src);
        }
    };

    float o_[16][4];
#pragma unroll
    for (int n = 0; n < 16; n++)
#pragma unroll
        for (int r = 0; r < 4; r++) o_[n][r] = 0.f;
    float m_a = -3.0e38f, m_b = -3.0e38f, l_a = 0.f, l_b = 0.f;

    load_kv(0, 0); CP_COMMIT();
    load_kv(1, 1); CP_COMMIT();

    const int qrow = wrow + (lane & 15);
    const int lh = lane >> 4;

    int st = 0;                                   // stage of current kt
    for (int kt = 0; kt < NKT; kt++) {
        CP_WAIT(1);
        __syncthreads();                          // single barrier per iteration
        uint32_t bs = ST + st * ATT_STAGE_B;

        // issue next-next load into stage (st+2)%3 — untouched by kt, kt+1
        if (kt + 2 < NKT) {
            int st2 = st + 2; if (st2 >= ATT_NSTAGE) st2 -= ATT_NSTAGE;
            load_kv(st2, kt + 2); CP_COMMIT();
        } else {
            CP_COMMIT();                          // keep group accounting uniform
        }

        float s[8][4];
#pragma unroll
        for (int j = 0; j < 8; j++)
#pragma unroll
            for (int r = 0; r < 4; r++) s[j][r] = 0.f;

#pragma unroll
        for (int ks = 0; ks < 8; ks++) {
            uint32_t qoff = (uint32_t)(qrow * 256 + (((ks * 2 + lh) ^ (qrow & 15)) << 4));
            uint32_t ah[4], al[4];
            LDSM4(ah[0], ah[1], ah[2], ah[3], QH + qoff);
            LDSM4(al[0], al[1], al[2], al[3], QL + qoff);
#pragma unroll
            for (int nb = 0; nb < 4; nb++) {
                int krow = nb * 16 + (lane & 15);
                uint32_t koff = (uint32_t)(krow * 256 + (((ks * 2 + lh) ^ (krow & 15)) << 4));
                uint32_t h0, h1, h2, h3, l0, l1, l2, l3;
                LDSM4(h0, h1, h2, h3, bs + koff);
                LDSM4(l0, l1, l2, l3, bs + ATT_PLANE_B + koff);
                uint32_t bh0[2] = { h0, h2 }, bh1[2] = { h1, h3 };
                uint32_t bl0[2] = { l0, l2 }, bl1[2] = { l1, l3 };
                MMA16816(s[2*nb],   ah, bh0); MMA16816(s[2*nb],   ah, bl0); MMA16816(s[2*nb],   al, bh0);
                MMA16816(s[2*nb+1], ah, bh1); MMA16816(s[2*nb+1], ah, bl1); MMA16816(s[2*nb+1], al, bh1);
            }
        }

        float mla = -3.0e38f, mlb = -3.0e38f;
#pragma unroll
        for (int j = 0; j < 8; j++) {
            mla = fmaxf(mla, fmaxf(s[j][0], s[j][1]));
            mlb = fmaxf(mlb, fmaxf(s[j][2], s[j][3]));
        }
        mla = fmaxf(mla, __shfl_xor_sync(0xffffffffu, mla, 1));
        mla = fmaxf(mla, __shfl_xor_sync(0xffffffffu, mla, 2));
        mlb = fmaxf(mlb, __shfl_xor_sync(0xffffffffu, mlb, 1));
        mlb = fmaxf(mlb, __shfl_xor_sync(0xffffffffu, mlb, 2));
        float mna = fmaxf(m_a, mla), mnb = fmaxf(m_b, mlb);
        float aa = __expf(m_a - mna), ab = __expf(m_b - mnb);

        uint32_t pAh[8], pBh[8], pAl[8], pBl[8];
        float sa = 0.f, sb2 = 0.f;
#pragma unroll
        for (int j = 0; j < 8; j++) {
            float p0 = __expf(s[j][0] - mna), p1 = __expf(s[j][1] - mna);
            float p2 = __expf(s[j][2] - mnb), p3 = __expf(s[j][3] - mnb);
            sa += p0 + p1; sb2 += p2 + p3;
            __half h0, l0, h1, l1, h2, l2, h3, l3;
            split1(p0, h0, l0); split1(p1, h1, l1);
            split1(p2, h2, l2); split1(p3, h3, l3);
            pAh[j] = pk16(h0, h1); pAl[j] = pk16(l0, l1);
            pBh[j] = pk16(h2, h3); pBl[j] = pk16(l2, l3);
        }
        sa  += __shfl_xor_sync(0xffffffffu, sa, 1);
        sa  += __shfl_xor_sync(0xffffffffu, sa, 2);
        sb2 += __shfl_xor_sync(0xffffffffu, sb2, 1);
        sb2 += __shfl_xor_sync(0xffffffffu, sb2, 2);
        m_a = mna; m_b = mnb;
        l_a = l_a * aa + sa; l_b = l_b * ab + sb2;

#pragma unroll
        for (int n = 0; n < 16; n++) {
            o_[n][0] *= aa; o_[n][1] *= aa; o_[n][2] *= ab; o_[n][3] *= ab;
        }

#pragma unroll
        for (int kp = 0; kp < 4; kp++) {
            uint32_t ah4[4] = { pAh[2*kp], pBh[2*kp], pAh[2*kp+1], pBh[2*kp+1] };
            uint32_t al4[4] = { pAl[2*kp], pBl[2*kp], pAl[2*kp+1], pBl[2*kp+1] };
            int vrow = kp * 16 + (lane & 15);
#pragma unroll
            for (int nb = 0; nb < 8; nb++) {
                uint32_t ch = (uint32_t)(nb * 2 + lh);
                uint32_t voff = (uint32_t)(vrow * 256 + ((ch ^ (vrow & 15)) << 4));
                uint32_t h0, h1, h2, h3;
                LDSM4T(h0, h1, h2, h3, bs + 2 * ATT_PLANE_B + voff);
                uint32_t bh0[2] = { h0, h1 }, bh1[2] = { h2, h3 };
                MMA16816(o_[2*nb],   ah4, bh0); MMA16816(o_[2*nb],   al4, bh0);
                MMA16816(o_[2*nb+1], ah4, bh1); MMA16816(o_[2*nb+1], al4, bh1);
            }
        }

        if (++st == ATT_NSTAGE) st = 0;
    }

    float ia = 1.f / l_a, ib = 1.f / l_b;
    size_t r0 = (size_t)(b * SEQ + q0 + wrow + (lane >> 2)) * DMODEL + h * DHEAD + 2 * (lane & 3);
    size_t r1 = r0 + (size_t)8 * DMODEL;
#pragma unroll
    for (int n = 0; n < 16; n++) {
        __half h0, l0, h1, l1;
        split1(o_[n][0] * ia, h0, l0); split1(o_[n][1] * ia, h1, l1);
        *(uint32_t*)&ohi[r0 + n*8] = pk16(h0, h1);
        *(uint32_t*)&olo[r0 + n*8] = pk16(l0, l1);
        split1(o_[n][2] * ib, h0, l0); split1(o_[n][3] * ib, h1, l1);
        *(uint32_t*)&ohi[r1 + n*8] = pk16(h0, h1);
        *(uint32_t*)&olo[r1 + n*8] = pk16(l0, l1);
    }
}

// ============================================================================
extern "C" void kernel_launch(void* const* d_in, const int* in_sizes, int n_in,
                              void* d_out, int out_size)
{
    const float* x  = (const float*)d_in[0];
    const float* rc = (const float*)d_in[1];
    const float* rs = (const float*)d_in[2];
    const float* Wq = (const float*)d_in[3];
    const float* Wk = (const float*)d_in[4];
    const float* Wv = (const float*)d_in[5];
    const float* Wo = (const float*)d_in[6];
    float* out = (float*)d_out;

    float *q, *k, *v;
    cudaGetSymbolAddress((void**)&q, g_q);
    cudaGetSymbolAddress((void**)&k, g_k);
    cudaGetSymbolAddress((void**)&v, g_v);

    __half *xhi, *xlo, *wq, *wk, *wv, *wo, *atthi, *attlo, *khi, *klo, *vhi;
    cudaGetSymbolAddress((void**)&xhi, g_xhi);   cudaGetSymbolAddress((void**)&xlo, g_xlo);
    cudaGetSymbolAddress((void**)&wq, g_wq);     cudaGetSymbolAddress((void**)&wk, g_wk);
    cudaGetSymbolAddress((void**)&wv, g_wv);     cudaGetSymbolAddress((void**)&wo, g_wo);
    cudaGetSymbolAddress((void**)&atthi, g_atthi); cudaGetSymbolAddress((void**)&attlo, g_attlo);
    cudaGetSymbolAddress((void**)&khi, g_khi);   cudaGetSymbolAddress((void**)&klo, g_klo);
    cudaGetSymbolAddress((void**)&vhi, g_vhi);

    cudaFuncSetAttribute(gemm_2p, cudaFuncAttributeMaxDynamicSharedMemorySize, GEMM_SMEM);
    cudaFuncSetAttribute(attn_tc, cudaFuncAttributeMaxDynamicSharedMemorySize, ATT_TC_SMEM);

    const int npx = MROWS * DMODEL / 2;
    const int npw = DMODEL * DMODEL / 2;
    pack_split<<<(npx + 255) / 256, 256>>>(x, (uint32_t*)xhi, (uint32_t*)xlo, npx);
    pack_single<<<(npw + 255) / 256, 256>>>(Wq, (uint32_t*)wq, npw);
    pack_single<<<(npw + 255) / 256, 256>>>(Wk, (uint32_t*)wk, npw);
    pack_single<<<(npw + 255) / 256, 256>>>(Wv, (uint32_t*)wv, npw);
    pack_single<<<(npw + 255) / 256, 256>>>(Wo, (uint32_t*)wo, npw);

    gemm_2p<<<dim3(DMODEL / 128, MROWS / 128, 3), 512, GEMM_SMEM>>>(
        xhi, xlo, wq, wk, wv, q, k, v);

    int rope_threads = BATCH * SEQ * NHEADS * 32;
    rope_pack<<<(rope_threads + 255) / 256, 256>>>(q, k, v, rc, rs, khi, klo, vhi);

    attn_tc<<<dim3(SEQ / 128, NHEADS, BATCH), 256, ATT_TC_SMEM>>>(q, khi, klo, vhi, atthi, attlo);

    gemm_2p<<<dim3(DMODEL / 128, MROWS / 128, 1), 512, GEMM_SMEM>>>(
        atthi, attlo, wo, wo, wo, out, out, out);
}

// round 10
// speedup vs baseline: 1.4767x; 1.0668x over previous
#include <cuda_runtime.h>
#include <cuda_fp16.h>
#include <math.h>
#include <stdint.h>

// Problem constants
#define BATCH 2
#define SEQ   2048
#define DMODEL 2048
#define NHEADS 16
#define DHEAD 128
#define MROWS (BATCH*SEQ)          // 4096
#define KDIM  DMODEL

// -------------------- scratch (static device globals; no allocation) ------
__device__ float g_q[MROWS * DMODEL];
__device__ float g_k[MROWS * DMODEL];
__device__ float g_v[MROWS * DMODEL];

__device__ __align__(16) __half g_xhi[MROWS * DMODEL];
__device__ __align__(16) __half g_xlo[MROWS * DMODEL];
__device__ __align__(16) __half g_wq[DMODEL * DMODEL];
__device__ __align__(16) __half g_wk[DMODEL * DMODEL];
__device__ __align__(16) __half g_wv[DMODEL * DMODEL];
__device__ __align__(16) __half g_wo[DMODEL * DMODEL];
__device__ __align__(16) __half g_atthi[MROWS * DMODEL];
__device__ __align__(16) __half g_attlo[MROWS * DMODEL];
__device__ __align__(16) __half g_khi[MROWS * DMODEL];
__device__ __align__(16) __half g_vhi[MROWS * DMODEL];

// ============================ PTX helpers ==================================
__device__ __forceinline__ uint32_t smem_u32(const void* p) {
    uint32_t a;
    asm("{ .reg .u64 t; cvta.to.shared.u64 t, %1; cvt.u32.u64 %0, t; }" : "=r"(a) : "l"(p));
    return a;
}
#define CP_ASYNC16(dst, src) \
    asm volatile("cp.async.cg.shared.global [%0], [%1], 16;" :: "r"(dst), "l"(src))
#define CP_COMMIT() asm volatile("cp.async.commit_group;" ::: "memory")
#define CP_WAIT(n)  asm volatile("cp.async.wait_group %0;" :: "n"(n) : "memory")

#define LDSM4(r0, r1, r2, r3, addr) \
    asm volatile("ldmatrix.sync.aligned.m8n8.x4.shared.b16 {%0,%1,%2,%3}, [%4];" \
        : "=r"(r0), "=r"(r1), "=r"(r2), "=r"(r3) : "r"(addr))
#define LDSM4T(r0, r1, r2, r3, addr) \
    asm volatile("ldmatrix.sync.aligned.m8n8.x4.trans.shared.b16 {%0,%1,%2,%3}, [%4];" \
        : "=r"(r0), "=r"(r1), "=r"(r2), "=r"(r3) : "r"(addr))

#define MMA16816(c, a, b) \
    asm volatile("mma.sync.aligned.m16n8k16.row.col.f32.f16.f16.f32 " \
        "{%0,%1,%2,%3},{%4,%5,%6,%7},{%8,%9},{%0,%1,%2,%3};" \
        : "+f"((c)[0]), "+f"((c)[1]), "+f"((c)[2]), "+f"((c)[3]) \
        : "r"((a)[0]), "r"((a)[1]), "r"((a)[2]), "r"((a)[3]), "r"((b)[0]), "r"((b)[1]))

__device__ __forceinline__ uint32_t pk16(__half a, __half b) {
    return (uint32_t)__half_as_ushort(a) | ((uint32_t)__half_as_ushort(b) << 16);
}
__device__ __forceinline__ void split1(float x, __half& h, __half& l) {
    h = __float2half(x);
    l = __float2half(x - __half2float(h));
}

// ============================================================================
// pack_split / pack_single
// ============================================================================
__global__ __launch_bounds__(256)
void pack_split(const float* __restrict__ src,
                uint32_t* __restrict__ hi, uint32_t* __restrict__ lo, int npairs)
{
    int i = blockIdx.x * 256 + threadIdx.x;
    if (i >= npairs) return;
    float2 v = ((const float2*)src)[i];
    __half h0, l0, h1, l1;
    split1(v.x, h0, l0); split1(v.y, h1, l1);
    hi[i] = pk16(h0, h1);
    lo[i] = pk16(l0, l1);
}

__global__ __launch_bounds__(256)
void pack_single(const float* __restrict__ src, uint32_t* __restrict__ dst, int npairs)
{
    int i = blockIdx.x * 256 + threadIdx.x;
    if (i >= npairs) return;
    float2 v = ((const float2*)src)[i];
    dst[i] = pk16(__float2half(v.x), __float2half(v.y));
}

// ============================================================================
// gemm_2p: C_z = A @ B_z^T — 2 products (A hi/lo split, B single fp16).
// ============================================================================
#define BKD 64
#define TILE_B   (128 * BKD * 2)              // 16 KB
#define STAGE_B  (3 * TILE_B)                 // 48 KB
#define GEMM_SMEM (2 * STAGE_B)               // 96 KB

__global__ __launch_bounds__(512)
void gemm_2p(const __half* __restrict__ Ahi, const __half* __restrict__ Alo,
             const __half* __restrict__ B0, const __half* __restrict__ B1,
             const __half* __restrict__ B2,
             float* __restrict__ C0, float* __restrict__ C1, float* __restrict__ C2)
{
    extern __shared__ char smc[];
    const uint32_t sb = smem_u32(smc);

    const int tid  = threadIdx.x;
    const int lane = tid & 31;
    const int wid  = tid >> 5;
    const int wm   = wid & 3;
    const int wn   = wid >> 2;
    const int m0   = blockIdx.y * 128;
    const int n0   = blockIdx.x * 128;
    const int z    = blockIdx.z;

    const __half* B = (z == 0) ? B0 : (z == 1) ? B1 : B2;
    float* C = (z == 0) ? C0 : (z == 1) ? C1 : C2;

    const int rA = tid >> 3, cA = tid & 7;
    const int rB = (tid + 512) >> 3, cB = (tid + 512) & 7;
    const uint32_t dA = (uint32_t)(rA * 128 + ((cA ^ (rA & 7)) << 4));
    const uint32_t dB = (uint32_t)(rB * 128 + ((cB ^ (rB & 7)) << 4));

    const __half* srcA[2] = { Ahi + (size_t)m0 * KDIM, Alo + (size_t)m0 * KDIM };
    const __half* srcB = B + (size_t)n0 * KDIM;

    auto load_stage = [&](int s, int kb) {
        uint32_t base = sb + s * STAGE_B;
        int koff = kb * BKD;
#pragma unroll
        for (int t = 0; t < 2; t++) {
            CP_ASYNC16(base + t * TILE_B + dA, srcA[t] + (size_t)rA * KDIM + koff + cA * 8);
            CP_ASYNC16(base + t * TILE_B + dB, srcA[t] + (size_t)rB * KDIM + koff + cB * 8);
        }
        CP_ASYNC16(base + 2 * TILE_B + dA, srcB + (size_t)rA * KDIM + koff + cA * 8);
        CP_ASYNC16(base + 2 * TILE_B + dB, srcB + (size_t)rB * KDIM + koff + cB * 8);
    };

    float acc[2][4][4];
#pragma unroll
    for (int i = 0; i < 2; i++)
#pragma unroll
        for (int j = 0; j < 4; j++)
#pragma unroll
            for (int r = 0; r < 4; r++) acc[i][j][r] = 0.f;

    load_stage(0, 0); CP_COMMIT();

    const int arow = wm * 32 + (lane & 15);
    const int bnrow = wn * 32 + (lane & 15);
    const int lhalf = lane >> 4;

    const int NKB = KDIM / BKD;                 // 32
    for (int kc = 0; kc < NKB; kc++) {
        if (kc + 1 < NKB) {
            load_stage((kc + 1) & 1, kc + 1); CP_COMMIT();
            CP_WAIT(1);
        } else {
            CP_WAIT(0);
        }
        __syncthreads();

        uint32_t base = sb + (kc & 1) * STAGE_B;
        uint32_t aHb = base, aLb = base + TILE_B, bHb = base + 2 * TILE_B;

#pragma unroll
        for (int ks = 0; ks < 4; ks++) {
            uint32_t ah[2][4], al[2][4], bh[4][2];
#pragma unroll
            for (int i = 0; i < 2; i++) {
                int row = arow + i * 16;
                uint32_t off = (uint32_t)(row * 128 + (((ks * 2 + lhalf) ^ (row & 7)) << 4));
                LDSM4(ah[i][0], ah[i][1], ah[i][2], ah[i][3], aHb + off);
                LDSM4(al[i][0], al[i][1], al[i][2], al[i][3], aLb + off);
            }
#pragma unroll
            for (int jp = 0; jp < 2; jp++) {
                int row = bnrow + jp * 16;
                uint32_t off = (uint32_t)(row * 128 + (((ks * 2 + lhalf) ^ (row & 7)) << 4));
                uint32_t r0, r1_, r2_, r3_;
                LDSM4(r0, r1_, r2_, r3_, bHb + off);
                bh[2 * jp][0] = r0;  bh[2 * jp][1] = r2_;
                bh[2 * jp + 1][0] = r1_; bh[2 * jp + 1][1] = r3_;
            }
#pragma unroll
            for (int i = 0; i < 2; i++)
#pragma unroll
                for (int j = 0; j < 4; j++) {
                    MMA16816(acc[i][j], ah[i], bh[j]);
                    MMA16816(acc[i][j], al[i], bh[j]);
                }
        }
        __syncthreads();
    }

#pragma unroll
    for (int i = 0; i < 2; i++) {
#pragma unroll
        for (int j = 0; j < 4; j++) {
            int m = m0 + wm * 32 + i * 16 + (lane >> 2);
            int n = n0 + wn * 32 + j * 8 + (lane & 3) * 2;
            *(float2*)&C[(size_t)m * DMODEL + n]       = make_float2(acc[i][j][0], acc[i][j][1]);
            *(float2*)&C[(size_t)(m + 8) * DMODEL + n] = make_float2(acc[i][j][2], acc[i][j][3]);
        }
    }
}

// ============================================================================
// rope_pack: rope q (fp32 in place) and k -> khi (single); v -> vhi.
// ============================================================================
__global__ __launch_bounds__(256)
void rope_pack(float* __restrict__ q, const float* __restrict__ k, const float* __restrict__ v,
               const float* __restrict__ rc, const float* __restrict__ rs,
               __half* __restrict__ khi, __half* __restrict__ vhi)
{
    int idx = blockIdx.x * 256 + threadIdx.x;
    const int total = BATCH * SEQ * NHEADS * 32;
    if (idx >= total) return;
    int d = (idx & 31) * 2;
    int h = (idx >> 5) & (NHEADS - 1);
    int s = (idx >> 9) & (SEQ - 1);
    int b = idx >> 20;
    size_t base = ((size_t)(b * SEQ + s)) * DMODEL + h * DHEAD;

    float2 c0 = *(const float2*)&rc[s * DHEAD + d];
    float2 s0 = *(const float2*)&rs[s * DHEAD + d];
    float2 c1 = *(const float2*)&rc[s * DHEAD + 64 + d];
    float2 s1 = *(const float2*)&rs[s * DHEAD + 64 + d];

    float2 qa = *(const float2*)&q[base + d];
    float2 qb = *(const float2*)&q[base + 64 + d];
    *(float2*)&q[base + d]      = make_float2(qa.x * c0.x - qb.x * s0.x, qa.y * c0.y - qb.y * s0.y);
    *(float2*)&q[base + 64 + d] = make_float2(qb.x * c1.x + qa.x * s1.x, qb.y * c1.y + qa.y * s1.y);

    float2 ka = *(const float2*)&k[base + d];
    float2 kb = *(const float2*)&k[base + 64 + d];
    float kr0 = ka.x * c0.x - kb.x * s0.x, kr1 = ka.y * c0.y - kb.y * s0.y;
    float kr2 = kb.x * c1.x + ka.x * s1.x, kr3 = kb.y * c1.y + ka.y * s1.y;
    *(uint32_t*)&khi[base + d]      = pk16(__float2half(kr0), __float2half(kr1));
    *(uint32_t*)&khi[base + 64 + d] = pk16(__float2half(kr2), __float2half(kr3));

    float2 va = *(const float2*)&v[base + d];
    float2 vb = *(const float2*)&v[base + 64 + d];
    *(uint32_t*)&vhi[base + d]      = pk16(__float2half(va.x), __float2half(va.y));
    *(uint32_t*)&vhi[base + 64 + d] = pk16(__float2half(vb.x), __float2half(vb.y));
}

// ============================================================================
// attn_tc: flash attention.
// R10: QK 2-product (Q hi/lo, K single plane); PV 2-product (P hi/lo, V single).
// KV stage = K + V planes (2 x 16KB = 32KB), 3 stages, 1 barrier/iter.
// ============================================================================
#define NKT (SEQ/64)
#define ATT_PLANE_B 16384
#define ATT_STAGE_B (2*ATT_PLANE_B)              // 32 KB
#define ATT_Q_B     65536
#define ATT_NSTAGE  3
#define ATT_TC_SMEM (ATT_Q_B + ATT_NSTAGE*ATT_STAGE_B)   // 163840

__global__ __launch_bounds__(256, 1)
void attn_tc(const float* __restrict__ q,
             const __half* __restrict__ khi,
             const __half* __restrict__ vhi,
             __half* __restrict__ ohi, __half* __restrict__ olo)
{
    extern __shared__ char smc[];
    const uint32_t sb = smem_u32(smc);
    const uint32_t QH = sb, QL = sb + 32768;
    const uint32_t ST = sb + ATT_Q_B;

    const int tid = threadIdx.x;
    const int lane = tid & 31;
    const int wid = tid >> 5;
    const int b = blockIdx.z, h = blockIdx.y;
    const int q0 = blockIdx.x * 128;
    const int wrow = wid * 16;
    const float scale = 0.088388347648318447f;

    const float* qp = q + ((size_t)(b * SEQ + q0)) * DMODEL + h * DHEAD;
#pragma unroll
    for (int i = 0; i < 8; i++) {
        int idx = tid + i * 256;
        int row = idx >> 4, ch = idx & 15;
        const float* s = qp + (size_t)row * DMODEL + ch * 8;
        float4 f0 = *(const float4*)s;
        float4 f1 = *(const float4*)(s + 4);
        float v[8] = { f0.x*scale, f0.y*scale, f0.z*scale, f0.w*scale,
                       f1.x*scale, f1.y*scale, f1.z*scale, f1.w*scale };
        uint32_t hp[4], lp[4];
#pragma unroll
        for (int p = 0; p < 4; p++) {
            __half ha, la, hc, lc;
            split1(v[2*p], ha, la); split1(v[2*p+1], hc, lc);
            hp[p] = pk16(ha, hc);
            lp[p] = pk16(la, lc);
        }
        uint32_t off = (uint32_t)(row * 256 + ((ch ^ (row & 15)) << 4));
        *(uint4*)(smc + off)         = make_uint4(hp[0], hp[1], hp[2], hp[3]);
        *(uint4*)(smc + 32768 + off) = make_uint4(lp[0], lp[1], lp[2], lp[3]);
    }

    const __half* pl[2] = { khi, vhi };
    auto load_kv = [&](int st, int kt) {
        uint32_t base = ST + st * ATT_STAGE_B;
#pragma unroll
        for (int i = 0; i < 8; i++) {
            int idx = tid + i * 256;           // 0..2047
            int p = idx >> 10;                 // plane 0..1
            int c = idx & 1023;
            int row = c >> 4, ch = c & 15;
            const __half* src = pl[p] +
                ((size_t)(b * SEQ + kt * 64 + row)) * DMODEL + h * DHEAD + ch * 8;
            uint32_t dst = base + p * ATT_PLANE_B + row * 256 + ((ch ^ (row & 15)) << 4);
            CP_ASYNC16(dst, src);
        }
    };

    float o_[16][4];
#pragma unroll
    for (int n = 0; n < 16; n++)
#pragma unroll
        for (int r = 0; r < 4; r++) o_[n][r] = 0.f;
    float m_a = -3.0e38f, m_b = -3.0e38f, l_a = 0.f, l_b = 0.f;

    load_kv(0, 0); CP_COMMIT();
    load_kv(1, 1); CP_COMMIT();

    const int qrow = wrow + (lane & 15);
    const int lh = lane >> 4;

    int st = 0;
    for (int kt = 0; kt < NKT; kt++) {
        CP_WAIT(1);
        __syncthreads();
        uint32_t bs = ST + st * ATT_STAGE_B;

        if (kt + 2 < NKT) {
            int st2 = st + 2; if (st2 >= ATT_NSTAGE) st2 -= ATT_NSTAGE;
            load_kv(st2, kt + 2); CP_COMMIT();
        } else {
            CP_COMMIT();
        }

        float s[8][4];
#pragma unroll
        for (int j = 0; j < 8; j++)
#pragma unroll
            for (int r = 0; r < 4; r++) s[j][r] = 0.f;

#pragma unroll
        for (int ks = 0; ks < 8; ks++) {
            uint32_t qoff = (uint32_t)(qrow * 256 + (((ks * 2 + lh) ^ (qrow & 15)) << 4));
            uint32_t ah[4], al[4];
            LDSM4(ah[0], ah[1], ah[2], ah[3], QH + qoff);
            LDSM4(al[0], al[1], al[2], al[3], QL + qoff);
#pragma unroll
            for (int nb = 0; nb < 4; nb++) {
                int krow = nb * 16 + (lane & 15);
                uint32_t koff = (uint32_t)(krow * 256 + (((ks * 2 + lh) ^ (krow & 15)) << 4));
                uint32_t h0, h1, h2, h3;
                LDSM4(h0, h1, h2, h3, bs + koff);
                uint32_t bh0[2] = { h0, h2 }, bh1[2] = { h1, h3 };
                MMA16816(s[2*nb],   ah, bh0); MMA16816(s[2*nb],   al, bh0);
                MMA16816(s[2*nb+1], ah, bh1); MMA16816(s[2*nb+1], al, bh1);
            }
        }

        float mla = -3.0e38f, mlb = -3.0e38f;
#pragma unroll
        for (int j = 0; j < 8; j++) {
            mla = fmaxf(mla, fmaxf(s[j][0], s[j][1]));
            mlb = fmaxf(mlb, fmaxf(s[j][2], s[j][3]));
        }
        mla = fmaxf(mla, __shfl_xor_sync(0xffffffffu, mla, 1));
        mla = fmaxf(mla, __shfl_xor_sync(0xffffffffu, mla, 2));
        mlb = fmaxf(mlb, __shfl_xor_sync(0xffffffffu, mlb, 1));
        mlb = fmaxf(mlb, __shfl_xor_sync(0xffffffffu, mlb, 2));
        float mna = fmaxf(m_a, mla), mnb = fmaxf(m_b, mlb);
        float aa = __expf(m_a - mna), ab = __expf(m_b - mnb);

        uint32_t pAh[8], pBh[8], pAl[8], pBl[8];
        float sa = 0.f, sb2 = 0.f;
#pragma unroll
        for (int j = 0; j < 8; j++) {
            float p0 = __expf(s[j][0] - mna), p1 = __expf(s[j][1] - mna);
            float p2 = __expf(s[j][2] - mnb), p3 = __expf(s[j][3] - mnb);
            sa += p0 + p1; sb2 += p2 + p3;
            __half h0, l0, h1, l1, h2, l2, h3, l3;
            split1(p0, h0, l0); split1(p1, h1, l1);
            split1(p2, h2, l2); split1(p3, h3, l3);
            pAh[j] = pk16(h0, h1); pAl[j] = pk16(l0, l1);
            pBh[j] = pk16(h2, h3); pBl[j] = pk16(l2, l3);
        }
        sa  += __shfl_xor_sync(0xffffffffu, sa, 1);
        sa  += __shfl_xor_sync(0xffffffffu, sa, 2);
        sb2 += __shfl_xor_sync(0xffffffffu, sb2, 1);
        sb2 += __shfl_xor_sync(0xffffffffu, sb2, 2);
        m_a = mna; m_b = mnb;
        l_a = l_a * aa + sa; l_b = l_b * ab + sb2;

#pragma unroll
        for (int n = 0; n < 16; n++) {
            o_[n][0] *= aa; o_[n][1] *= aa; o_[n][2] *= ab; o_[n][3] *= ab;
        }

#pragma unroll
        for (int kp = 0; kp < 4; kp++) {
            uint32_t ah4[4] = { pAh[2*kp], pBh[2*kp], pAh[2*kp+1], pBh[2*kp+1] };
            uint32_t al4[4] = { pAl[2*kp], pBl[2*kp], pAl[2*kp+1], pBl[2*kp+1] };
            int vrow = kp * 16 + (lane & 15);
#pragma unroll
            for (int nb = 0; nb < 8; nb++) {
                uint32_t ch = (uint32_t)(nb * 2 + lh);
                uint32_t voff = (uint32_t)(vrow * 256 + ((ch ^ (vrow & 15)) << 4));
                uint32_t h0, h1, h2, h3;
                LDSM4T(h0, h1, h2, h3, bs + ATT_PLANE_B + voff);
                uint32_t bh0[2] = { h0, h1 }, bh1[2] = { h2, h3 };
                MMA16816(o_[2*nb],   ah4, bh0); MMA16816(o_[2*nb],   al4, bh0);
                MMA16816(o_[2*nb+1], ah4, bh1); MMA16816(o_[2*nb+1], al4, bh1);
            }
        }

        if (++st == ATT_NSTAGE) st = 0;
    }

    float ia = 1.f / l_a, ib = 1.f / l_b;
    size_t r0 = (size_t)(b * SEQ + q0 + wrow + (lane >> 2)) * DMODEL + h * DHEAD + 2 * (lane & 3);
    size_t r1 = r0 + (size_t)8 * DMODEL;
#pragma unroll
    for (int n = 0; n < 16; n++) {
        __half h0, l0, h1, l1;
        split1(o_[n][0] * ia, h0, l0); split1(o_[n][1] * ia, h1, l1);
        *(uint32_t*)&ohi[r0 + n*8] = pk16(h0, h1);
        *(uint32_t*)&olo[r0 + n*8] = pk16(l0, l1);
        split1(o_[n][2] * ib, h0, l0); split1(o_[n][3] * ib, h1, l1);
        *(uint32_t*)&ohi[r1 + n*8] = pk16(h0, h1);
        *(uint32_t*)&olo[r1 + n*8] = pk16(l0, l1);
    }
}

// ============================================================================
extern "C" void kernel_launch(void* const* d_in, const int* in_sizes, int n_in,
                              void* d_out, int out_size)
{
    const float* x  = (const float*)d_in[0];
    const float* rc = (const float*)d_in[1];
    const float* rs = (const float*)d_in[2];
    const float* Wq = (const float*)d_in[3];
    const float* Wk = (const float*)d_in[4];
    const float* Wv = (const float*)d_in[5];
    const float* Wo = (const float*)d_in[6];
    float* out = (float*)d_out;

    float *q, *k, *v;
    cudaGetSymbolAddress((void**)&q, g_q);
    cudaGetSymbolAddress((void**)&k, g_k);
    cudaGetSymbolAddress((void**)&v, g_v);

    __half *xhi, *xlo, *wq, *wk, *wv, *wo, *atthi, *attlo, *khi, *vhi;
    cudaGetSymbolAddress((void**)&xhi, g_xhi);   cudaGetSymbolAddress((void**)&xlo, g_xlo);
    cudaGetSymbolAddress((void**)&wq, g_wq);     cudaGetSymbolAddress((void**)&wk, g_wk);
    cudaGetSymbolAddress((void**)&wv, g_wv);     cudaGetSymbolAddress((void**)&wo, g_wo);
    cudaGetSymbolAddress((void**)&atthi, g_atthi); cudaGetSymbolAddress((void**)&attlo, g_attlo);
    cudaGetSymbolAddress((void**)&khi, g_khi);   cudaGetSymbolAddress((void**)&vhi, g_vhi);

    cudaFuncSetAttribute(gemm_2p, cudaFuncAttributeMaxDynamicSharedMemorySize, GEMM_SMEM);
    cudaFuncSetAttribute(attn_tc, cudaFuncAttributeMaxDynamicSharedMemorySize, ATT_TC_SMEM);

    const int npx = MROWS * DMODEL / 2;
    const int npw = DMODEL * DMODEL / 2;
    pack_split<<<(npx + 255) / 256, 256>>>(x, (uint32_t*)xhi, (uint32_t*)xlo, npx);
    pack_single<<<(npw + 255) / 256, 256>>>(Wq, (uint32_t*)wq, npw);
    pack_single<<<(npw + 255) / 256, 256>>>(Wk, (uint32_t*)wk, npw);
    pack_single<<<(npw + 255) / 256, 256>>>(Wv, (uint32_t*)wv, npw);
    pack_single<<<(npw + 255) / 256, 256>>>(Wo, (uint32_t*)wo, npw);

    gemm_2p<<<dim3(DMODEL / 128, MROWS / 128, 3), 512, GEMM_SMEM>>>(
        xhi, xlo, wq, wk, wv, q, k, v);

    int rope_threads = BATCH * SEQ * NHEADS * 32;
    rope_pack<<<(rope_threads + 255) / 256, 256>>>(q, k, v, rc, rs, khi, vhi);

    attn_tc<<<dim3(SEQ / 128, NHEADS, BATCH), 256, ATT_TC_SMEM>>>(q, khi, vhi, atthi, attlo);

    gemm_2p<<<dim3(DMODEL / 128, MROWS / 128, 1), 512, GEMM_SMEM>>>(
        atthi, attlo, wo, wo, wo, out, out, out);
}

// round 11
// speedup vs baseline: 1.5560x; 1.0537x over previous
#include <cuda_runtime.h>
#include <cuda_fp16.h>
#include <math.h>
#include <stdint.h>

// Problem constants
#define BATCH 2
#define SEQ   2048
#define DMODEL 2048
#define NHEADS 16
#define DHEAD 128
#define MROWS (BATCH*SEQ)          // 4096
#define KDIM  DMODEL

// -------------------- scratch (static device globals; no allocation) ------
__device__ __align__(16) __half g_xhi[MROWS * DMODEL];
__device__ __align__(16) __half g_xlo[MROWS * DMODEL];
__device__ __align__(16) __half g_wq[DMODEL * DMODEL];
__device__ __align__(16) __half g_wk[DMODEL * DMODEL];
__device__ __align__(16) __half g_wv[DMODEL * DMODEL];
__device__ __align__(16) __half g_wo[DMODEL * DMODEL];
__device__ __align__(16) __half g_qh[MROWS * DMODEL];
__device__ __align__(16) __half g_kh[MROWS * DMODEL];
__device__ __align__(16) __half g_vh[MROWS * DMODEL];
__device__ __align__(16) __half g_atthi[MROWS * DMODEL];
__device__ __align__(16) __half g_attlo[MROWS * DMODEL];

// ============================ PTX helpers ==================================
__device__ __forceinline__ uint32_t smem_u32(const void* p) {
    uint32_t a;
    asm("{ .reg .u64 t; cvta.to.shared.u64 t, %1; cvt.u32.u64 %0, t; }" : "=r"(a) : "l"(p));
    return a;
}
#define CP_ASYNC16(dst, src) \
    asm volatile("cp.async.cg.shared.global [%0], [%1], 16;" :: "r"(dst), "l"(src))
#define CP_COMMIT() asm volatile("cp.async.commit_group;" ::: "memory")
#define CP_WAIT(n)  asm volatile("cp.async.wait_group %0;" :: "n"(n) : "memory")

#define LDSM4(r0, r1, r2, r3, addr) \
    asm volatile("ldmatrix.sync.aligned.m8n8.x4.shared.b16 {%0,%1,%2,%3}, [%4];" \
        : "=r"(r0), "=r"(r1), "=r"(r2), "=r"(r3) : "r"(addr))
#define LDSM4T(r0, r1, r2, r3, addr) \
    asm volatile("ldmatrix.sync.aligned.m8n8.x4.trans.shared.b16 {%0,%1,%2,%3}, [%4];" \
        : "=r"(r0), "=r"(r1), "=r"(r2), "=r"(r3) : "r"(addr))

#define MMA16816(c, a, b) \
    asm volatile("mma.sync.aligned.m16n8k16.row.col.f32.f16.f16.f32 " \
        "{%0,%1,%2,%3},{%4,%5,%6,%7},{%8,%9},{%0,%1,%2,%3};" \
        : "+f"((c)[0]), "+f"((c)[1]), "+f"((c)[2]), "+f"((c)[3]) \
        : "r"((a)[0]), "r"((a)[1]), "r"((a)[2]), "r"((a)[3]), "r"((b)[0]), "r"((b)[1]))

__device__ __forceinline__ uint32_t pk16(__half a, __half b) {
    return (uint32_t)__half_as_ushort(a) | ((uint32_t)__half_as_ushort(b) << 16);
}
__device__ __forceinline__ void split1(float x, __half& h, __half& l) {
    h = __float2half(x);
    l = __float2half(x - __half2float(h));
}

// ============================================================================
// pack_split / pack_single
// ============================================================================
__global__ __launch_bounds__(256)
void pack_split(const float* __restrict__ src,
                uint32_t* __restrict__ hi, uint32_t* __restrict__ lo, int npairs)
{
    int i = blockIdx.x * 256 + threadIdx.x;
    if (i >= npairs) return;
    float2 v = ((const float2*)src)[i];
    __half h0, l0, h1, l1;
    split1(v.x, h0, l0); split1(v.y, h1, l1);
    hi[i] = pk16(h0, h1);
    lo[i] = pk16(l0, l1);
}

__global__ __launch_bounds__(256)
void pack_single(const float* __restrict__ src, uint32_t* __restrict__ dst, int npairs)
{
    int i = blockIdx.x * 256 + threadIdx.x;
    if (i >= npairs) return;
    float2 v = ((const float2*)src)[i];
    dst[i] = pk16(__float2half(v.x), __float2half(v.y));
}

// ============================================================================
// gemm cores: 2 products (A hi/lo split, B single fp16). BKD=64, 2 stages.
// gemm_2p_h writes fp16 C (QKV); gemm_2p writes fp32 C (output proj).
// ============================================================================
#define BKD 64
#define TILE_B   (128 * BKD * 2)              // 16 KB
#define STAGE_B  (3 * TILE_B)                 // 48 KB
#define GEMM_SMEM (2 * STAGE_B)               // 96 KB

// shared mainloop body via macro to keep both kernels identical except epilogue
#define GEMM_BODY(EPILOGUE)                                                          \
    extern __shared__ char smc[];                                                    \
    const uint32_t sb = smem_u32(smc);                                               \
    const int tid  = threadIdx.x;                                                    \
    const int lane = tid & 31;                                                       \
    const int wid  = tid >> 5;                                                       \
    const int wm   = wid & 3;                                                        \
    const int wn   = wid >> 2;                                                       \
    const int m0   = blockIdx.y * 128;                                               \
    const int n0   = blockIdx.x * 128;                                               \
    const int z    = blockIdx.z;                                                     \
    const __half* B = (z == 0) ? B0 : (z == 1) ? B1 : B2;                            \
    const int rA = tid >> 3, cA = tid & 7;                                           \
    const int rB = (tid + 512) >> 3, cB = (tid + 512) & 7;                           \
    const uint32_t dA = (uint32_t)(rA * 128 + ((cA ^ (rA & 7)) << 4));               \
    const uint32_t dB = (uint32_t)(rB * 128 + ((cB ^ (rB & 7)) << 4));               \
    const __half* srcA[2] = { Ahi + (size_t)m0 * KDIM, Alo + (size_t)m0 * KDIM };    \
    const __half* srcB = B + (size_t)n0 * KDIM;                                      \
    auto load_stage = [&](int s, int kb) {                                           \
        uint32_t base = sb + s * STAGE_B;                                            \
        int koff = kb * BKD;                                                         \
        _Pragma("unroll")                                                            \
        for (int t = 0; t < 2; t++) {                                                \
            CP_ASYNC16(base + t * TILE_B + dA, srcA[t] + (size_t)rA * KDIM + koff + cA * 8); \
            CP_ASYNC16(base + t * TILE_B + dB, srcA[t] + (size_t)rB * KDIM + koff + cB * 8); \
        }                                                                            \
        CP_ASYNC16(base + 2 * TILE_B + dA, srcB + (size_t)rA * KDIM + koff + cA * 8);\
        CP_ASYNC16(base + 2 * TILE_B + dB, srcB + (size_t)rB * KDIM + koff + cB * 8);\
    };                                                                               \
    float acc[2][4][4];                                                              \
    _Pragma("unroll")                                                                \
    for (int i = 0; i < 2; i++)                                                      \
        for (int j = 0; j < 4; j++)                                                  \
            for (int r = 0; r < 4; r++) acc[i][j][r] = 0.f;                          \
    load_stage(0, 0); CP_COMMIT();                                                   \
    const int arow = wm * 32 + (lane & 15);                                          \
    const int bnrow = wn * 32 + (lane & 15);                                         \
    const int lhalf = lane >> 4;                                                     \
    const int NKB = KDIM / BKD;                                                      \
    for (int kc = 0; kc < NKB; kc++) {                                               \
        if (kc + 1 < NKB) { load_stage((kc + 1) & 1, kc + 1); CP_COMMIT(); CP_WAIT(1); } \
        else             { CP_WAIT(0); }                                             \
        __syncthreads();                                                             \
        uint32_t base = sb + (kc & 1) * STAGE_B;                                     \
        uint32_t aHb = base, aLb = base + TILE_B, bHb = base + 2 * TILE_B;           \
        _Pragma("unroll")                                                            \
        for (int ks = 0; ks < 4; ks++) {                                             \
            uint32_t ah[2][4], al[2][4], bh[4][2];                                   \
            _Pragma("unroll")                                                        \
            for (int i = 0; i < 2; i++) {                                            \
                int row = arow + i * 16;                                             \
                uint32_t off = (uint32_t)(row * 128 + (((ks * 2 + lhalf) ^ (row & 7)) << 4)); \
                LDSM4(ah[i][0], ah[i][1], ah[i][2], ah[i][3], aHb + off);            \
                LDSM4(al[i][0], al[i][1], al[i][2], al[i][3], aLb + off);            \
            }                                                                        \
            _Pragma("unroll")                                                        \
            for (int jp = 0; jp < 2; jp++) {                                         \
                int row = bnrow + jp * 16;                                           \
                uint32_t off = (uint32_t)(row * 128 + (((ks * 2 + lhalf) ^ (row & 7)) << 4)); \
                uint32_t r0, r1_, r2_, r3_;                                          \
                LDSM4(r0, r1_, r2_, r3_, bHb + off);                                 \
                bh[2 * jp][0] = r0;  bh[2 * jp][1] = r2_;                            \
                bh[2 * jp + 1][0] = r1_; bh[2 * jp + 1][1] = r3_;                    \
            }                                                                        \
            _Pragma("unroll")                                                        \
            for (int i = 0; i < 2; i++)                                              \
                for (int j = 0; j < 4; j++) {                                        \
                    MMA16816(acc[i][j], ah[i], bh[j]);                               \
                    MMA16816(acc[i][j], al[i], bh[j]);                               \
                }                                                                    \
        }                                                                            \
        __syncthreads();                                                             \
    }                                                                                \
    EPILOGUE

__global__ __launch_bounds__(512)
void gemm_2p(const __half* __restrict__ Ahi, const __half* __restrict__ Alo,
             const __half* __restrict__ B0, const __half* __restrict__ B1,
             const __half* __restrict__ B2,
             float* __restrict__ C0, float* __restrict__ C1, float* __restrict__ C2)
{
    GEMM_BODY({
        float* C = (z == 0) ? C0 : (z == 1) ? C1 : C2;
#pragma unroll
        for (int i = 0; i < 2; i++)
#pragma unroll
            for (int j = 0; j < 4; j++) {
                int m = m0 + wm * 32 + i * 16 + (lane >> 2);
                int n = n0 + wn * 32 + j * 8 + (lane & 3) * 2;
                *(float2*)&C[(size_t)m * DMODEL + n]       = make_float2(acc[i][j][0], acc[i][j][1]);
                *(float2*)&C[(size_t)(m + 8) * DMODEL + n] = make_float2(acc[i][j][2], acc[i][j][3]);
            }
    })
}

__global__ __launch_bounds__(512)
void gemm_2p_h(const __half* __restrict__ Ahi, const __half* __restrict__ Alo,
               const __half* __restrict__ B0, const __half* __restrict__ B1,
               const __half* __restrict__ B2,
               __half* __restrict__ C0, __half* __restrict__ C1, __half* __restrict__ C2)
{
    GEMM_BODY({
        __half* C = (z == 0) ? C0 : (z == 1) ? C1 : C2;
#pragma unroll
        for (int i = 0; i < 2; i++)
#pragma unroll
            for (int j = 0; j < 4; j++) {
                int m = m0 + wm * 32 + i * 16 + (lane >> 2);
                int n = n0 + wn * 32 + j * 8 + (lane & 3) * 2;
                *(uint32_t*)&C[(size_t)m * DMODEL + n] =
                    pk16(__float2half(acc[i][j][0]), __float2half(acc[i][j][1]));
                *(uint32_t*)&C[(size_t)(m + 8) * DMODEL + n] =
                    pk16(__float2half(acc[i][j][2]), __float2half(acc[i][j][3]));
            }
    })
}

// ============================================================================
// rope_qk: in-place fp16 rope. q additionally scaled by 1/sqrt(dh).
// Each thread owns 2 consecutive d's in both rotation halves of one (b,s,h).
// ============================================================================
__global__ __launch_bounds__(256)
void rope_qk(__half* __restrict__ qh, __half* __restrict__ kh,
             const float* __restrict__ rc, const float* __restrict__ rs)
{
    int idx = blockIdx.x * 256 + threadIdx.x;
    const int total = BATCH * SEQ * NHEADS * 32;
    if (idx >= total) return;
    int d = (idx & 31) * 2;
    int h = (idx >> 5) & (NHEADS - 1);
    int s = (idx >> 9) & (SEQ - 1);
    int b = idx >> 20;
    size_t base = ((size_t)(b * SEQ + s)) * DMODEL + h * DHEAD;
    const float scale = 0.088388347648318447f;   // 1/sqrt(128)

    float2 c0 = *(const float2*)&rc[s * DHEAD + d];
    float2 s0 = *(const float2*)&rs[s * DHEAD + d];
    float2 c1 = *(const float2*)&rc[s * DHEAD + 64 + d];
    float2 s1 = *(const float2*)&rs[s * DHEAD + 64 + d];

    __half2 qa2 = *(__half2*)&qh[base + d];
    __half2 qb2 = *(__half2*)&qh[base + 64 + d];
    float2 qa = __half22float2(qa2), qb = __half22float2(qb2);
    *(uint32_t*)&qh[base + d] = pk16(
        __float2half((qa.x * c0.x - qb.x * s0.x) * scale),
        __float2half((qa.y * c0.y - qb.y * s0.y) * scale));
    *(uint32_t*)&qh[base + 64 + d] = pk16(
        __float2half((qb.x * c1.x + qa.x * s1.x) * scale),
        __float2half((qb.y * c1.y + qa.y * s1.y) * scale));

    __half2 ka2 = *(__half2*)&kh[base + d];
    __half2 kb2 = *(__half2*)&kh[base + 64 + d];
    float2 ka = __half22float2(ka2), kb = __half22float2(kb2);
    *(uint32_t*)&kh[base + d] = pk16(
        __float2half(ka.x * c0.x - kb.x * s0.x),
        __float2half(ka.y * c0.y - kb.y * s0.y));
    *(uint32_t*)&kh[base + 64 + d] = pk16(
        __float2half(kb.x * c1.x + ka.x * s1.x),
        __float2half(kb.y * c1.y + ka.y * s1.y));
}

// ============================================================================
// attn_tc: flash attention, all-fp16 operands.
// QK 1-product (Q, K single planes); PV 2-product (P hi/lo, V single).
// Q loaded by cp.async into swizzled smem (32KB); 3 KV stages x 32KB.
// ============================================================================
#define NKT (SEQ/64)
#define ATT_PLANE_B 16384
#define ATT_STAGE_B (2*ATT_PLANE_B)              // 32 KB
#define ATT_Q_B     32768                        // single fp16 plane, 128x128
#define ATT_NSTAGE  3
#define ATT_TC_SMEM (ATT_Q_B + ATT_NSTAGE*ATT_STAGE_B)   // 131072

__global__ __launch_bounds__(256, 1)
void attn_tc(const __half* __restrict__ qh,
             const __half* __restrict__ khi,
             const __half* __restrict__ vhi,
             __half* __restrict__ ohi, __half* __restrict__ olo)
{
    extern __shared__ char smc[];
    const uint32_t sb = smem_u32(smc);
    const uint32_t QH = sb;
    const uint32_t ST = sb + ATT_Q_B;

    const int tid = threadIdx.x;
    const int lane = tid & 31;
    const int wid = tid >> 5;
    const int b = blockIdx.z, h = blockIdx.y;
    const int q0 = blockIdx.x * 128;
    const int wrow = wid * 16;

    // ---- Q plane via cp.async (128 rows x 256B, swizzled) ----
    {
        const __half* src0 = qh + ((size_t)(b * SEQ + q0)) * DMODEL + h * DHEAD;
#pragma unroll
        for (int i = 0; i < 8; i++) {
            int idx = tid + i * 256;            // 0..2047 chunks
            int row = idx >> 4, ch = idx & 15;
            uint32_t dst = QH + row * 256 + ((ch ^ (row & 15)) << 4);
            CP_ASYNC16(dst, src0 + (size_t)row * DMODEL + ch * 8);
        }
    }

    const __half* pl[2] = { khi, vhi };
    auto load_kv = [&](int st, int kt) {
        uint32_t base = ST + st * ATT_STAGE_B;
#pragma unroll
        for (int i = 0; i < 8; i++) {
            int idx = tid + i * 256;
            int p = idx >> 10;
            int c = idx & 1023;
            int row = c >> 4, ch = c & 15;
            const __half* src = pl[p] +
                ((size_t)(b * SEQ + kt * 64 + row)) * DMODEL + h * DHEAD + ch * 8;
            uint32_t dst = base + p * ATT_PLANE_B + row * 256 + ((ch ^ (row & 15)) << 4);
            CP_ASYNC16(dst, src);
        }
    };

    float o_[16][4];
#pragma unroll
    for (int n = 0; n < 16; n++)
#pragma unroll
        for (int r = 0; r < 4; r++) o_[n][r] = 0.f;
    float m_a = -3.0e38f, m_b = -3.0e38f, l_a = 0.f, l_b = 0.f;

    load_kv(0, 0); CP_COMMIT();          // group: Q plane + kv0
    load_kv(1, 1); CP_COMMIT();

    const int qrow = wrow + (lane & 15);
    const int lh = lane >> 4;

    int st = 0;
    for (int kt = 0; kt < NKT; kt++) {
        CP_WAIT(1);
        __syncthreads();
        uint32_t bs = ST + st * ATT_STAGE_B;

        if (kt + 2 < NKT) {
            int st2 = st + 2; if (st2 >= ATT_NSTAGE) st2 -= ATT_NSTAGE;
            load_kv(st2, kt + 2); CP_COMMIT();
        } else {
            CP_COMMIT();
        }

        // ---- scores: plain fp16 Q.K^T, fp32 accumulate ----
        float s[8][4];
#pragma unroll
        for (int j = 0; j < 8; j++)
#pragma unroll
            for (int r = 0; r < 4; r++) s[j][r] = 0.f;

#pragma unroll
        for (int ks = 0; ks < 8; ks++) {
            uint32_t qoff = (uint32_t)(qrow * 256 + (((ks * 2 + lh) ^ (qrow & 15)) << 4));
            uint32_t ah[4];
            LDSM4(ah[0], ah[1], ah[2], ah[3], QH + qoff);
#pragma unroll
            for (int nb = 0; nb < 4; nb++) {
                int krow = nb * 16 + (lane & 15);
                uint32_t koff = (uint32_t)(krow * 256 + (((ks * 2 + lh) ^ (krow & 15)) << 4));
                uint32_t h0, h1, h2, h3;
                LDSM4(h0, h1, h2, h3, bs + koff);
                uint32_t bh0[2] = { h0, h2 }, bh1[2] = { h1, h3 };
                MMA16816(s[2*nb],   ah, bh0);
                MMA16816(s[2*nb+1], ah, bh1);
            }
        }

        float mla = -3.0e38f, mlb = -3.0e38f;
#pragma unroll
        for (int j = 0; j < 8; j++) {
            mla = fmaxf(mla, fmaxf(s[j][0], s[j][1]));
            mlb = fmaxf(mlb, fmaxf(s[j][2], s[j][3]));
        }
        mla = fmaxf(mla, __shfl_xor_sync(0xffffffffu, mla, 1));
        mla = fmaxf(mla, __shfl_xor_sync(0xffffffffu, mla, 2));
        mlb = fmaxf(mlb, __shfl_xor_sync(0xffffffffu, mlb, 1));
        mlb = fmaxf(mlb, __shfl_xor_sync(0xffffffffu, mlb, 2));
        float mna = fmaxf(m_a, mla), mnb = fmaxf(m_b, mlb);
        float aa = __expf(m_a - mna), ab = __expf(m_b - mnb);

        uint32_t pAh[8], pBh[8], pAl[8], pBl[8];
        float sa = 0.f, sb2 = 0.f;
#pragma unroll
        for (int j = 0; j < 8; j++) {
            float p0 = __expf(s[j][0] - mna), p1 = __expf(s[j][1] - mna);
            float p2 = __expf(s[j][2] - mnb), p3 = __expf(s[j][3] - mnb);
            sa += p0 + p1; sb2 += p2 + p3;
            __half h0, l0, h1, l1, h2, l2, h3, l3;
            split1(p0, h0, l0); split1(p1, h1, l1);
            split1(p2, h2, l2); split1(p3, h3, l3);
            pAh[j] = pk16(h0, h1); pAl[j] = pk16(l0, l1);
            pBh[j] = pk16(h2, h3); pBl[j] = pk16(l2, l3);
        }
        sa  += __shfl_xor_sync(0xffffffffu, sa, 1);
        sa  += __shfl_xor_sync(0xffffffffu, sa, 2);
        sb2 += __shfl_xor_sync(0xffffffffu, sb2, 1);
        sb2 += __shfl_xor_sync(0xffffffffu, sb2, 2);
        m_a = mna; m_b = mnb;
        l_a = l_a * aa + sa; l_b = l_b * ab + sb2;

#pragma unroll
        for (int n = 0; n < 16; n++) {
            o_[n][0] *= aa; o_[n][1] *= aa; o_[n][2] *= ab; o_[n][3] *= ab;
        }

        // ---- PV: 2 products (P hi/lo, V single), V via ldmatrix.trans ----
#pragma unroll
        for (int kp = 0; kp < 4; kp++) {
            uint32_t ah4[4] = { pAh[2*kp], pBh[2*kp], pAh[2*kp+1], pBh[2*kp+1] };
            uint32_t al4[4] = { pAl[2*kp], pBl[2*kp], pAl[2*kp+1], pBl[2*kp+1] };
            int vrow = kp * 16 + (lane & 15);
#pragma unroll
            for (int nb = 0; nb < 8; nb++) {
                uint32_t ch = (uint32_t)(nb * 2 + lh);
                uint32_t voff = (uint32_t)(vrow * 256 + ((ch ^ (vrow & 15)) << 4));
                uint32_t h0, h1, h2, h3;
                LDSM4T(h0, h1, h2, h3, bs + ATT_PLANE_B + voff);
                uint32_t bh0[2] = { h0, h1 }, bh1[2] = { h2, h3 };
                MMA16816(o_[2*nb],   ah4, bh0); MMA16816(o_[2*nb],   al4, bh0);
                MMA16816(o_[2*nb+1], ah4, bh1); MMA16816(o_[2*nb+1], al4, bh1);
            }
        }

        if (++st == ATT_NSTAGE) st = 0;
    }

    float ia = 1.f / l_a, ib = 1.f / l_b;
    size_t r0 = (size_t)(b * SEQ + q0 + wrow + (lane >> 2)) * DMODEL + h * DHEAD + 2 * (lane & 3);
    size_t r1 = r0 + (size_t)8 * DMODEL;
#pragma unroll
    for (int n = 0; n < 16; n++) {
        __half h0, l0, h1, l1;
        split1(o_[n][0] * ia, h0, l0); split1(o_[n][1] * ia, h1, l1);
        *(uint32_t*)&ohi[r0 + n*8] = pk16(h0, h1);
        *(uint32_t*)&olo[r0 + n*8] = pk16(l0, l1);
        split1(o_[n][2] * ib, h0, l0); split1(o_[n][3] * ib, h1, l1);
        *(uint32_t*)&ohi[r1 + n*8] = pk16(h0, h1);
        *(uint32_t*)&olo[r1 + n*8] = pk16(l0, l1);
    }
}

// ============================================================================
extern "C" void kernel_launch(void* const* d_in, const int* in_sizes, int n_in,
                              void* d_out, int out_size)
{
    const float* x  = (const float*)d_in[0];
    const float* rc = (const float*)d_in[1];
    const float* rs = (const float*)d_in[2];
    const float* Wq = (const float*)d_in[3];
    const float* Wk = (const float*)d_in[4];
    const float* Wv = (const float*)d_in[5];
    const float* Wo = (const float*)d_in[6];
    float* out = (float*)d_out;

    __half *xhi, *xlo, *wq, *wk, *wv, *wo, *qhp, *khp, *vhp, *atthi, *attlo;
    cudaGetSymbolAddress((void**)&xhi, g_xhi);   cudaGetSymbolAddress((void**)&xlo, g_xlo);
    cudaGetSymbolAddress((void**)&wq, g_wq);     cudaGetSymbolAddress((void**)&wk, g_wk);
    cudaGetSymbolAddress((void**)&wv, g_wv);     cudaGetSymbolAddress((void**)&wo, g_wo);
    cudaGetSymbolAddress((void**)&qhp, g_qh);    cudaGetSymbolAddress((void**)&khp, g_kh);
    cudaGetSymbolAddress((void**)&vhp, g_vh);
    cudaGetSymbolAddress((void**)&atthi, g_atthi); cudaGetSymbolAddress((void**)&attlo, g_attlo);

    cudaFuncSetAttribute(gemm_2p,   cudaFuncAttributeMaxDynamicSharedMemorySize, GEMM_SMEM);
    cudaFuncSetAttribute(gemm_2p_h, cudaFuncAttributeMaxDynamicSharedMemorySize, GEMM_SMEM);
    cudaFuncSetAttribute(attn_tc,   cudaFuncAttributeMaxDynamicSharedMemorySize, ATT_TC_SMEM);

    const int npx = MROWS * DMODEL / 2;
    const int npw = DMODEL * DMODEL / 2;
    pack_split<<<(npx + 255) / 256, 256>>>(x, (uint32_t*)xhi, (uint32_t*)xlo, npx);
    pack_single<<<(npw + 255) / 256, 256>>>(Wq, (uint32_t*)wq, npw);
    pack_single<<<(npw + 255) / 256, 256>>>(Wk, (uint32_t*)wk, npw);
    pack_single<<<(npw + 255) / 256, 256>>>(Wv, (uint32_t*)wv, npw);
    pack_single<<<(npw + 255) / 256, 256>>>(Wo, (uint32_t*)wo, npw);

    // QKV projection directly to fp16 planes
    gemm_2p_h<<<dim3(DMODEL / 128, MROWS / 128, 3), 512, GEMM_SMEM>>>(
        xhi, xlo, wq, wk, wv, qhp, khp, vhp);

    int rope_threads = BATCH * SEQ * NHEADS * 32;
    rope_qk<<<(rope_threads + 255) / 256, 256>>>(qhp, khp, rc, rs);

    attn_tc<<<dim3(SEQ / 128, NHEADS, BATCH), 256, ATT_TC_SMEM>>>(qhp, khp, vhp, atthi, attlo);

    gemm_2p<<<dim3(DMODEL / 128, MROWS / 128, 1), 512, GEMM_SMEM>>>(
        atthi, attlo, wo, wo, wo, out, out, out);
}

// round 12
// speedup vs baseline: 2.2609x; 1.4530x over previous
#include <cuda_runtime.h>
#include <cuda_fp16.h>
#include <math.h>
#include <stdint.h>

// Problem constants
#define BATCH 2
#define SEQ   2048
#define DMODEL 2048
#define NHEADS 16
#define DHEAD 128
#define MROWS (BATCH*SEQ)          // 4096
#define KDIM  DMODEL

// -------------------- scratch (static device globals; no allocation) ------
__device__ __align__(16) __half g_xh[MROWS * DMODEL];
__device__ __align__(16) __half g_wq[DMODEL * DMODEL];
__device__ __align__(16) __half g_wk[DMODEL * DMODEL];
__device__ __align__(16) __half g_wv[DMODEL * DMODEL];
__device__ __align__(16) __half g_wo[DMODEL * DMODEL];
__device__ __align__(16) __half g_qh[MROWS * DMODEL];
__device__ __align__(16) __half g_kh[MROWS * DMODEL];
__device__ __align__(16) __half g_vh[MROWS * DMODEL];
__device__ __align__(16) __half g_atthi[MROWS * DMODEL];
__device__ __align__(16) __half g_attlo[MROWS * DMODEL];

// ============================ PTX helpers ==================================
__device__ __forceinline__ uint32_t smem_u32(const void* p) {
    uint32_t a;
    asm("{ .reg .u64 t; cvta.to.shared.u64 t, %1; cvt.u32.u64 %0, t; }" : "=r"(a) : "l"(p));
    return a;
}
#define CP_ASYNC16(dst, src) \
    asm volatile("cp.async.cg.shared.global [%0], [%1], 16;" :: "r"(dst), "l"(src))
#define CP_COMMIT() asm volatile("cp.async.commit_group;" ::: "memory")
#define CP_WAIT(n)  asm volatile("cp.async.wait_group %0;" :: "n"(n) : "memory")

#define LDSM4(r0, r1, r2, r3, addr) \
    asm volatile("ldmatrix.sync.aligned.m8n8.x4.shared.b16 {%0,%1,%2,%3}, [%4];" \
        : "=r"(r0), "=r"(r1), "=r"(r2), "=r"(r3) : "r"(addr))
#define LDSM4T(r0, r1, r2, r3, addr) \
    asm volatile("ldmatrix.sync.aligned.m8n8.x4.trans.shared.b16 {%0,%1,%2,%3}, [%4];" \
        : "=r"(r0), "=r"(r1), "=r"(r2), "=r"(r3) : "r"(addr))

#define MMA16816(c, a, b) \
    asm volatile("mma.sync.aligned.m16n8k16.row.col.f32.f16.f16.f32 " \
        "{%0,%1,%2,%3},{%4,%5,%6,%7},{%8,%9},{%0,%1,%2,%3};" \
        : "+f"((c)[0]), "+f"((c)[1]), "+f"((c)[2]), "+f"((c)[3]) \
        : "r"((a)[0]), "r"((a)[1]), "r"((a)[2]), "r"((a)[3]), "r"((b)[0]), "r"((b)[1]))

__device__ __forceinline__ uint32_t pk16(__half a, __half b) {
    return (uint32_t)__half_as_ushort(a) | ((uint32_t)__half_as_ushort(b) << 16);
}
__device__ __forceinline__ void split1(float x, __half& h, __half& l) {
    h = __float2half(x);
    l = __float2half(x - __half2float(h));
}

// ============================================================================
// pack_single: fp32 -> fp16 plane (coalesced uint32 I/O)
// ============================================================================
__global__ __launch_bounds__(256)
void pack_single(const float* __restrict__ src, uint32_t* __restrict__ dst, int npairs)
{
    int i = blockIdx.x * 256 + threadIdx.x;
    if (i >= npairs) return;
    float2 v = ((const float2*)src)[i];
    dst[i] = pk16(__float2half(v.x), __float2half(v.y));
}

// ============================================================================
// gemm_1p_h: C_z = A @ B_z^T, plain fp16 operands, fp32 accumulate, fp16 out.
// 512 threads / 16 warps (4m x 4n), BKD=64, 2 stages x 32KB.
// ============================================================================
#define BKD 64
#define TILE_B   (128 * BKD * 2)              // 16 KB per plane
#define STG1_B   (2 * TILE_B)                 // 32 KB (A, B)
#define G1_SMEM  (2 * STG1_B)                 // 64 KB
#define STG2_B   (3 * TILE_B)                 // 48 KB (Ahi, Alo, B)
#define G2_SMEM  (2 * STG2_B)                 // 96 KB

__global__ __launch_bounds__(512)
void gemm_1p_h(const __half* __restrict__ A,
               const __half* __restrict__ B0, const __half* __restrict__ B1,
               const __half* __restrict__ B2,
               __half* __restrict__ C0, __half* __restrict__ C1, __half* __restrict__ C2)
{
    extern __shared__ char smc[];
    const uint32_t sb = smem_u32(smc);

    const int tid  = threadIdx.x;
    const int lane = tid & 31;
    const int wid  = tid >> 5;
    const int wm   = wid & 3;
    const int wn   = wid >> 2;
    const int m0   = blockIdx.y * 128;
    const int n0   = blockIdx.x * 128;
    const int z    = blockIdx.z;

    const __half* B = (z == 0) ? B0 : (z == 1) ? B1 : B2;
    __half* C = (z == 0) ? C0 : (z == 1) ? C1 : C2;

    const int rA = tid >> 3, cA = tid & 7;
    const int rB = (tid + 512) >> 3, cB = (tid + 512) & 7;
    const uint32_t dA = (uint32_t)(rA * 128 + ((cA ^ (rA & 7)) << 4));
    const uint32_t dB = (uint32_t)(rB * 128 + ((cB ^ (rB & 7)) << 4));

    const __half* srcA = A + (size_t)m0 * KDIM;
    const __half* srcB = B + (size_t)n0 * KDIM;

    auto load_stage = [&](int s, int kb) {
        uint32_t base = sb + s * STG1_B;
        int koff = kb * BKD;
        CP_ASYNC16(base + dA,          srcA + (size_t)rA * KDIM + koff + cA * 8);
        CP_ASYNC16(base + dB,          srcA + (size_t)rB * KDIM + koff + cB * 8);
        CP_ASYNC16(base + TILE_B + dA, srcB + (size_t)rA * KDIM + koff + cA * 8);
        CP_ASYNC16(base + TILE_B + dB, srcB + (size_t)rB * KDIM + koff + cB * 8);
    };

    float acc[2][4][4];
#pragma unroll
    for (int i = 0; i < 2; i++)
#pragma unroll
        for (int j = 0; j < 4; j++)
#pragma unroll
            for (int r = 0; r < 4; r++) acc[i][j][r] = 0.f;

    load_stage(0, 0); CP_COMMIT();

    const int arow = wm * 32 + (lane & 15);
    const int bnrow = wn * 32 + (lane & 15);
    const int lhalf = lane >> 4;

    const int NKB = KDIM / BKD;
    for (int kc = 0; kc < NKB; kc++) {
        if (kc + 1 < NKB) { load_stage((kc + 1) & 1, kc + 1); CP_COMMIT(); CP_WAIT(1); }
        else              { CP_WAIT(0); }
        __syncthreads();

        uint32_t base = sb + (kc & 1) * STG1_B;
        uint32_t aB = base, bB = base + TILE_B;

#pragma unroll
        for (int ks = 0; ks < 4; ks++) {
            uint32_t ah[2][4], bh[4][2];
#pragma unroll
            for (int i = 0; i < 2; i++) {
                int row = arow + i * 16;
                uint32_t off = (uint32_t)(row * 128 + (((ks * 2 + lhalf) ^ (row & 7)) << 4));
                LDSM4(ah[i][0], ah[i][1], ah[i][2], ah[i][3], aB + off);
            }
#pragma unroll
            for (int jp = 0; jp < 2; jp++) {
                int row = bnrow + jp * 16;
                uint32_t off = (uint32_t)(row * 128 + (((ks * 2 + lhalf) ^ (row & 7)) << 4));
                uint32_t r0, r1_, r2_, r3_;
                LDSM4(r0, r1_, r2_, r3_, bB + off);
                bh[2 * jp][0] = r0;  bh[2 * jp][1] = r2_;
                bh[2 * jp + 1][0] = r1_; bh[2 * jp + 1][1] = r3_;
            }
#pragma unroll
            for (int i = 0; i < 2; i++)
#pragma unroll
                for (int j = 0; j < 4; j++)
                    MMA16816(acc[i][j], ah[i], bh[j]);
        }
        __syncthreads();
    }

#pragma unroll
    for (int i = 0; i < 2; i++)
#pragma unroll
        for (int j = 0; j < 4; j++) {
            int m = m0 + wm * 32 + i * 16 + (lane >> 2);
            int n = n0 + wn * 32 + j * 8 + (lane & 3) * 2;
            *(uint32_t*)&C[(size_t)m * DMODEL + n] =
                pk16(__float2half(acc[i][j][0]), __float2half(acc[i][j][1]));
            *(uint32_t*)&C[(size_t)(m + 8) * DMODEL + n] =
                pk16(__float2half(acc[i][j][2]), __float2half(acc[i][j][3]));
        }
}

// ============================================================================
// gemm_2p: C = A @ B^T — 2 products (A hi/lo split, B single). fp32 out.
// Used for the output projection (att hi/lo planes).
// ============================================================================
__global__ __launch_bounds__(512)
void gemm_2p(const __half* __restrict__ Ahi, const __half* __restrict__ Alo,
             const __half* __restrict__ B,
             float* __restrict__ C)
{
    extern __shared__ char smc[];
    const uint32_t sb = smem_u32(smc);

    const int tid  = threadIdx.x;
    const int lane = tid & 31;
    const int wid  = tid >> 5;
    const int wm   = wid & 3;
    const int wn   = wid >> 2;
    const int m0   = blockIdx.y * 128;
    const int n0   = blockIdx.x * 128;

    const int rA = tid >> 3, cA = tid & 7;
    const int rB = (tid + 512) >> 3, cB = (tid + 512) & 7;
    const uint32_t dA = (uint32_t)(rA * 128 + ((cA ^ (rA & 7)) << 4));
    const uint32_t dB = (uint32_t)(rB * 128 + ((cB ^ (rB & 7)) << 4));

    const __half* srcA[2] = { Ahi + (size_t)m0 * KDIM, Alo + (size_t)m0 * KDIM };
    const __half* srcB = B + (size_t)n0 * KDIM;

    auto load_stage = [&](int s, int kb) {
        uint32_t base = sb + s * STG2_B;
        int koff = kb * BKD;
#pragma unroll
        for (int t = 0; t < 2; t++) {
            CP_ASYNC16(base + t * TILE_B + dA, srcA[t] + (size_t)rA * KDIM + koff + cA * 8);
            CP_ASYNC16(base + t * TILE_B + dB, srcA[t] + (size_t)rB * KDIM + koff + cB * 8);
        }
        CP_ASYNC16(base + 2 * TILE_B + dA, srcB + (size_t)rA * KDIM + koff + cA * 8);
        CP_ASYNC16(base + 2 * TILE_B + dB, srcB + (size_t)rB * KDIM + koff + cB * 8);
    };

    float acc[2][4][4];
#pragma unroll
    for (int i = 0; i < 2; i++)
#pragma unroll
        for (int j = 0; j < 4; j++)
#pragma unroll
            for (int r = 0; r < 4; r++) acc[i][j][r] = 0.f;

    load_stage(0, 0); CP_COMMIT();

    const int arow = wm * 32 + (lane & 15);
    const int bnrow = wn * 32 + (lane & 15);
    const int lhalf = lane >> 4;

    const int NKB = KDIM / BKD;
    for (int kc = 0; kc < NKB; kc++) {
        if (kc + 1 < NKB) { load_stage((kc + 1) & 1, kc + 1); CP_COMMIT(); CP_WAIT(1); }
        else              { CP_WAIT(0); }
        __syncthreads();

        uint32_t base = sb + (kc & 1) * STG2_B;
        uint32_t aHb = base, aLb = base + TILE_B, bHb = base + 2 * TILE_B;

#pragma unroll
        for (int ks = 0; ks < 4; ks++) {
            uint32_t ah[2][4], al[2][4], bh[4][2];
#pragma unroll
            for (int i = 0; i < 2; i++) {
                int row = arow + i * 16;
                uint32_t off = (uint32_t)(row * 128 + (((ks * 2 + lhalf) ^ (row & 7)) << 4));
                LDSM4(ah[i][0], ah[i][1], ah[i][2], ah[i][3], aHb + off);
                LDSM4(al[i][0], al[i][1], al[i][2], al[i][3], aLb + off);
            }
#pragma unroll
            for (int jp = 0; jp < 2; jp++) {
                int row = bnrow + jp * 16;
                uint32_t off = (uint32_t)(row * 128 + (((ks * 2 + lhalf) ^ (row & 7)) << 4));
                uint32_t r0, r1_, r2_, r3_;
                LDSM4(r0, r1_, r2_, r3_, bHb + off);
                bh[2 * jp][0] = r0;  bh[2 * jp][1] = r2_;
                bh[2 * jp + 1][0] = r1_; bh[2 * jp + 1][1] = r3_;
            }
#pragma unroll
            for (int i = 0; i < 2; i++)
#pragma unroll
                for (int j = 0; j < 4; j++) {
                    MMA16816(acc[i][j], ah[i], bh[j]);
                    MMA16816(acc[i][j], al[i], bh[j]);
                }
        }
        __syncthreads();
    }

#pragma unroll
    for (int i = 0; i < 2; i++)
#pragma unroll
        for (int j = 0; j < 4; j++) {
            int m = m0 + wm * 32 + i * 16 + (lane >> 2);
            int n = n0 + wn * 32 + j * 8 + (lane & 3) * 2;
            *(float2*)&C[(size_t)m * DMODEL + n]       = make_float2(acc[i][j][0], acc[i][j][1]);
            *(float2*)&C[(size_t)(m + 8) * DMODEL + n] = make_float2(acc[i][j][2], acc[i][j][3]);
        }
}

// ============================================================================
// rope_qk: in-place fp16 rope; q additionally scaled by 1/sqrt(dh).
// ============================================================================
__global__ __launch_bounds__(256)
void rope_qk(__half* __restrict__ qh, __half* __restrict__ kh,
             const float* __restrict__ rc, const float* __restrict__ rs)
{
    int idx = blockIdx.x * 256 + threadIdx.x;
    const int total = BATCH * SEQ * NHEADS * 32;
    if (idx >= total) return;
    int d = (idx & 31) * 2;
    int h = (idx >> 5) & (NHEADS - 1);
    int s = (idx >> 9) & (SEQ - 1);
    int b = idx >> 20;
    size_t base = ((size_t)(b * SEQ + s)) * DMODEL + h * DHEAD;
    const float scale = 0.088388347648318447f;

    float2 c0 = *(const float2*)&rc[s * DHEAD + d];
    float2 s0 = *(const float2*)&rs[s * DHEAD + d];
    float2 c1 = *(const float2*)&rc[s * DHEAD + 64 + d];
    float2 s1 = *(const float2*)&rs[s * DHEAD + 64 + d];

    __half2 qa2 = *(__half2*)&qh[base + d];
    __half2 qb2 = *(__half2*)&qh[base + 64 + d];
    float2 qa = __half22float2(qa2), qb = __half22float2(qb2);
    *(uint32_t*)&qh[base + d] = pk16(
        __float2half((qa.x * c0.x - qb.x * s0.x) * scale),
        __float2half((qa.y * c0.y - qb.y * s0.y) * scale));
    *(uint32_t*)&qh[base + 64 + d] = pk16(
        __float2half((qb.x * c1.x + qa.x * s1.x) * scale),
        __float2half((qb.y * c1.y + qa.y * s1.y) * scale));

    __half2 ka2 = *(__half2*)&kh[base + d];
    __half2 kb2 = *(__half2*)&kh[base + 64 + d];
    float2 ka = __half22float2(ka2), kb = __half22float2(kb2);
    *(uint32_t*)&kh[base + d] = pk16(
        __float2half(ka.x * c0.x - kb.x * s0.x),
        __float2half(ka.y * c0.y - kb.y * s0.y));
    *(uint32_t*)&kh[base + 64 + d] = pk16(
        __float2half(kb.x * c1.x + ka.x * s1.x),
        __float2half(kb.y * c1.y + ka.y * s1.y));
}

// ============================================================================
// attn_tc: flash attention, all plain fp16 operands (fp32 accumulate).
// QK 1-product; PV 1-product (P single fp16). Output: att hi/lo planes.
// ============================================================================
#define NKT (SEQ/64)
#define ATT_PLANE_B 16384
#define ATT_STAGE_B (2*ATT_PLANE_B)              // 32 KB
#define ATT_Q_B     32768
#define ATT_NSTAGE  3
#define ATT_TC_SMEM (ATT_Q_B + ATT_NSTAGE*ATT_STAGE_B)   // 131072

__global__ __launch_bounds__(256, 1)
void attn_tc(const __half* __restrict__ qh,
             const __half* __restrict__ khi,
             const __half* __restrict__ vhi,
             __half* __restrict__ ohi, __half* __restrict__ olo)
{
    extern __shared__ char smc[];
    const uint32_t sb = smem_u32(smc);
    const uint32_t QH = sb;
    const uint32_t ST = sb + ATT_Q_B;

    const int tid = threadIdx.x;
    const int lane = tid & 31;
    const int wid = tid >> 5;
    const int b = blockIdx.z, h = blockIdx.y;
    const int q0 = blockIdx.x * 128;
    const int wrow = wid * 16;

    // ---- Q plane via cp.async ----
    {
        const __half* src0 = qh + ((size_t)(b * SEQ + q0)) * DMODEL + h * DHEAD;
#pragma unroll
        for (int i = 0; i < 8; i++) {
            int idx = tid + i * 256;
            int row = idx >> 4, ch = idx & 15;
            uint32_t dst = QH + row * 256 + ((ch ^ (row & 15)) << 4);
            CP_ASYNC16(dst, src0 + (size_t)row * DMODEL + ch * 8);
        }
    }

    const __half* pl[2] = { khi, vhi };
    auto load_kv = [&](int st, int kt) {
        uint32_t base = ST + st * ATT_STAGE_B;
#pragma unroll
        for (int i = 0; i < 8; i++) {
            int idx = tid + i * 256;
            int p = idx >> 10;
            int c = idx & 1023;
            int row = c >> 4, ch = c & 15;
            const __half* src = pl[p] +
                ((size_t)(b * SEQ + kt * 64 + row)) * DMODEL + h * DHEAD + ch * 8;
            uint32_t dst = base + p * ATT_PLANE_B + row * 256 + ((ch ^ (row & 15)) << 4);
            CP_ASYNC16(dst, src);
        }
    };

    float o_[16][4];
#pragma unroll
    for (int n = 0; n < 16; n++)
#pragma unroll
        for (int r = 0; r < 4; r++) o_[n][r] = 0.f;
    float m_a = -3.0e38f, m_b = -3.0e38f, l_a = 0.f, l_b = 0.f;

    load_kv(0, 0); CP_COMMIT();
    load_kv(1, 1); CP_COMMIT();

    const int qrow = wrow + (lane & 15);
    const int lh = lane >> 4;

    int st = 0;
    for (int kt = 0; kt < NKT; kt++) {
        CP_WAIT(1);
        __syncthreads();
        uint32_t bs = ST + st * ATT_STAGE_B;

        if (kt + 2 < NKT) {
            int st2 = st + 2; if (st2 >= ATT_NSTAGE) st2 -= ATT_NSTAGE;
            load_kv(st2, kt + 2); CP_COMMIT();
        } else {
            CP_COMMIT();
        }

        // ---- scores: fp16 Q.K^T, fp32 accumulate ----
        float s[8][4];
#pragma unroll
        for (int j = 0; j < 8; j++)
#pragma unroll
            for (int r = 0; r < 4; r++) s[j][r] = 0.f;

#pragma unroll
        for (int ks = 0; ks < 8; ks++) {
            uint32_t qoff = (uint32_t)(qrow * 256 + (((ks * 2 + lh) ^ (qrow & 15)) << 4));
            uint32_t ah[4];
            LDSM4(ah[0], ah[1], ah[2], ah[3], QH + qoff);
#pragma unroll
            for (int nb = 0; nb < 4; nb++) {
                int krow = nb * 16 + (lane & 15);
                uint32_t koff = (uint32_t)(krow * 256 + (((ks * 2 + lh) ^ (krow & 15)) << 4));
                uint32_t h0, h1, h2, h3;
                LDSM4(h0, h1, h2, h3, bs + koff);
                uint32_t bh0[2] = { h0, h2 }, bh1[2] = { h1, h3 };
                MMA16816(s[2*nb],   ah, bh0);
                MMA16816(s[2*nb+1], ah, bh1);
            }
        }

        // ---- online softmax ----
        float mla = -3.0e38f, mlb = -3.0e38f;
#pragma unroll
        for (int j = 0; j < 8; j++) {
            mla = fmaxf(mla, fmaxf(s[j][0], s[j][1]));
            mlb = fmaxf(mlb, fmaxf(s[j][2], s[j][3]));
        }
        mla = fmaxf(mla, __shfl_xor_sync(0xffffffffu, mla, 1));
        mla = fmaxf(mla, __shfl_xor_sync(0xffffffffu, mla, 2));
        mlb = fmaxf(mlb, __shfl_xor_sync(0xffffffffu, mlb, 1));
        mlb = fmaxf(mlb, __shfl_xor_sync(0xffffffffu, mlb, 2));
        float mna = fmaxf(m_a, mla), mnb = fmaxf(m_b, mlb);
        float aa = __expf(m_a - mna), ab = __expf(m_b - mnb);

        uint32_t pAh[8], pBh[8];
        float sa = 0.f, sb2 = 0.f;
#pragma unroll
        for (int j = 0; j < 8; j++) {
            float p0 = __expf(s[j][0] - mna), p1 = __expf(s[j][1] - mna);
            float p2 = __expf(s[j][2] - mnb), p3 = __expf(s[j][3] - mnb);
            sa += p0 + p1; sb2 += p2 + p3;
            pAh[j] = pk16(__float2half(p0), __float2half(p1));
            pBh[j] = pk16(__float2half(p2), __float2half(p3));
        }
        sa  += __shfl_xor_sync(0xffffffffu, sa, 1);
        sa  += __shfl_xor_sync(0xffffffffu, sa, 2);
        sb2 += __shfl_xor_sync(0xffffffffu, sb2, 1);
        sb2 += __shfl_xor_sync(0xffffffffu, sb2, 2);
        m_a = mna; m_b = mnb;
        l_a = l_a * aa + sa; l_b = l_b * ab + sb2;

#pragma unroll
        for (int n = 0; n < 16; n++) {
            o_[n][0] *= aa; o_[n][1] *= aa; o_[n][2] *= ab; o_[n][3] *= ab;
        }

        // ---- PV: 1 product (P single fp16, V single), V via ldmatrix.trans ----
#pragma unroll
        for (int kp = 0; kp < 4; kp++) {
            uint32_t ah4[4] = { pAh[2*kp], pBh[2*kp], pAh[2*kp+1], pBh[2*kp+1] };
            int vrow = kp * 16 + (lane & 15);
#pragma unroll
            for (int nb = 0; nb < 8; nb++) {
                uint32_t ch = (uint32_t)(nb * 2 + lh);
                uint32_t voff = (uint32_t)(vrow * 256 + ((ch ^ (vrow & 15)) << 4));
                uint32_t h0, h1, h2, h3;
                LDSM4T(h0, h1, h2, h3, bs + ATT_PLANE_B + voff);
                uint32_t bh0[2] = { h0, h1 }, bh1[2] = { h2, h3 };
                MMA16816(o_[2*nb],   ah4, bh0);
                MMA16816(o_[2*nb+1], ah4, bh1);
            }
        }

        if (++st == ATT_NSTAGE) st = 0;
    }

    // ---- epilogue: split O/l into fp16 hi/lo att planes ----
    float ia = 1.f / l_a, ib = 1.f / l_b;
    size_t r0 = (size_t)(b * SEQ + q0 + wrow + (lane >> 2)) * DMODEL + h * DHEAD + 2 * (lane & 3);
    size_t r1 = r0 + (size_t)8 * DMODEL;
#pragma unroll
    for (int n = 0; n < 16; n++) {
        __half h0, l0, h1, l1;
        split1(o_[n][0] * ia, h0, l0); split1(o_[n][1] * ia, h1, l1);
        *(uint32_t*)&ohi[r0 + n*8] = pk16(h0, h1);
        *(uint32_t*)&olo[r0 + n*8] = pk16(l0, l1);
        split1(o_[n][2] * ib, h0, l0); split1(o_[n][3] * ib, h1, l1);
        *(uint32_t*)&ohi[r1 + n*8] = pk16(h0, h1);
        *(uint32_t*)&olo[r1 + n*8] = pk16(l0, l1);
    }
}

// ============================================================================
extern "C" void kernel_launch(void* const* d_in, const int* in_sizes, int n_in,
                              void* d_out, int out_size)
{
    const float* x  = (const float*)d_in[0];
    const float* rc = (const float*)d_in[1];
    const float* rs = (const float*)d_in[2];
    const float* Wq = (const float*)d_in[3];
    const float* Wk = (const float*)d_in[4];
    const float* Wv = (const float*)d_in[5];
    const float* Wo = (const float*)d_in[6];
    float* out = (float*)d_out;

    __half *xh, *wq, *wk, *wv, *wo, *qhp, *khp, *vhp, *atthi, *attlo;
    cudaGetSymbolAddress((void**)&xh, g_xh);
    cudaGetSymbolAddress((void**)&wq, g_wq);     cudaGetSymbolAddress((void**)&wk, g_wk);
    cudaGetSymbolAddress((void**)&wv, g_wv);     cudaGetSymbolAddress((void**)&wo, g_wo);
    cudaGetSymbolAddress((void**)&qhp, g_qh);    cudaGetSymbolAddress((void**)&khp, g_kh);
    cudaGetSymbolAddress((void**)&vhp, g_vh);
    cudaGetSymbolAddress((void**)&atthi, g_atthi); cudaGetSymbolAddress((void**)&attlo, g_attlo);

    cudaFuncSetAttribute(gemm_1p_h, cudaFuncAttributeMaxDynamicSharedMemorySize, G1_SMEM);
    cudaFuncSetAttribute(gemm_2p,   cudaFuncAttributeMaxDynamicSharedMemorySize, G2_SMEM);
    cudaFuncSetAttribute(attn_tc,   cudaFuncAttributeMaxDynamicSharedMemorySize, ATT_TC_SMEM);

    const int npx = MROWS * DMODEL / 2;
    const int npw = DMODEL * DMODEL / 2;
    pack_single<<<(npx + 255) / 256, 256>>>(x,  (uint32_t*)xh, npx);
    pack_single<<<(npw + 255) / 256, 256>>>(Wq, (uint32_t*)wq, npw);
    pack_single<<<(npw + 255) / 256, 256>>>(Wk, (uint32_t*)wk, npw);
    pack_single<<<(npw + 255) / 256, 256>>>(Wv, (uint32_t*)wv, npw);
    pack_single<<<(npw + 255) / 256, 256>>>(Wo, (uint32_t*)wo, npw);

    // QKV projection, plain fp16 (fp32 accumulate), fp16 outputs
    gemm_1p_h<<<dim3(DMODEL / 128, MROWS / 128, 3), 512, G1_SMEM>>>(
        xh, wq, wk, wv, qhp, khp, vhp);

    int rope_threads = BATCH * SEQ * NHEADS * 32;
    rope_qk<<<(rope_threads + 255) / 256, 256>>>(qhp, khp, rc, rs);

    attn_tc<<<dim3(SEQ / 128, NHEADS, BATCH), 256, ATT_TC_SMEM>>>(qhp, khp, vhp, atthi, attlo);

    // output projection: att hi/lo 2-product, fp32 out
    gemm_2p<<<dim3(DMODEL / 128, MROWS / 128, 1), 512, G2_SMEM>>>(
        atthi, attlo, wo, out);
}

// round 13
// speedup vs baseline: 2.6446x; 1.1697x over previous
#include <cuda_runtime.h>
#include <cuda_fp16.h>
#include <math.h>
#include <stdint.h>

// Problem constants
#define BATCH 2
#define SEQ   2048
#define DMODEL 2048
#define NHEADS 16
#define DHEAD 128
#define MROWS (BATCH*SEQ)          // 4096
#define KDIM  DMODEL

// -------------------- scratch (static device globals; no allocation) ------
__device__ __align__(16) __half g_xh[MROWS * DMODEL];
__device__ __align__(16) __half g_wq[DMODEL * DMODEL];
__device__ __align__(16) __half g_wk[DMODEL * DMODEL];
__device__ __align__(16) __half g_wv[DMODEL * DMODEL];
__device__ __align__(16) __half g_wo[DMODEL * DMODEL];
__device__ __align__(16) __half g_qh[MROWS * DMODEL];
__device__ __align__(16) __half g_kh[MROWS * DMODEL];
__device__ __align__(16) __half g_vh[MROWS * DMODEL];
__device__ __align__(16) __half g_att[MROWS * DMODEL];

// ============================ PTX helpers ==================================
__device__ __forceinline__ uint32_t smem_u32(const void* p) {
    uint32_t a;
    asm("{ .reg .u64 t; cvta.to.shared.u64 t, %1; cvt.u32.u64 %0, t; }" : "=r"(a) : "l"(p));
    return a;
}
#define CP_ASYNC16(dst, src) \
    asm volatile("cp.async.cg.shared.global [%0], [%1], 16;" :: "r"(dst), "l"(src))
#define CP_COMMIT() asm volatile("cp.async.commit_group;" ::: "memory")
#define CP_WAIT(n)  asm volatile("cp.async.wait_group %0;" :: "n"(n) : "memory")

#define LDSM4(r0, r1, r2, r3, addr) \
    asm volatile("ldmatrix.sync.aligned.m8n8.x4.shared.b16 {%0,%1,%2,%3}, [%4];" \
        : "=r"(r0), "=r"(r1), "=r"(r2), "=r"(r3) : "r"(addr))
#define LDSM4T(r0, r1, r2, r3, addr) \
    asm volatile("ldmatrix.sync.aligned.m8n8.x4.trans.shared.b16 {%0,%1,%2,%3}, [%4];" \
        : "=r"(r0), "=r"(r1), "=r"(r2), "=r"(r3) : "r"(addr))

#define MMA16816(c, a, b) \
    asm volatile("mma.sync.aligned.m16n8k16.row.col.f32.f16.f16.f32 " \
        "{%0,%1,%2,%3},{%4,%5,%6,%7},{%8,%9},{%0,%1,%2,%3};" \
        : "+f"((c)[0]), "+f"((c)[1]), "+f"((c)[2]), "+f"((c)[3]) \
        : "r"((a)[0]), "r"((a)[1]), "r"((a)[2]), "r"((a)[3]), "r"((b)[0]), "r"((b)[1]))

__device__ __forceinline__ uint32_t pk16(__half a, __half b) {
    return (uint32_t)__half_as_ushort(a) | ((uint32_t)__half_as_ushort(b) << 16);
}

// ============================================================================
// pack_all: one launch converts x + 4 weights fp32->fp16 (segment routing).
// ============================================================================
#define NPX (MROWS * DMODEL / 2)
#define NPW (DMODEL * DMODEL / 2)
#define NP_TOTAL (NPX + 4 * NPW)

__global__ __launch_bounds__(256)
void pack_all(const float* __restrict__ x,
              const float* __restrict__ Wq, const float* __restrict__ Wk,
              const float* __restrict__ Wv, const float* __restrict__ Wo,
              uint32_t* __restrict__ xh,
              uint32_t* __restrict__ wq, uint32_t* __restrict__ wk,
              uint32_t* __restrict__ wv, uint32_t* __restrict__ wo)
{
    int i = blockIdx.x * 256 + threadIdx.x;
    if (i >= NP_TOTAL) return;
    const float* src; uint32_t* dst; int off;
    if (i < NPX)                { src = x;  dst = xh; off = i; }
    else if (i < NPX + NPW)     { src = Wq; dst = wq; off = i - NPX; }
    else if (i < NPX + 2*NPW)   { src = Wk; dst = wk; off = i - NPX - NPW; }
    else if (i < NPX + 3*NPW)   { src = Wv; dst = wv; off = i - NPX - 2*NPW; }
    else                        { src = Wo; dst = wo; off = i - NPX - 3*NPW; }
    float2 v = ((const float2*)src)[off];
    dst[off] = pk16(__float2half(v.x), __float2half(v.y));
}

// ============================================================================
// gemm_1p core: C_z = A @ B_z^T, plain fp16 operands, fp32 accumulate.
// 512 threads / 16 warps (4m x 4n), BKD=64, 2 stages x 32KB.
// Two epilogues: fp16 out (QKV) and fp32 out (final projection).
// ============================================================================
#define BKD 64
#define TILE_B   (128 * BKD * 2)              // 16 KB per plane
#define STG1_B   (2 * TILE_B)                 // 32 KB (A, B)
#define G1_SMEM  (2 * STG1_B)                 // 64 KB

#define GEMM1_BODY(EPILOGUE)                                                         \
    extern __shared__ char smc[];                                                    \
    const uint32_t sb = smem_u32(smc);                                               \
    const int tid  = threadIdx.x;                                                    \
    const int lane = tid & 31;                                                       \
    const int wid  = tid >> 5;                                                       \
    const int wm   = wid & 3;                                                        \
    const int wn   = wid >> 2;                                                       \
    const int m0   = blockIdx.y * 128;                                               \
    const int n0   = blockIdx.x * 128;                                               \
    const int rA = tid >> 3, cA = tid & 7;                                           \
    const int rB = (tid + 512) >> 3, cB = (tid + 512) & 7;                           \
    const uint32_t dA = (uint32_t)(rA * 128 + ((cA ^ (rA & 7)) << 4));               \
    const uint32_t dB = (uint32_t)(rB * 128 + ((cB ^ (rB & 7)) << 4));               \
    const __half* srcA = A + (size_t)m0 * KDIM;                                      \
    const __half* srcB = B + (size_t)n0 * KDIM;                                      \
    auto load_stage = [&](int s, int kb) {                                           \
        uint32_t base = sb + s * STG1_B;                                             \
        int koff = kb * BKD;                                                         \
        CP_ASYNC16(base + dA,          srcA + (size_t)rA * KDIM + koff + cA * 8);    \
        CP_ASYNC16(base + dB,          srcA + (size_t)rB * KDIM + koff + cB * 8);    \
        CP_ASYNC16(base + TILE_B + dA, srcB + (size_t)rA * KDIM + koff + cA * 8);    \
        CP_ASYNC16(base + TILE_B + dB, srcB + (size_t)rB * KDIM + koff + cB * 8);    \
    };                                                                               \
    float acc[2][4][4];                                                              \
    _Pragma("unroll")                                                                \
    for (int i = 0; i < 2; i++)                                                      \
        for (int j = 0; j < 4; j++)                                                  \
            for (int r = 0; r < 4; r++) acc[i][j][r] = 0.f;                          \
    load_stage(0, 0); CP_COMMIT();                                                   \
    const int arow = wm * 32 + (lane & 15);                                          \
    const int bnrow = wn * 32 + (lane & 15);                                         \
    const int lhalf = lane >> 4;                                                     \
    const int NKB = KDIM / BKD;                                                      \
    for (int kc = 0; kc < NKB; kc++) {                                               \
        if (kc + 1 < NKB) { load_stage((kc + 1) & 1, kc + 1); CP_COMMIT(); CP_WAIT(1); } \
        else              { CP_WAIT(0); }                                            \
        __syncthreads();                                                             \
        uint32_t base = sb + (kc & 1) * STG1_B;                                      \
        uint32_t aB = base, bB = base + TILE_B;                                      \
        _Pragma("unroll")                                                            \
        for (int ks = 0; ks < 4; ks++) {                                             \
            uint32_t ah[2][4], bh[4][2];                                             \
            _Pragma("unroll")                                                        \
            for (int i = 0; i < 2; i++) {                                            \
                int row = arow + i * 16;                                             \
                uint32_t off = (uint32_t)(row * 128 + (((ks * 2 + lhalf) ^ (row & 7)) << 4)); \
                LDSM4(ah[i][0], ah[i][1], ah[i][2], ah[i][3], aB + off);             \
            }                                                                        \
            _Pragma("unroll")                                                        \
            for (int jp = 0; jp < 2; jp++) {                                         \
                int row = bnrow + jp * 16;                                           \
                uint32_t off = (uint32_t)(row * 128 + (((ks * 2 + lhalf) ^ (row & 7)) << 4)); \
                uint32_t r0, r1_, r2_, r3_;                                          \
                LDSM4(r0, r1_, r2_, r3_, bB + off);                                  \
                bh[2 * jp][0] = r0;  bh[2 * jp][1] = r2_;                            \
                bh[2 * jp + 1][0] = r1_; bh[2 * jp + 1][1] = r3_;                    \
            }                                                                        \
            _Pragma("unroll")                                                        \
            for (int i = 0; i < 2; i++)                                              \
                for (int j = 0; j < 4; j++)                                          \
                    MMA16816(acc[i][j], ah[i], bh[j]);                               \
        }                                                                            \
        __syncthreads();                                                             \
    }                                                                                \
    EPILOGUE

__global__ __launch_bounds__(512)
void gemm_1p_h(const __half* __restrict__ A,
               const __half* __restrict__ B0, const __half* __restrict__ B1,
               const __half* __restrict__ B2,
               __half* __restrict__ C0, __half* __restrict__ C1, __half* __restrict__ C2)
{
    const int z = blockIdx.z;
    const __half* B = (z == 0) ? B0 : (z == 1) ? B1 : B2;
    __half* C = (z == 0) ? C0 : (z == 1) ? C1 : C2;
    GEMM1_BODY({
#pragma unroll
        for (int i = 0; i < 2; i++)
#pragma unroll
            for (int j = 0; j < 4; j++) {
                int m = m0 + wm * 32 + i * 16 + (lane >> 2);
                int n = n0 + wn * 32 + j * 8 + (lane & 3) * 2;
                *(uint32_t*)&C[(size_t)m * DMODEL + n] =
                    pk16(__float2half(acc[i][j][0]), __float2half(acc[i][j][1]));
                *(uint32_t*)&C[(size_t)(m + 8) * DMODEL + n] =
                    pk16(__float2half(acc[i][j][2]), __float2half(acc[i][j][3]));
            }
    })
}

__global__ __launch_bounds__(512)
void gemm_1p_f(const __half* __restrict__ A, const __half* __restrict__ B,
               float* __restrict__ C)
{
    GEMM1_BODY({
#pragma unroll
        for (int i = 0; i < 2; i++)
#pragma unroll
            for (int j = 0; j < 4; j++) {
                int m = m0 + wm * 32 + i * 16 + (lane >> 2);
                int n = n0 + wn * 32 + j * 8 + (lane & 3) * 2;
                *(float2*)&C[(size_t)m * DMODEL + n]       = make_float2(acc[i][j][0], acc[i][j][1]);
                *(float2*)&C[(size_t)(m + 8) * DMODEL + n] = make_float2(acc[i][j][2], acc[i][j][3]);
            }
    })
}

// ============================================================================
// rope_qk: in-place fp16 rope; q additionally scaled by 1/sqrt(dh).
// ============================================================================
__global__ __launch_bounds__(256)
void rope_qk(__half* __restrict__ qh, __half* __restrict__ kh,
             const float* __restrict__ rc, const float* __restrict__ rs)
{
    int idx = blockIdx.x * 256 + threadIdx.x;
    const int total = BATCH * SEQ * NHEADS * 32;
    if (idx >= total) return;
    int d = (idx & 31) * 2;
    int h = (idx >> 5) & (NHEADS - 1);
    int s = (idx >> 9) & (SEQ - 1);
    int b = idx >> 20;
    size_t base = ((size_t)(b * SEQ + s)) * DMODEL + h * DHEAD;
    const float scale = 0.088388347648318447f;

    float2 c0 = *(const float2*)&rc[s * DHEAD + d];
    float2 s0 = *(const float2*)&rs[s * DHEAD + d];
    float2 c1 = *(const float2*)&rc[s * DHEAD + 64 + d];
    float2 s1 = *(const float2*)&rs[s * DHEAD + 64 + d];

    __half2 qa2 = *(__half2*)&qh[base + d];
    __half2 qb2 = *(__half2*)&qh[base + 64 + d];
    float2 qa = __half22float2(qa2), qb = __half22float2(qb2);
    *(uint32_t*)&qh[base + d] = pk16(
        __float2half((qa.x * c0.x - qb.x * s0.x) * scale),
        __float2half((qa.y * c0.y - qb.y * s0.y) * scale));
    *(uint32_t*)&qh[base + 64 + d] = pk16(
        __float2half((qb.x * c1.x + qa.x * s1.x) * scale),
        __float2half((qb.y * c1.y + qa.y * s1.y) * scale));

    __half2 ka2 = *(__half2*)&kh[base + d];
    __half2 kb2 = *(__half2*)&kh[base + 64 + d];
    float2 ka = __half22float2(ka2), kb = __half22float2(kb2);
    *(uint32_t*)&kh[base + d] = pk16(
        __float2half(ka.x * c0.x - kb.x * s0.x),
        __float2half(ka.y * c0.y - kb.y * s0.y));
    *(uint32_t*)&kh[base + 64 + d] = pk16(
        __float2half(kb.x * c1.x + ka.x * s1.x),
        __float2half(kb.y * c1.y + ka.y * s1.y));
}

// ============================================================================
// attn_tc: flash attention, all plain fp16 operands (fp32 accumulate).
// QK 1-product; PV 1-product. Output: single fp16 att plane.
// ============================================================================
#define NKT (SEQ/64)
#define ATT_PLANE_B 16384
#define ATT_STAGE_B (2*ATT_PLANE_B)              // 32 KB
#define ATT_Q_B     32768
#define ATT_NSTAGE  3
#define ATT_TC_SMEM (ATT_Q_B + ATT_NSTAGE*ATT_STAGE_B)   // 131072

__global__ __launch_bounds__(256, 1)
void attn_tc(const __half* __restrict__ qh,
             const __half* __restrict__ khi,
             const __half* __restrict__ vhi,
             __half* __restrict__ oh)
{
    extern __shared__ char smc[];
    const uint32_t sb = smem_u32(smc);
    const uint32_t QH = sb;
    const uint32_t ST = sb + ATT_Q_B;

    const int tid = threadIdx.x;
    const int lane = tid & 31;
    const int wid = tid >> 5;
    const int b = blockIdx.z, h = blockIdx.y;
    const int q0 = blockIdx.x * 128;
    const int wrow = wid * 16;

    // ---- Q plane via cp.async ----
    {
        const __half* src0 = qh + ((size_t)(b * SEQ + q0)) * DMODEL + h * DHEAD;
#pragma unroll
        for (int i = 0; i < 8; i++) {
            int idx = tid + i * 256;
            int row = idx >> 4, ch = idx & 15;
            uint32_t dst = QH + row * 256 + ((ch ^ (row & 15)) << 4);
            CP_ASYNC16(dst, src0 + (size_t)row * DMODEL + ch * 8);
        }
    }

    const __half* pl[2] = { khi, vhi };
    auto load_kv = [&](int st, int kt) {
        uint32_t base = ST + st * ATT_STAGE_B;
#pragma unroll
        for (int i = 0; i < 8; i++) {
            int idx = tid + i * 256;
            int p = idx >> 10;
            int c = idx & 1023;
            int row = c >> 4, ch = c & 15;
            const __half* src = pl[p] +
                ((size_t)(b * SEQ + kt * 64 + row)) * DMODEL + h * DHEAD + ch * 8;
            uint32_t dst = base + p * ATT_PLANE_B + row * 256 + ((ch ^ (row & 15)) << 4);
            CP_ASYNC16(dst, src);
        }
    };

    float o_[16][4];
#pragma unroll
    for (int n = 0; n < 16; n++)
#pragma unroll
        for (int r = 0; r < 4; r++) o_[n][r] = 0.f;
    float m_a = -3.0e38f, m_b = -3.0e38f, l_a = 0.f, l_b = 0.f;

    load_kv(0, 0); CP_COMMIT();
    load_kv(1, 1); CP_COMMIT();

    const int qrow = wrow + (lane & 15);
    const int lh = lane >> 4;

    int st = 0;
    for (int kt = 0; kt < NKT; kt++) {
        CP_WAIT(1);
        __syncthreads();
        uint32_t bs = ST + st * ATT_STAGE_B;

        if (kt + 2 < NKT) {
            int st2 = st + 2; if (st2 >= ATT_NSTAGE) st2 -= ATT_NSTAGE;
            load_kv(st2, kt + 2); CP_COMMIT();
        } else {
            CP_COMMIT();
        }

        // ---- scores: fp16 Q.K^T, fp32 accumulate ----
        float s[8][4];
#pragma unroll
        for (int j = 0; j < 8; j++)
#pragma unroll
            for (int r = 0; r < 4; r++) s[j][r] = 0.f;

#pragma unroll
        for (int ks = 0; ks < 8; ks++) {
            uint32_t qoff = (uint32_t)(qrow * 256 + (((ks * 2 + lh) ^ (qrow & 15)) << 4));
            uint32_t ah[4];
            LDSM4(ah[0], ah[1], ah[2], ah[3], QH + qoff);
#pragma unroll
            for (int nb = 0; nb < 4; nb++) {
                int krow = nb * 16 + (lane & 15);
                uint32_t koff = (uint32_t)(krow * 256 + (((ks * 2 + lh) ^ (krow & 15)) << 4));
                uint32_t h0, h1, h2, h3;
                LDSM4(h0, h1, h2, h3, bs + koff);
                uint32_t bh0[2] = { h0, h2 }, bh1[2] = { h1, h3 };
                MMA16816(s[2*nb],   ah, bh0);
                MMA16816(s[2*nb+1], ah, bh1);
            }
        }

        // ---- online softmax ----
        float mla = -3.0e38f, mlb = -3.0e38f;
#pragma unroll
        for (int j = 0; j < 8; j++) {
            mla = fmaxf(mla, fmaxf(s[j][0], s[j][1]));
            mlb = fmaxf(mlb, fmaxf(s[j][2], s[j][3]));
        }
        mla = fmaxf(mla, __shfl_xor_sync(0xffffffffu, mla, 1));
        mla = fmaxf(mla, __shfl_xor_sync(0xffffffffu, mla, 2));
        mlb = fmaxf(mlb, __shfl_xor_sync(0xffffffffu, mlb, 1));
        mlb = fmaxf(mlb, __shfl_xor_sync(0xffffffffu, mlb, 2));
        float mna = fmaxf(m_a, mla), mnb = fmaxf(m_b, mlb);
        float aa = __expf(m_a - mna), ab = __expf(m_b - mnb);

        uint32_t pAh[8], pBh[8];
        float sa = 0.f, sb2 = 0.f;
#pragma unroll
        for (int j = 0; j < 8; j++) {
            float p0 = __expf(s[j][0] - mna), p1 = __expf(s[j][1] - mna);
            float p2 = __expf(s[j][2] - mnb), p3 = __expf(s[j][3] - mnb);
            sa += p0 + p1; sb2 += p2 + p3;
            pAh[j] = pk16(__float2half(p0), __float2half(p1));
            pBh[j] = pk16(__float2half(p2), __float2half(p3));
        }
        sa  += __shfl_xor_sync(0xffffffffu, sa, 1);
        sa  += __shfl_xor_sync(0xffffffffu, sa, 2);
        sb2 += __shfl_xor_sync(0xffffffffu, sb2, 1);
        sb2 += __shfl_xor_sync(0xffffffffu, sb2, 2);
        m_a = mna; m_b = mnb;
        l_a = l_a * aa + sa; l_b = l_b * ab + sb2;

#pragma unroll
        for (int n = 0; n < 16; n++) {
            o_[n][0] *= aa; o_[n][1] *= aa; o_[n][2] *= ab; o_[n][3] *= ab;
        }

        // ---- PV: 1 product, V via ldmatrix.trans ----
#pragma unroll
        for (int kp = 0; kp < 4; kp++) {
            uint32_t ah4[4] = { pAh[2*kp], pBh[2*kp], pAh[2*kp+1], pBh[2*kp+1] };
            int vrow = kp * 16 + (lane & 15);
#pragma unroll
            for (int nb = 0; nb < 8; nb++) {
                uint32_t ch = (uint32_t)(nb * 2 + lh);
                uint32_t voff = (uint32_t)(vrow * 256 + ((ch ^ (vrow & 15)) << 4));
                uint32_t h0, h1, h2, h3;
                LDSM4T(h0, h1, h2, h3, bs + ATT_PLANE_B + voff);
                uint32_t bh0[2] = { h0, h1 }, bh1[2] = { h2, h3 };
                MMA16816(o_[2*nb],   ah4, bh0);
                MMA16816(o_[2*nb+1], ah4, bh1);
            }
        }

        if (++st == ATT_NSTAGE) st = 0;
    }

    // ---- epilogue: single fp16 att plane ----
    float ia = 1.f / l_a, ib = 1.f / l_b;
    size_t r0 = (size_t)(b * SEQ + q0 + wrow + (lane >> 2)) * DMODEL + h * DHEAD + 2 * (lane & 3);
    size_t r1 = r0 + (size_t)8 * DMODEL;
#pragma unroll
    for (int n = 0; n < 16; n++) {
        *(uint32_t*)&oh[r0 + n*8] = pk16(__float2half(o_[n][0] * ia), __float2half(o_[n][1] * ia));
        *(uint32_t*)&oh[r1 + n*8] = pk16(__float2half(o_[n][2] * ib), __float2half(o_[n][3] * ib));
    }
}

// ============================================================================
extern "C" void kernel_launch(void* const* d_in, const int* in_sizes, int n_in,
                              void* d_out, int out_size)
{
    const float* x  = (const float*)d_in[0];
    const float* rc = (const float*)d_in[1];
    const float* rs = (const float*)d_in[2];
    const float* Wq = (const float*)d_in[3];
    const float* Wk = (const float*)d_in[4];
    const float* Wv = (const float*)d_in[5];
    const float* Wo = (const float*)d_in[6];
    float* out = (float*)d_out;

    __half *xh, *wq, *wk, *wv, *wo, *qhp, *khp, *vhp, *att;
    cudaGetSymbolAddress((void**)&xh, g_xh);
    cudaGetSymbolAddress((void**)&wq, g_wq);     cudaGetSymbolAddress((void**)&wk, g_wk);
    cudaGetSymbolAddress((void**)&wv, g_wv);     cudaGetSymbolAddress((void**)&wo, g_wo);
    cudaGetSymbolAddress((void**)&qhp, g_qh);    cudaGetSymbolAddress((void**)&khp, g_kh);
    cudaGetSymbolAddress((void**)&vhp, g_vh);
    cudaGetSymbolAddress((void**)&att, g_att);

    cudaFuncSetAttribute(gemm_1p_h, cudaFuncAttributeMaxDynamicSharedMemorySize, G1_SMEM);
    cudaFuncSetAttribute(gemm_1p_f, cudaFuncAttributeMaxDynamicSharedMemorySize, G1_SMEM);
    cudaFuncSetAttribute(attn_tc,   cudaFuncAttributeMaxDynamicSharedMemorySize, ATT_TC_SMEM);

    pack_all<<<(NP_TOTAL + 255) / 256, 256>>>(
        x, Wq, Wk, Wv, Wo,
        (uint32_t*)xh, (uint32_t*)wq, (uint32_t*)wk, (uint32_t*)wv, (uint32_t*)wo);

    // QKV projection, plain fp16, fp16 outputs
    gemm_1p_h<<<dim3(DMODEL / 128, MROWS / 128, 3), 512, G1_SMEM>>>(
        xh, wq, wk, wv, qhp, khp, vhp);

    int rope_threads = BATCH * SEQ * NHEADS * 32;
    rope_qk<<<(rope_threads + 255) / 256, 256>>>(qhp, khp, rc, rs);

    attn_tc<<<dim3(SEQ / 128, NHEADS, BATCH), 256, ATT_TC_SMEM>>>(qhp, khp, vhp, att);

    // output projection: plain fp16, fp32 out
    gemm_1p_f<<<dim3(DMODEL / 128, MROWS / 128, 1), 512, G1_SMEM>>>(att, wo, out);
}

// round 14
// speedup vs baseline: 2.6507x; 1.0023x over previous
#include <cuda_runtime.h>
#include <cuda_fp16.h>
#include <math.h>
#include <stdint.h>

// Problem constants
#define BATCH 2
#define SEQ   2048
#define DMODEL 2048
#define NHEADS 16
#define DHEAD 128
#define MROWS (BATCH*SEQ)          // 4096
#define KDIM  DMODEL

// -------------------- scratch (static device globals; no allocation) ------
__device__ __align__(16) __half g_xh[MROWS * DMODEL];
__device__ __align__(16) __half g_wq[DMODEL * DMODEL];
__device__ __align__(16) __half g_wk[DMODEL * DMODEL];
__device__ __align__(16) __half g_wv[DMODEL * DMODEL];
__device__ __align__(16) __half g_wo[DMODEL * DMODEL];
__device__ __align__(16) __half g_qh[MROWS * DMODEL];
__device__ __align__(16) __half g_kh[MROWS * DMODEL];
__device__ __align__(16) __half g_vh[MROWS * DMODEL];
__device__ __align__(16) __half g_att[MROWS * DMODEL];

// ============================ PTX helpers ==================================
__device__ __forceinline__ uint32_t smem_u32(const void* p) {
    uint32_t a;
    asm("{ .reg .u64 t; cvta.to.shared.u64 t, %1; cvt.u32.u64 %0, t; }" : "=r"(a) : "l"(p));
    return a;
}
#define CP_ASYNC16(dst, src) \
    asm volatile("cp.async.cg.shared.global [%0], [%1], 16;" :: "r"(dst), "l"(src))
#define CP_COMMIT() asm volatile("cp.async.commit_group;" ::: "memory")
#define CP_WAIT(n)  asm volatile("cp.async.wait_group %0;" :: "n"(n) : "memory")

#define LDSM4(r0, r1, r2, r3, addr) \
    asm volatile("ldmatrix.sync.aligned.m8n8.x4.shared.b16 {%0,%1,%2,%3}, [%4];" \
        : "=r"(r0), "=r"(r1), "=r"(r2), "=r"(r3) : "r"(addr))
#define LDSM4T(r0, r1, r2, r3, addr) \
    asm volatile("ldmatrix.sync.aligned.m8n8.x4.trans.shared.b16 {%0,%1,%2,%3}, [%4];" \
        : "=r"(r0), "=r"(r1), "=r"(r2), "=r"(r3) : "r"(addr))

#define MMA16816(c, a, b) \
    asm volatile("mma.sync.aligned.m16n8k16.row.col.f32.f16.f16.f32 " \
        "{%0,%1,%2,%3},{%4,%5,%6,%7},{%8,%9},{%0,%1,%2,%3};" \
        : "+f"((c)[0]), "+f"((c)[1]), "+f"((c)[2]), "+f"((c)[3]) \
        : "r"((a)[0]), "r"((a)[1]), "r"((a)[2]), "r"((a)[3]), "r"((b)[0]), "r"((b)[1]))

__device__ __forceinline__ uint32_t pk16(__half a, __half b) {
    return (uint32_t)__half_as_ushort(a) | ((uint32_t)__half_as_ushort(b) << 16);
}

// ============================================================================
// pack_all: one launch converts x + 4 weights fp32->fp16; 4 pairs/thread (MLP).
// ============================================================================
#define NPX (MROWS * DMODEL / 2)
#define NPW (DMODEL * DMODEL / 2)
#define NP_TOTAL (NPX + 4 * NPW)

__global__ __launch_bounds__(256)
void pack_all(const float* __restrict__ x,
              const float* __restrict__ Wq, const float* __restrict__ Wk,
              const float* __restrict__ Wv, const float* __restrict__ Wo,
              uint32_t* __restrict__ xh,
              uint32_t* __restrict__ wq, uint32_t* __restrict__ wk,
              uint32_t* __restrict__ wv, uint32_t* __restrict__ wo)
{
    int i0 = blockIdx.x * 1024 + threadIdx.x;
#pragma unroll
    for (int t = 0; t < 4; t++) {
        int i = i0 + t * 256;
        if (i >= NP_TOTAL) return;
        const float* src; uint32_t* dst; int off;
        if (i < NPX)                { src = x;  dst = xh; off = i; }
        else if (i < NPX + NPW)     { src = Wq; dst = wq; off = i - NPX; }
        else if (i < NPX + 2*NPW)   { src = Wk; dst = wk; off = i - NPX - NPW; }
        else if (i < NPX + 3*NPW)   { src = Wv; dst = wv; off = i - NPX - 2*NPW; }
        else                        { src = Wo; dst = wo; off = i - NPX - 3*NPW; }
        float2 v = ((const float2*)src)[off];
        dst[off] = pk16(__float2half(v.x), __float2half(v.y));
    }
}

// ============================================================================
// gemm mainloop core: C_z = A @ B_z^T, fp16 operands, fp32 accumulate.
// 512 threads / 16 warps (4m x 4n), BKD=64, 2 stages x 32KB.
// ============================================================================
#define BKD 64
#define TILE_B   (128 * BKD * 2)              // 16 KB per plane
#define STG1_B   (2 * TILE_B)                 // 32 KB (A, B)
#define G1_SMEM  (2 * STG1_B)                 // 64 KB (also = 128x128 fp32 stage)

#define GEMM1_BODY                                                                   \
    extern __shared__ char smc[];                                                    \
    const uint32_t sb = smem_u32(smc);                                               \
    const int tid  = threadIdx.x;                                                    \
    const int lane = tid & 31;                                                       \
    const int wid  = tid >> 5;                                                       \
    const int wm   = wid & 3;                                                        \
    const int wn   = wid >> 2;                                                       \
    const int m0   = blockIdx.y * 128;                                               \
    const int n0   = blockIdx.x * 128;                                               \
    const int rA = tid >> 3, cA = tid & 7;                                           \
    const int rB = (tid + 512) >> 3, cB = (tid + 512) & 7;                           \
    const uint32_t dA = (uint32_t)(rA * 128 + ((cA ^ (rA & 7)) << 4));               \
    const uint32_t dB = (uint32_t)(rB * 128 + ((cB ^ (rB & 7)) << 4));               \
    const __half* srcA = A + (size_t)m0 * KDIM;                                      \
    const __half* srcB = B + (size_t)n0 * KDIM;                                      \
    auto load_stage = [&](int s, int kb) {                                           \
        uint32_t base = sb + s * STG1_B;                                             \
        int koff = kb * BKD;                                                         \
        CP_ASYNC16(base + dA,          srcA + (size_t)rA * KDIM + koff + cA * 8);    \
        CP_ASYNC16(base + dB,          srcA + (size_t)rB * KDIM + koff + cB * 8);    \
        CP_ASYNC16(base + TILE_B + dA, srcB + (size_t)rA * KDIM + koff + cA * 8);    \
        CP_ASYNC16(base + TILE_B + dB, srcB + (size_t)rB * KDIM + koff + cB * 8);    \
    };                                                                               \
    float acc[2][4][4];                                                              \
    _Pragma("unroll")                                                                \
    for (int i = 0; i < 2; i++)                                                      \
        for (int j = 0; j < 4; j++)                                                  \
            for (int r = 0; r < 4; r++) acc[i][j][r] = 0.f;                          \
    load_stage(0, 0); CP_COMMIT();                                                   \
    const int arow = wm * 32 + (lane & 15);                                          \
    const int bnrow = wn * 32 + (lane & 15);                                         \
    const int lhalf = lane >> 4;                                                     \
    const int NKB = KDIM / BKD;                                                      \
    for (int kc = 0; kc < NKB; kc++) {                                               \
        if (kc + 1 < NKB) { load_stage((kc + 1) & 1, kc + 1); CP_COMMIT(); CP_WAIT(1); } \
        else              { CP_WAIT(0); }                                            \
        __syncthreads();                                                             \
        uint32_t base = sb + (kc & 1) * STG1_B;                                      \
        uint32_t aB = base, bB = base + TILE_B;                                      \
        _Pragma("unroll")                                                            \
        for (int ks = 0; ks < 4; ks++) {                                             \
            uint32_t ah[2][4], bh[4][2];                                             \
            _Pragma("unroll")                                                        \
            for (int i = 0; i < 2; i++) {                                            \
                int row = arow + i * 16;                                             \
                uint32_t off = (uint32_t)(row * 128 + (((ks * 2 + lhalf) ^ (row & 7)) << 4)); \
                LDSM4(ah[i][0], ah[i][1], ah[i][2], ah[i][3], aB + off);             \
            }                                                                        \
            _Pragma("unroll")                                                        \
            for (int jp = 0; jp < 2; jp++) {                                         \
                int row = bnrow + jp * 16;                                           \
                uint32_t off = (uint32_t)(row * 128 + (((ks * 2 + lhalf) ^ (row & 7)) << 4)); \
                uint32_t r0, r1_, r2_, r3_;                                          \
                LDSM4(r0, r1_, r2_, r3_, bB + off);                                  \
                bh[2 * jp][0] = r0;  bh[2 * jp][1] = r2_;                            \
                bh[2 * jp + 1][0] = r1_; bh[2 * jp + 1][1] = r3_;                    \
            }                                                                        \
            _Pragma("unroll")                                                        \
            for (int i = 0; i < 2; i++)                                              \
                for (int j = 0; j < 4; j++)                                          \
                    MMA16816(acc[i][j], ah[i], bh[j]);                               \
        }                                                                            \
        __syncthreads();                                                             \
    }

// ============================================================================
// gemm_qkv: QKV projection with ROPE FUSED INTO EPILOGUE.
// The 128-col n-tile == one head, so (d, d+64) rotation pairs are CTA-local.
// Stage fp32 acc in the (idle) 64KB pipeline smem, rotate, emit fp16.
// z==0: q (rope + 1/sqrt(dh)); z==1: k (rope); z==2: v (plain convert).
// ============================================================================
__global__ __launch_bounds__(512)
void gemm_qkv(const __half* __restrict__ A,
              const __half* __restrict__ B0, const __half* __restrict__ B1,
              const __half* __restrict__ B2,
              __half* __restrict__ C0, __half* __restrict__ C1, __half* __restrict__ C2,
              const float* __restrict__ rc, const float* __restrict__ rs)
{
    const int z = blockIdx.z;
    const __half* B = (z == 0) ? B0 : (z == 1) ? B1 : B2;
    __half* C = (z == 0) ? C0 : (z == 1) ? C1 : C2;

    GEMM1_BODY

    // ---- stage fp32 accumulators (pipeline smem is idle past final sync) ----
    float* stg = (float*)smc;
#pragma unroll
    for (int i = 0; i < 2; i++)
#pragma unroll
        for (int j = 0; j < 4; j++) {
            int ml = wm * 32 + i * 16 + (lane >> 2);
            int nl = wn * 32 + j * 8 + (lane & 3) * 2;
            stg[ml * 128 + nl]           = acc[i][j][0];
            stg[ml * 128 + nl + 1]       = acc[i][j][1];
            stg[(ml + 8) * 128 + nl]     = acc[i][j][2];
            stg[(ml + 8) * 128 + nl + 1] = acc[i][j][3];
        }
    __syncthreads();

    if (z == 2) {
        // plain convert: 16384 elems, 4 per item, 8 items/thread
#pragma unroll
        for (int it = 0; it < 8; it++) {
            int idx = tid + it * 512;          // 0..4095
            int row = idx >> 5;
            int q4 = (idx & 31) * 4;
            float4 v = *(float4*)&stg[row * 128 + q4];
            __half* Cp = C + (size_t)(m0 + row) * DMODEL + n0 + q4;
            *(uint32_t*)&Cp[0] = pk16(__float2half(v.x), __float2half(v.y));
            *(uint32_t*)&Cp[2] = pk16(__float2half(v.z), __float2half(v.w));
        }
    } else {
        const float qs = (z == 0) ? 0.088388347648318447f : 1.0f;
        // 128 rows x 16 quads of lower-half d: 2048 items, 4/thread
#pragma unroll
        for (int it = 0; it < 4; it++) {
            int idx = tid + it * 512;          // 0..2047
            int row = idx >> 4;
            int d = (idx & 15) * 4;            // 0..60
            int spos = (m0 + row) & (SEQ - 1);
            float4 lo = *(float4*)&stg[row * 128 + d];
            float4 hi = *(float4*)&stg[row * 128 + 64 + d];
            float4 c0 = *(const float4*)&rc[spos * DHEAD + d];
            float4 s0 = *(const float4*)&rs[spos * DHEAD + d];
            float4 c1 = *(const float4*)&rc[spos * DHEAD + 64 + d];
            float4 s1 = *(const float4*)&rs[spos * DHEAD + 64 + d];
            float l0 = (lo.x * c0.x - hi.x * s0.x) * qs;
            float l1 = (lo.y * c0.y - hi.y * s0.y) * qs;
            float l2 = (lo.z * c0.z - hi.z * s0.z) * qs;
            float l3 = (lo.w * c0.w - hi.w * s0.w) * qs;
            float u0 = (hi.x * c1.x + lo.x * s1.x) * qs;
            float u1 = (hi.y * c1.y + lo.y * s1.y) * qs;
            float u2 = (hi.z * c1.z + lo.z * s1.z) * qs;
            float u3 = (hi.w * c1.w + lo.w * s1.w) * qs;
            __half* Cp = C + (size_t)(m0 + row) * DMODEL + n0 + d;
            *(uint32_t*)&Cp[0]      = pk16(__float2half(l0), __float2half(l1));
            *(uint32_t*)&Cp[2]      = pk16(__float2half(l2), __float2half(l3));
            *(uint32_t*)&Cp[64]     = pk16(__float2half(u0), __float2half(u1));
            *(uint32_t*)&Cp[66]     = pk16(__float2half(u2), __float2half(u3));
        }
    }
}

// ============================================================================
// gemm_1p_f: plain fp16 GEMM, fp32 output (final projection).
// ============================================================================
__global__ __launch_bounds__(512)
void gemm_1p_f(const __half* __restrict__ A, const __half* __restrict__ B,
               float* __restrict__ C)
{
    GEMM1_BODY
#pragma unroll
    for (int i = 0; i < 2; i++)
#pragma unroll
        for (int j = 0; j < 4; j++) {
            int m = m0 + wm * 32 + i * 16 + (lane >> 2);
            int n = n0 + wn * 32 + j * 8 + (lane & 3) * 2;
            *(float2*)&C[(size_t)m * DMODEL + n]       = make_float2(acc[i][j][0], acc[i][j][1]);
            *(float2*)&C[(size_t)(m + 8) * DMODEL + n] = make_float2(acc[i][j][2], acc[i][j][3]);
        }
}

// ============================================================================
// attn_tc: flash attention, plain fp16 operands (fp32 accumulate).
// QK 1-product; PV 1-product. Output: single fp16 att plane. (unchanged R13)
// ============================================================================
#define NKT (SEQ/64)
#define ATT_PLANE_B 16384
#define ATT_STAGE_B (2*ATT_PLANE_B)              // 32 KB
#define ATT_Q_B     32768
#define ATT_NSTAGE  3
#define ATT_TC_SMEM (ATT_Q_B + ATT_NSTAGE*ATT_STAGE_B)   // 131072

__global__ __launch_bounds__(256, 1)
void attn_tc(const __half* __restrict__ qh,
             const __half* __restrict__ khi,
             const __half* __restrict__ vhi,
             __half* __restrict__ oh)
{
    extern __shared__ char smc[];
    const uint32_t sb = smem_u32(smc);
    const uint32_t QH = sb;
    const uint32_t ST = sb + ATT_Q_B;

    const int tid = threadIdx.x;
    const int lane = tid & 31;
    const int wid = tid >> 5;
    const int b = blockIdx.z, h = blockIdx.y;
    const int q0 = blockIdx.x * 128;
    const int wrow = wid * 16;

    {
        const __half* src0 = qh + ((size_t)(b * SEQ + q0)) * DMODEL + h * DHEAD;
#pragma unroll
        for (int i = 0; i < 8; i++) {
            int idx = tid + i * 256;
            int row = idx >> 4, ch = idx & 15;
            uint32_t dst = QH + row * 256 + ((ch ^ (row & 15)) << 4);
            CP_ASYNC16(dst, src0 + (size_t)row * DMODEL + ch * 8);
        }
    }

    const __half* pl[2] = { khi, vhi };
    auto load_kv = [&](int st, int kt) {
        uint32_t base = ST + st * ATT_STAGE_B;
#pragma unroll
        for (int i = 0; i < 8; i++) {
            int idx = tid + i * 256;
            int p = idx >> 10;
            int c = idx & 1023;
            int row = c >> 4, ch = c & 15;
            const __half* src = pl[p] +
                ((size_t)(b * SEQ + kt * 64 + row)) * DMODEL + h * DHEAD + ch * 8;
            uint32_t dst = base + p * ATT_PLANE_B + row * 256 + ((ch ^ (row & 15)) << 4);
            CP_ASYNC16(dst, src);
        }
    };

    float o_[16][4];
#pragma unroll
    for (int n = 0; n < 16; n++)
#pragma unroll
        for (int r = 0; r < 4; r++) o_[n][r] = 0.f;
    float m_a = -3.0e38f, m_b = -3.0e38f, l_a = 0.f, l_b = 0.f;

    load_kv(0, 0); CP_COMMIT();
    load_kv(1, 1); CP_COMMIT();

    const int qrow = wrow + (lane & 15);
    const int lh = lane >> 4;

    int st = 0;
    for (int kt = 0; kt < NKT; kt++) {
        CP_WAIT(1);
        __syncthreads();
        uint32_t bs = ST + st * ATT_STAGE_B;

        if (kt + 2 < NKT) {
            int st2 = st + 2; if (st2 >= ATT_NSTAGE) st2 -= ATT_NSTAGE;
            load_kv(st2, kt + 2); CP_COMMIT();
        } else {
            CP_COMMIT();
        }

        float s[8][4];
#pragma unroll
        for (int j = 0; j < 8; j++)
#pragma unroll
            for (int r = 0; r < 4; r++) s[j][r] = 0.f;

#pragma unroll
        for (int ks = 0; ks < 8; ks++) {
            uint32_t qoff = (uint32_t)(qrow * 256 + (((ks * 2 + lh) ^ (qrow & 15)) << 4));
            uint32_t ah[4];
            LDSM4(ah[0], ah[1], ah[2], ah[3], QH + qoff);
#pragma unroll
            for (int nb = 0; nb < 4; nb++) {
                int krow = nb * 16 + (lane & 15);
                uint32_t koff = (uint32_t)(krow * 256 + (((ks * 2 + lh) ^ (krow & 15)) << 4));
                uint32_t h0, h1, h2, h3;
                LDSM4(h0, h1, h2, h3, bs + koff);
                uint32_t bh0[2] = { h0, h2 }, bh1[2] = { h1, h3 };
                MMA16816(s[2*nb],   ah, bh0);
                MMA16816(s[2*nb+1], ah, bh1);
            }
        }

        float mla = -3.0e38f, mlb = -3.0e38f;
#pragma unroll
        for (int j = 0; j < 8; j++) {
            mla = fmaxf(mla, fmaxf(s[j][0], s[j][1]));
            mlb = fmaxf(mlb, fmaxf(s[j][2], s[j][3]));
        }
        mla = fmaxf(mla, __shfl_xor_sync(0xffffffffu, mla, 1));
        mla = fmaxf(mla, __shfl_xor_sync(0xffffffffu, mla, 2));
        mlb = fmaxf(mlb, __shfl_xor_sync(0xffffffffu, mlb, 1));
        mlb = fmaxf(mlb, __shfl_xor_sync(0xffffffffu, mlb, 2));
        float mna = fmaxf(m_a, mla), mnb = fmaxf(m_b, mlb);
        float aa = __expf(m_a - mna), ab = __expf(m_b - mnb);

        uint32_t pAh[8], pBh[8];
        float sa = 0.f, sb2 = 0.f;
#pragma unroll
        for (int j = 0; j < 8; j++) {
            float p0 = __expf(s[j][0] - mna), p1 = __expf(s[j][1] - mna);
            float p2 = __expf(s[j][2] - mnb), p3 = __expf(s[j][3] - mnb);
            sa += p0 + p1; sb2 += p2 + p3;
            pAh[j] = pk16(__float2half(p0), __float2half(p1));
            pBh[j] = pk16(__float2half(p2), __float2half(p3));
        }
        sa  += __shfl_xor_sync(0xffffffffu, sa, 1);
        sa  += __shfl_xor_sync(0xffffffffu, sa, 2);
        sb2 += __shfl_xor_sync(0xffffffffu, sb2, 1);
        sb2 += __shfl_xor_sync(0xffffffffu, sb2, 2);
        m_a = mna; m_b = mnb;
        l_a = l_a * aa + sa; l_b = l_b * ab + sb2;

#pragma unroll
        for (int n = 0; n < 16; n++) {
            o_[n][0] *= aa; o_[n][1] *= aa; o_[n][2] *= ab; o_[n][3] *= ab;
        }

#pragma unroll
        for (int kp = 0; kp < 4; kp++) {
            uint32_t ah4[4] = { pAh[2*kp], pBh[2*kp], pAh[2*kp+1], pBh[2*kp+1] };
            int vrow = kp * 16 + (lane & 15);
#pragma unroll
            for (int nb = 0; nb < 8; nb++) {
                uint32_t ch = (uint32_t)(nb * 2 + lh);
                uint32_t voff = (uint32_t)(vrow * 256 + ((ch ^ (vrow & 15)) << 4));
                uint32_t h0, h1, h2, h3;
                LDSM4T(h0, h1, h2, h3, bs + ATT_PLANE_B + voff);
                uint32_t bh0[2] = { h0, h1 }, bh1[2] = { h2, h3 };
                MMA16816(o_[2*nb],   ah4, bh0);
                MMA16816(o_[2*nb+1], ah4, bh1);
            }
        }

        if (++st == ATT_NSTAGE) st = 0;
    }

    float ia = 1.f / l_a, ib = 1.f / l_b;
    size_t r0 = (size_t)(b * SEQ + q0 + wrow + (lane >> 2)) * DMODEL + h * DHEAD + 2 * (lane & 3);
    size_t r1 = r0 + (size_t)8 * DMODEL;
#pragma unroll
    for (int n = 0; n < 16; n++) {
        *(uint32_t*)&oh[r0 + n*8] = pk16(__float2half(o_[n][0] * ia), __float2half(o_[n][1] * ia));
        *(uint32_t*)&oh[r1 + n*8] = pk16(__float2half(o_[n][2] * ib), __float2half(o_[n][3] * ib));
    }
}

// ============================================================================
extern "C" void kernel_launch(void* const* d_in, const int* in_sizes, int n_in,
                              void* d_out, int out_size)
{
    const float* x  = (const float*)d_in[0];
    const float* rc = (const float*)d_in[1];
    const float* rs = (const float*)d_in[2];
    const float* Wq = (const float*)d_in[3];
    const float* Wk = (const float*)d_in[4];
    const float* Wv = (const float*)d_in[5];
    const float* Wo = (const float*)d_in[6];
    float* out = (float*)d_out;

    __half *xh, *wq, *wk, *wv, *wo, *qhp, *khp, *vhp, *att;
    cudaGetSymbolAddress((void**)&xh, g_xh);
    cudaGetSymbolAddress((void**)&wq, g_wq);     cudaGetSymbolAddress((void**)&wk, g_wk);
    cudaGetSymbolAddress((void**)&wv, g_wv);     cudaGetSymbolAddress((void**)&wo, g_wo);
    cudaGetSymbolAddress((void**)&qhp, g_qh);    cudaGetSymbolAddress((void**)&khp, g_kh);
    cudaGetSymbolAddress((void**)&vhp, g_vh);
    cudaGetSymbolAddress((void**)&att, g_att);

    cudaFuncSetAttribute(gemm_qkv,  cudaFuncAttributeMaxDynamicSharedMemorySize, G1_SMEM);
    cudaFuncSetAttribute(gemm_1p_f, cudaFuncAttributeMaxDynamicSharedMemorySize, G1_SMEM);
    cudaFuncSetAttribute(attn_tc,   cudaFuncAttributeMaxDynamicSharedMemorySize, ATT_TC_SMEM);

    pack_all<<<(NP_TOTAL + 1023) / 1024, 256>>>(
        x, Wq, Wk, Wv, Wo,
        (uint32_t*)xh, (uint32_t*)wq, (uint32_t*)wk, (uint32_t*)wv, (uint32_t*)wo);

    // QKV projection with fused rope (q scaled), fp16 outputs
    gemm_qkv<<<dim3(DMODEL / 128, MROWS / 128, 3), 512, G1_SMEM>>>(
        xh, wq, wk, wv, qhp, khp, vhp, rc, rs);

    attn_tc<<<dim3(SEQ / 128, NHEADS, BATCH), 256, ATT_TC_SMEM>>>(qhp, khp, vhp, att);

    // output projection: plain fp16, fp32 out
    gemm_1p_f<<<dim3(DMODEL / 128, MROWS / 128, 1), 512, G1_SMEM>>>(att, wo, out);
}